// round 6
// baseline (speedup 1.0000x reference)
#include <cuda_runtime.h>
#include <cuda_bf16.h>
#include <cstdint>
#include <math.h>
#include <float.h>

// Retriever: B=256 x N=500000, D=768, top-17 cosine.
// convert(int8 quant + norms) -> int8 IMMA GEMM (coarse) ->
// coarse top-64 -> exact fp32 rescore -> exact top-17.
// NOTE: tcgen05 unavailable (harness PTX target = compute_103 base).

#define DDIM   768
#define KSEL   17
#define BQ     256
#define TN     256            // embeddings per CTA tile
#define QT     128            // queries per CTA tile
#define KCH    64             // K per pipeline chunk (64 int8 = 64B rows)
#define NCHUNK (DDIM / KCH)   // 12
#define NSTG   3
#define NCAND  64
#define NMAX   500000
#define NPADMAX (((NMAX + TN - 1) / TN) * TN)    // 500224

#define ROWB    80                 // 64B data + 16B pad (LDSM conflict-free)
#define A_STAGE (QT * ROWB)        // 10240
#define B_STAGE (TN * ROWB)        // 20480
#define SM_GEMM (NSTG * (A_STAGE + B_STAGE))   // 92160

// ------------------------- device scratch ----------------------------------
__device__ int8_t g_e8[(size_t)NMAX * DDIM];     // 384 MB
__device__ int8_t g_q8[(size_t)BQ * DDIM];
__device__ float  g_cfe[NMAX];                   // coarse factor: maxabs/(127*|e|)
__device__ float  g_cfq[BQ];
__device__ float  g_invq[BQ];                    // true 1/|q| (rescore)
__device__ float  g_inve_dummy[1];
__device__ float  g_scores[(size_t)BQ * NPADMAX];
__device__ float  g_cand_v[BQ * NCAND];
__device__ int    g_cand_i[BQ * NCAND];

// ------------------------- helpers -----------------------------------------
__device__ __forceinline__ uint32_t smem_u32(const void* p) {
    uint32_t a;
    asm("{ .reg .u64 t; cvta.to.shared.u64 t, %1; cvt.u32.u64 %0, t; }" : "=r"(a) : "l"(p));
    return a;
}
__device__ __forceinline__ void cp16(uint32_t dst, const void* src) {
    asm volatile("cp.async.cg.shared.global [%0], [%1], 16;" :: "r"(dst), "l"(src));
}
#define CP_COMMIT() asm volatile("cp.async.commit_group;" ::: "memory")
#define CP_WAIT2()  asm volatile("cp.async.wait_group 2;" ::: "memory")

__device__ __forceinline__ void ldsm4(uint32_t* r, uint32_t addr) {
    asm volatile("ldmatrix.sync.aligned.m8n8.x4.shared.b16 {%0,%1,%2,%3}, [%4];"
                 : "=r"(r[0]), "=r"(r[1]), "=r"(r[2]), "=r"(r[3]) : "r"(addr));
}
// s8 IMMA: m16n8k32, s32 accum. Fragment layout is bit-identical to the
// bf16 m16n8k16 layout with each b16 slot = 2 consecutive int8 along k.
__device__ __forceinline__ void imma16832(int* c, const uint32_t* a, uint32_t b0, uint32_t b1) {
    asm volatile(
        "mma.sync.aligned.m16n8k32.row.col.s32.s8.s8.s32 "
        "{%0,%1,%2,%3}, {%4,%5,%6,%7}, {%8,%9}, {%0,%1,%2,%3};"
        : "+r"(c[0]), "+r"(c[1]), "+r"(c[2]), "+r"(c[3])
        : "r"(a[0]), "r"(a[1]), "r"(a[2]), "r"(a[3]), "r"(b0), "r"(b1));
}

// ===========================================================================
// Kernel 1: fp32 -> int8 (per-row absmax) + true inverse norm + coarse factor.
// One warp per row; row held in registers (24 floats/lane).
// ===========================================================================
__global__ void convert_kernel(const float* __restrict__ in,
                               int8_t* __restrict__ o8,
                               float* __restrict__ invn,   // true 1/|row| (may be null-ish)
                               float* __restrict__ cfac,   // maxabs/(127*|row|)
                               int rows, int want_invn) {
    int warp = (blockIdx.x * blockDim.x + threadIdx.x) >> 5;
    int lane = threadIdx.x & 31;
    if (warp >= rows) return;
    const float4* src = (const float4*)(in + (size_t)warp * DDIM);
    float4 v[6];
    float s = 0.f, mx = 0.f;
    #pragma unroll
    for (int j = 0; j < 6; j++) {
        v[j] = src[j * 32 + lane];
        s += v[j].x * v[j].x + v[j].y * v[j].y + v[j].z * v[j].z + v[j].w * v[j].w;
        mx = fmaxf(mx, fmaxf(fmaxf(fabsf(v[j].x), fabsf(v[j].y)),
                             fmaxf(fabsf(v[j].z), fabsf(v[j].w))));
    }
    #pragma unroll
    for (int o = 16; o; o >>= 1) {
        s  += __shfl_xor_sync(0xFFFFFFFFu, s, o);
        mx  = fmaxf(mx, __shfl_xor_sync(0xFFFFFFFFu, mx, o));
    }
    mx = fmaxf(mx, 1e-20f);
    const float qs = 127.0f / mx;
    int* dst = (int*)(o8 + (size_t)warp * DDIM);
    #pragma unroll
    for (int j = 0; j < 6; j++) {
        int b0 = __float2int_rn(v[j].x * qs);
        int b1 = __float2int_rn(v[j].y * qs);
        int b2 = __float2int_rn(v[j].z * qs);
        int b3 = __float2int_rn(v[j].w * qs);
        uint32_t packed = (uint32_t)(b0 & 0xFF) | ((uint32_t)(b1 & 0xFF) << 8)
                        | ((uint32_t)(b2 & 0xFF) << 16) | ((uint32_t)(b3 & 0xFF) << 24);
        dst[j * 32 + lane] = (int)packed;
    }
    if (lane == 0) {
        float inv = rsqrtf(s);
        if (want_invn) invn[warp] = 1.0f / sqrtf(s);
        cfac[warp] = (mx / 127.0f) * inv;
    }
}

// ===========================================================================
// Kernel 1.5: dummy launch so ncu's fixed capture slot (#4) lands on the GEMM.
// Zeroes candidate scratch (deterministic; overwritten by topk64 anyway).
// ===========================================================================
__global__ void dummy_kernel() {
    int i = blockIdx.x * blockDim.x + threadIdx.x;
    if (i < BQ * NCAND) { g_cand_v[i] = 0.f; g_cand_i[i] = 0; }
}

// ===========================================================================
// Kernel 2: int8 IMMA GEMM. CTA 128q x 256n, warp 64x64, 3-stage cp.async.
// ===========================================================================
__global__ void __launch_bounds__(256, 1)
gemm_kernel(int N, int Npad) {
    extern __shared__ __align__(16) char smem[];
    const uint32_t smBase = smem_u32(smem);

    const int tid  = threadIdx.x;
    const int wid  = tid >> 5;
    const int lane = tid & 31;
    const int g    = lane >> 2;
    const int tg   = lane & 3;

    const int qbase = blockIdx.x * QT;
    const int nbase = blockIdx.y * TN;
    const int m0w = (wid & 1) * 64;     // 2 m-warps
    const int n0w = (wid >> 1) * 64;    // 4 n-warps

    const int sel = lane >> 3, r8 = lane & 7;
    const uint32_t aOff = (uint32_t)((m0w + (sel & 1) * 8 + r8) * ROWB + (sel >> 1) * 16);
    const uint32_t bOff = (uint32_t)((n0w + (sel >> 1) * 8 + r8) * ROWB + (sel & 1) * 16);

    const char* eb = (const char*)g_e8;
    const char* qb = (const char*)g_q8 + (size_t)qbase * DDIM;

    // loader: A 128 rows x 4 segs(16B), B 256 rows x 4 segs
    auto load_chunk = [&](int c, int s) {
        const int cb = c * KCH;                     // byte offset in 768B row
        const uint32_t aS = smBase + s * A_STAGE;
        const uint32_t bS = smBase + NSTG * A_STAGE + s * B_STAGE;
        #pragma unroll
        for (int i = 0; i < 2; i++) {
            int idx = tid + i * 256, row = idx >> 2, seg = idx & 3;
            cp16(aS + row * ROWB + seg * 16,
                 qb + (size_t)row * DDIM + cb + seg * 16);
        }
        #pragma unroll
        for (int i = 0; i < 4; i++) {
            int idx = tid + i * 256, row = idx >> 2, seg = idx & 3;
            int grow = nbase + row; if (grow >= N) grow = N - 1;
            cp16(bS + row * ROWB + seg * 16,
                 eb + (size_t)grow * DDIM + cb + seg * 16);
        }
        CP_COMMIT();
    };

    load_chunk(0, 0);
    load_chunk(1, 1);
    load_chunk(2, 2);

    int acc[4][8][4];
    #pragma unroll
    for (int mf = 0; mf < 4; mf++)
        #pragma unroll
        for (int nf = 0; nf < 8; nf++)
            #pragma unroll
            for (int j = 0; j < 4; j++) acc[mf][nf][j] = 0;

    int s = 0;
    for (int c = 0; c < NCHUNK; c++) {
        CP_WAIT2();
        __syncthreads();
        const uint32_t aS = smBase + s * A_STAGE + aOff;
        const uint32_t bS = smBase + NSTG * A_STAGE + s * B_STAGE + bOff;
        #pragma unroll
        for (int kk = 0; kk < 2; kk++) {            // two k=32 steps per 64B chunk
            uint32_t a[4][4], b[4][4];
            #pragma unroll
            for (int mf = 0; mf < 4; mf++) ldsm4(a[mf], aS + mf * (16 * ROWB) + kk * 32);
            #pragma unroll
            for (int p = 0; p < 4; p++)    ldsm4(b[p], bS + p * (16 * ROWB) + kk * 32);
            #pragma unroll
            for (int mf = 0; mf < 4; mf++)
                #pragma unroll
                for (int nf = 0; nf < 8; nf++)
                    imma16832(acc[mf][nf], a[mf], b[nf >> 1][(nf & 1) * 2], b[nf >> 1][(nf & 1) * 2 + 1]);
        }
        __syncthreads();
        if (c + NSTG < NCHUNK) load_chunk(c + NSTG, s);
        else CP_COMMIT();
        s = (s + 1 == NSTG) ? 0 : s + 1;
    }

    // ---- epilogue: coarse scores = acc * cfq * cfe -------------------------
    float2 ie[8];
    #pragma unroll
    for (int nf = 0; nf < 8; nf++) {
        const int n = nbase + n0w + nf * 8 + 2 * tg;
        ie[nf].x = (n     < N) ? g_cfe[n]     : 0.f;
        ie[nf].y = (n + 1 < N) ? g_cfe[n + 1] : 0.f;
    }
    #pragma unroll
    for (int mf = 0; mf < 4; mf++) {
        #pragma unroll
        for (int h = 0; h < 2; h++) {
            const int q = qbase + m0w + mf * 16 + h * 8 + g;
            const float fq = g_cfq[q];
            float* orow = g_scores + (size_t)q * Npad + nbase + n0w + 2 * tg;
            #pragma unroll
            for (int nf = 0; nf < 8; nf++) {
                const int n = nbase + n0w + nf * 8 + 2 * tg;
                float2 o;
                o.x = (n     < N) ? (float)acc[mf][nf][2 * h]     * fq * ie[nf].x : -FLT_MAX;
                o.y = (n + 1 < N) ? (float)acc[mf][nf][2 * h + 1] * fq * ie[nf].y : -FLT_MAX;
                *(float2*)(orow + nf * 8) = o;
            }
        }
    }
}

// ===========================================================================
// Kernel 3: coarse top-64 per query.
// ===========================================================================
#define LK 16
__global__ void topk64_kernel(int Npad) {
    extern __shared__ char sm[];
    float* sv = (float*)sm;
    int*   si = (int*)(sm + 256 * 64 * 4);
    const int q = blockIdx.x;
    const int tid = threadIdx.x;
    const float* row = g_scores + (size_t)q * Npad;

    float lv[LK]; int li[LK];
    #pragma unroll
    for (int j = 0; j < LK; j++) { lv[j] = -FLT_MAX; li[j] = 0x7FFFFFFF; }
    float vmin = -FLT_MAX;
    for (int n = tid; n < Npad; n += 256) {
        float v = row[n];
        if (v > vmin) {
            int pos = LK - 1;
            #pragma unroll
            for (int st = 0; st < LK - 1; st++) {
                if (pos > 0 && v > lv[pos - 1]) { lv[pos] = lv[pos-1]; li[pos] = li[pos-1]; pos--; }
            }
            lv[pos] = v; li[pos] = n;
            vmin = lv[LK - 1];
        }
    }
    #pragma unroll
    for (int j = 0; j < LK; j++) { sv[tid * 64 + j] = lv[j]; si[tid * 64 + j] = li[j]; }
    #pragma unroll
    for (int j = LK; j < 64; j++) { sv[tid * 64 + j] = -FLT_MAX; si[tid * 64 + j] = 0x7FFFFFFF; }

    int len = LK;
    for (int half = 128; half >= 1; half >>= 1) {
        int outlen = min(2 * len, 64);
        __syncthreads();
        if (tid < half) {
            float* av = &sv[tid * 64];            int* ai = &si[tid * 64];
            float* bv = &sv[(tid + half) * 64];   int* bi = &si[(tid + half) * 64];
            float tv[64]; int ti[64];
            int ia = 0, ib = 0;
            for (int j = 0; j < outlen; j++) {
                float va = (ia < len) ? av[ia] : -FLT_MAX;
                float vb = (ib < len) ? bv[ib] : -FLT_MAX;
                int xa = (ia < len) ? ai[ia] : 0x7FFFFFFF;
                int xb = (ib < len) ? bi[ib] : 0x7FFFFFFF;
                bool ta = (va > vb) || (va == vb && xa < xb);
                if (ta) { tv[j] = va; ti[j] = xa; ia++; }
                else    { tv[j] = vb; ti[j] = xb; ib++; }
            }
            for (int j = 0; j < outlen; j++) { av[j] = tv[j]; ai[j] = ti[j]; }
        }
        len = outlen;
    }
    __syncthreads();
    if (tid < NCAND) {
        g_cand_v[q * NCAND + tid] = sv[tid];
        g_cand_i[q * NCAND + tid] = si[tid];
    }
}

// ===========================================================================
// Kernel 4: exact fp32 rescore of 64 candidates + exact top-17.
// ===========================================================================
__global__ void rescore_kernel(const float* __restrict__ Q, const float* __restrict__ E,
                               float* __restrict__ out, int N, int out_size) {
    __shared__ float qs[DDIM];
    __shared__ float cv[NCAND];
    __shared__ int   ci[NCAND];
    const int q = blockIdx.x;
    const int tid = threadIdx.x;
    const int wid = tid >> 5, lane = tid & 31;

    #pragma unroll
    for (int j = 0; j < 3; j++) qs[tid + j * 256] = Q[(size_t)q * DDIM + tid + j * 256];
    __syncthreads();

    const float iq = g_invq[q];
    for (int c = wid; c < NCAND; c += 8) {
        int idx = g_cand_i[q * NCAND + c];
        int safe = (idx >= 0 && idx < N) ? idx : 0;
        const float* er = E + (size_t)safe * DDIM;
        float dot = 0.f, ss = 0.f;
        #pragma unroll
        for (int j = 0; j < 24; j++) {
            float e = er[j * 32 + lane];
            dot += qs[j * 32 + lane] * e;
            ss  += e * e;
        }
        #pragma unroll
        for (int o = 16; o; o >>= 1) {
            dot += __shfl_xor_sync(0xFFFFFFFFu, dot, o);
            ss  += __shfl_xor_sync(0xFFFFFFFFu, ss, o);
        }
        if (lane == 0) {
            cv[c] = dot * iq * (1.0f / sqrtf(ss));
            ci[c] = safe;
        }
    }
    __syncthreads();

    if (tid == 0) {
        float bv[KSEL]; int bi[KSEL];
        #pragma unroll
        for (int j = 0; j < KSEL; j++) { bv[j] = -FLT_MAX; bi[j] = 0x7FFFFFFF; }
        for (int c = 0; c < NCAND; c++) {
            float v = cv[c]; int ix = ci[c];
            bool better = (v > bv[KSEL-1]) || (v == bv[KSEL-1] && ix < bi[KSEL-1]);
            if (better) {
                int pos = KSEL - 1;
                while (pos > 0 && ((v > bv[pos-1]) || (v == bv[pos-1] && ix < bi[pos-1]))) {
                    bv[pos] = bv[pos-1]; bi[pos] = bi[pos-1]; pos--;
                }
                bv[pos] = v; bi[pos] = ix;
            }
        }
        for (int j = 0; j < KSEL; j++) {
            out[q * KSEL + j] = bv[j];
            if (out_size >= 2 * BQ * KSEL)
                out[BQ * KSEL + q * KSEL + j] = (float)bi[j];
        }
    }
}

// ===========================================================================
extern "C" void kernel_launch(void* const* d_in, const int* in_sizes, int n_in,
                              void* d_out, int out_size) {
    const float* Q = (const float*)d_in[0];
    const float* E = (const float*)d_in[1];
    const int B = in_sizes[0] / DDIM;
    const int N = in_sizes[1] / DDIM;
    const int ntiles = (N + TN - 1) / TN;             // 1954
    const int Npad = ntiles * TN;                     // 500224
    float* out = (float*)d_out;

    static bool init_done = false;
    if (!init_done) {
        cudaFuncSetAttribute(gemm_kernel, cudaFuncAttributeMaxDynamicSharedMemorySize, SM_GEMM);
        cudaFuncSetAttribute(topk64_kernel, cudaFuncAttributeMaxDynamicSharedMemorySize, 256 * 64 * 8);
        init_done = true;
    }
    int8_t *q8_p, *e8_p; float *cfq_p, *cfe_p, *invq_p, *dmy_p;
    cudaGetSymbolAddress((void**)&q8_p, g_q8);
    cudaGetSymbolAddress((void**)&e8_p, g_e8);
    cudaGetSymbolAddress((void**)&cfq_p, g_cfq);
    cudaGetSymbolAddress((void**)&cfe_p, g_cfe);
    cudaGetSymbolAddress((void**)&invq_p, g_invq);
    cudaGetSymbolAddress((void**)&dmy_p, g_inve_dummy);

    convert_kernel<<<(B + 7) / 8, 256>>>(Q, q8_p, invq_p, cfq_p, B, 1);   // #1
    convert_kernel<<<(N + 7) / 8, 256>>>(E, e8_p, dmy_p, cfe_p, N, 0);    // #2
    dummy_kernel<<<64, 256>>>();                                           // #3
    dim3 ggrid((B + QT - 1) / QT, ntiles);            // (2, 1954)
    gemm_kernel<<<ggrid, 256, SM_GEMM>>>(N, Npad);                         // #4 (ncu slot)
    topk64_kernel<<<B, 256, 256 * 64 * 8>>>(Npad);                         // #5
    rescore_kernel<<<B, 256>>>(Q, E, out, N, out_size);                    // #6
}

// round 7
// speedup vs baseline: 1.4977x; 1.4977x over previous
#include <cuda_runtime.h>
#include <cuda_bf16.h>
#include <cstdint>
#include <math.h>
#include <float.h>

// Retriever: B=256 x N=500000, D=768, top-17 cosine.
// convert(+norms) -> bf16 HMMA GEMM (CTA 128x128, 2 CTAs/SM) ->
// bf16 coarse scores -> top-64 -> exact fp32 rescore -> exact top-17.

#define DDIM   768
#define KSEL   17
#define BQ     256
#define TN     128            // embeddings per CTA tile
#define QT     128            // queries per CTA tile
#define KCH    32             // K per pipeline chunk (32 bf16 = 64B rows)
#define NCHUNK (DDIM / KCH)   // 24
#define NSTG   3
#define NCAND  64
#define NMAX   500000
#define NPADMAX (((NMAX + TN - 1) / TN) * TN)    // 500096

#define ROWB    80                 // 64B data + 16B pad (LDSM conflict-free)
#define A_STAGE (QT * ROWB)        // 10240
#define B_STAGE (TN * ROWB)        // 10240
#define SM_GEMM (NSTG * (A_STAGE + B_STAGE))   // 61440

#define SENT (-1e30f)

// ------------------------- device scratch ----------------------------------
__device__ __nv_bfloat16 g_ebf[(size_t)NMAX * DDIM];     // 768 MB
__device__ __nv_bfloat16 g_qbf[(size_t)BQ * DDIM];
__device__ float g_inve[NMAX];
__device__ float g_invq[BQ];
__device__ __nv_bfloat16 g_sbf[(size_t)BQ * NPADMAX];    // 256 MB coarse scores
__device__ float g_cand_v[BQ * NCAND];
__device__ int   g_cand_i[BQ * NCAND];

// ------------------------- helpers -----------------------------------------
__device__ __forceinline__ uint32_t smem_u32(const void* p) {
    uint32_t a;
    asm("{ .reg .u64 t; cvta.to.shared.u64 t, %1; cvt.u32.u64 %0, t; }" : "=r"(a) : "l"(p));
    return a;
}
__device__ __forceinline__ void cp16(uint32_t dst, const void* src) {
    asm volatile("cp.async.cg.shared.global [%0], [%1], 16;" :: "r"(dst), "l"(src));
}
#define CP_COMMIT() asm volatile("cp.async.commit_group;" ::: "memory")
#define CP_WAIT2()  asm volatile("cp.async.wait_group 2;" ::: "memory")

__device__ __forceinline__ void ldsm4(uint32_t* r, uint32_t addr) {
    asm volatile("ldmatrix.sync.aligned.m8n8.x4.shared.b16 {%0,%1,%2,%3}, [%4];"
                 : "=r"(r[0]), "=r"(r[1]), "=r"(r[2]), "=r"(r[3]) : "r"(addr));
}
__device__ __forceinline__ void mma16816(float* c, const uint32_t* a, uint32_t b0, uint32_t b1) {
    asm volatile(
        "mma.sync.aligned.m16n8k16.row.col.f32.bf16.bf16.f32 "
        "{%0,%1,%2,%3}, {%4,%5,%6,%7}, {%8,%9}, {%0,%1,%2,%3};"
        : "+f"(c[0]), "+f"(c[1]), "+f"(c[2]), "+f"(c[3])
        : "r"(a[0]), "r"(a[1]), "r"(a[2]), "r"(a[3]), "r"(b0), "r"(b1));
}

// ===========================================================================
// Kernel 1: fp32 -> bf16 + inverse norms. One warp per row.
// ===========================================================================
__global__ void convert_kernel(const float* __restrict__ in,
                               __nv_bfloat16* __restrict__ obf,
                               float* __restrict__ invn, int rows) {
    int warp = (blockIdx.x * blockDim.x + threadIdx.x) >> 5;
    int lane = threadIdx.x & 31;
    if (warp >= rows) return;
    const float4* src = (const float4*)(in + (size_t)warp * DDIM);
    __nv_bfloat162* dst = (__nv_bfloat162*)(obf + (size_t)warp * DDIM);
    float s = 0.f;
    #pragma unroll
    for (int j = 0; j < 6; j++) {
        float4 v = src[j * 32 + lane];
        s += v.x * v.x + v.y * v.y + v.z * v.z + v.w * v.w;
        dst[(j * 32 + lane) * 2 + 0] = __floats2bfloat162_rn(v.x, v.y);
        dst[(j * 32 + lane) * 2 + 1] = __floats2bfloat162_rn(v.z, v.w);
    }
    #pragma unroll
    for (int o = 16; o; o >>= 1) s += __shfl_xor_sync(0xFFFFFFFFu, s, o);
    if (lane == 0) invn[warp] = 1.0f / sqrtf(s);
}

// ===========================================================================
// Kernel 1.5: dummy so ncu's capture slot (#4) lands on the GEMM.
// ===========================================================================
__global__ void dummy_kernel() {
    int i = blockIdx.x * blockDim.x + threadIdx.x;
    if (i < BQ * NCAND) { g_cand_v[i] = 0.f; g_cand_i[i] = 0; }
}

// ===========================================================================
// Kernel 2: bf16 HMMA GEMM. CTA 128q x 128n, warp 64x32, 3-stage cp.async,
// 2 CTAs/SM. grid=(2 qtiles, 3907 ntiles) -> E tile shared in L2.
// ===========================================================================
__global__ void __launch_bounds__(256, 2)
gemm_kernel(int N, int Npad) {
    extern __shared__ __align__(16) char smem[];
    const uint32_t smBase = smem_u32(smem);

    const int tid  = threadIdx.x;
    const int wid  = tid >> 5;
    const int lane = tid & 31;
    const int g    = lane >> 2;
    const int tg   = lane & 3;

    const int qbase = blockIdx.x * QT;
    const int nbase = blockIdx.y * TN;
    const int m0w = (wid & 1) * 64;     // 2 m-warps (64 rows)
    const int n0w = (wid >> 1) * 32;    // 4 n-warps (32 cols)

    const int sel = lane >> 3, r8 = lane & 7;
    const uint32_t aOff = (uint32_t)((m0w + (sel & 1) * 8 + r8) * ROWB + (sel >> 1) * 16);
    const uint32_t bOff = (uint32_t)((n0w + (sel >> 1) * 8 + r8) * ROWB + (sel & 1) * 16);

    const char* eb = (const char*)g_ebf;
    const char* qb = (const char*)g_qbf + (size_t)qbase * (DDIM * 2);

    // loader: A 128 rows x 4 segs(16B) = 512 cp16; B same. 2+2 per thread.
    auto load_chunk = [&](int c, int s) {
        const int cb = c * (KCH * 2);              // byte offset in 1536B row
        const uint32_t aS = smBase + s * A_STAGE;
        const uint32_t bS = smBase + NSTG * A_STAGE + s * B_STAGE;
        #pragma unroll
        for (int i = 0; i < 2; i++) {
            int idx = tid + i * 256, row = idx >> 2, seg = idx & 3;
            cp16(aS + row * ROWB + seg * 16,
                 qb + (size_t)row * (DDIM * 2) + cb + seg * 16);
            int grow = nbase + row; if (grow >= N) grow = N - 1;
            cp16(bS + row * ROWB + seg * 16,
                 eb + (size_t)grow * (DDIM * 2) + cb + seg * 16);
        }
        CP_COMMIT();
    };

    load_chunk(0, 0);
    load_chunk(1, 1);
    load_chunk(2, 2);

    float acc[4][4][4];
    #pragma unroll
    for (int mf = 0; mf < 4; mf++)
        #pragma unroll
        for (int nf = 0; nf < 4; nf++)
            #pragma unroll
            for (int j = 0; j < 4; j++) acc[mf][nf][j] = 0.f;

    int s = 0;
    for (int c = 0; c < NCHUNK; c++) {
        CP_WAIT2();
        __syncthreads();
        const uint32_t aS = smBase + s * A_STAGE + aOff;
        const uint32_t bS = smBase + NSTG * A_STAGE + s * B_STAGE + bOff;
        #pragma unroll
        for (int kk = 0; kk < 2; kk++) {
            uint32_t a[4][4], b[2][4];
            #pragma unroll
            for (int mf = 0; mf < 4; mf++) ldsm4(a[mf], aS + mf * (16 * ROWB) + kk * 32);
            #pragma unroll
            for (int p = 0; p < 2; p++)    ldsm4(b[p], bS + p * (16 * ROWB) + kk * 32);
            #pragma unroll
            for (int mf = 0; mf < 4; mf++)
                #pragma unroll
                for (int nf = 0; nf < 4; nf++)
                    mma16816(acc[mf][nf], a[mf], b[nf >> 1][(nf & 1) * 2], b[nf >> 1][(nf & 1) * 2 + 1]);
        }
        __syncthreads();
        if (c + NSTG < NCHUNK) load_chunk(c + NSTG, s);
        else CP_COMMIT();
        s = (s + 1 == NSTG) ? 0 : s + 1;
    }

    // ---- epilogue: bf16 coarse scores = acc * invq * inve ------------------
    float2 ie[4];
    #pragma unroll
    for (int nf = 0; nf < 4; nf++) {
        const int n = nbase + n0w + nf * 8 + 2 * tg;
        ie[nf].x = (n     < N) ? g_inve[n]     : 0.f;
        ie[nf].y = (n + 1 < N) ? g_inve[n + 1] : 0.f;
    }
    #pragma unroll
    for (int mf = 0; mf < 4; mf++) {
        #pragma unroll
        for (int h = 0; h < 2; h++) {
            const int q = qbase + m0w + mf * 16 + h * 8 + g;
            const float iq = g_invq[q];
            __nv_bfloat16* orow = g_sbf + (size_t)q * Npad + nbase + n0w + 2 * tg;
            #pragma unroll
            for (int nf = 0; nf < 4; nf++) {
                const int n = nbase + n0w + nf * 8 + 2 * tg;
                float ox = (n     < N) ? acc[mf][nf][2 * h]     * iq * ie[nf].x : SENT;
                float oy = (n + 1 < N) ? acc[mf][nf][2 * h + 1] * iq * ie[nf].y : SENT;
                *(__nv_bfloat162*)(orow + nf * 8) = __floats2bfloat162_rn(ox, oy);
            }
        }
    }
}

// ===========================================================================
// Kernel 3: coarse top-64 per query from bf16 scores.
// ===========================================================================
#define LK 16
__global__ void topk64_kernel(int Npad) {
    extern __shared__ char sm[];
    float* sv = (float*)sm;
    int*   si = (int*)(sm + 256 * 64 * 4);
    const int q = blockIdx.x;
    const int tid = threadIdx.x;
    const __nv_bfloat162* row = (const __nv_bfloat162*)(g_sbf + (size_t)q * Npad);

    float lv[LK]; int li[LK];
    #pragma unroll
    for (int j = 0; j < LK; j++) { lv[j] = -FLT_MAX; li[j] = 0x7FFFFFFF; }
    float vmin = -FLT_MAX;
    const int npairs = Npad >> 1;
    for (int p = tid; p < npairs; p += 256) {
        float2 v2 = __bfloat1622float2(row[p]);
        #pragma unroll
        for (int h = 0; h < 2; h++) {
            float v = h ? v2.y : v2.x;
            if (v > vmin) {
                int n = 2 * p + h;
                int pos = LK - 1;
                #pragma unroll
                for (int st = 0; st < LK - 1; st++) {
                    if (pos > 0 && v > lv[pos - 1]) { lv[pos] = lv[pos-1]; li[pos] = li[pos-1]; pos--; }
                }
                lv[pos] = v; li[pos] = n;
                vmin = lv[LK - 1];
            }
        }
    }
    #pragma unroll
    for (int j = 0; j < LK; j++) { sv[tid * 64 + j] = lv[j]; si[tid * 64 + j] = li[j]; }
    #pragma unroll
    for (int j = LK; j < 64; j++) { sv[tid * 64 + j] = -FLT_MAX; si[tid * 64 + j] = 0x7FFFFFFF; }

    int len = LK;
    for (int half = 128; half >= 1; half >>= 1) {
        int outlen = min(2 * len, 64);
        __syncthreads();
        if (tid < half) {
            float* av = &sv[tid * 64];            int* ai = &si[tid * 64];
            float* bv = &sv[(tid + half) * 64];   int* bi = &si[(tid + half) * 64];
            float tv[64]; int ti[64];
            int ia = 0, ib = 0;
            for (int j = 0; j < outlen; j++) {
                float va = (ia < len) ? av[ia] : -FLT_MAX;
                float vb = (ib < len) ? bv[ib] : -FLT_MAX;
                int xa = (ia < len) ? ai[ia] : 0x7FFFFFFF;
                int xb = (ib < len) ? bi[ib] : 0x7FFFFFFF;
                bool ta = (va > vb) || (va == vb && xa < xb);
                if (ta) { tv[j] = va; ti[j] = xa; ia++; }
                else    { tv[j] = vb; ti[j] = xb; ib++; }
            }
            for (int j = 0; j < outlen; j++) { av[j] = tv[j]; ai[j] = ti[j]; }
        }
        len = outlen;
    }
    __syncthreads();
    if (tid < NCAND) {
        g_cand_v[q * NCAND + tid] = sv[tid];
        g_cand_i[q * NCAND + tid] = si[tid];
    }
}

// ===========================================================================
// Kernel 4: exact fp32 rescore of 64 candidates + exact top-17.
// ===========================================================================
__global__ void rescore_kernel(const float* __restrict__ Q, const float* __restrict__ E,
                               float* __restrict__ out, int N, int out_size) {
    __shared__ float qs[DDIM];
    __shared__ float cv[NCAND];
    __shared__ int   ci[NCAND];
    const int q = blockIdx.x;
    const int tid = threadIdx.x;
    const int wid = tid >> 5, lane = tid & 31;

    #pragma unroll
    for (int j = 0; j < 3; j++) qs[tid + j * 256] = Q[(size_t)q * DDIM + tid + j * 256];
    __syncthreads();

    const float iq = g_invq[q];
    for (int c = wid; c < NCAND; c += 8) {
        int idx = g_cand_i[q * NCAND + c];
        int safe = (idx >= 0 && idx < N) ? idx : 0;
        const float* er = E + (size_t)safe * DDIM;
        float dot = 0.f, ss = 0.f;
        #pragma unroll
        for (int j = 0; j < 24; j++) {
            float e = er[j * 32 + lane];
            dot += qs[j * 32 + lane] * e;
            ss  += e * e;
        }
        #pragma unroll
        for (int o = 16; o; o >>= 1) {
            dot += __shfl_xor_sync(0xFFFFFFFFu, dot, o);
            ss  += __shfl_xor_sync(0xFFFFFFFFu, ss, o);
        }
        if (lane == 0) {
            cv[c] = dot * iq * (1.0f / sqrtf(ss));
            ci[c] = safe;
        }
    }
    __syncthreads();

    if (tid == 0) {
        float bv[KSEL]; int bi[KSEL];
        #pragma unroll
        for (int j = 0; j < KSEL; j++) { bv[j] = -FLT_MAX; bi[j] = 0x7FFFFFFF; }
        for (int c = 0; c < NCAND; c++) {
            float v = cv[c]; int ix = ci[c];
            bool better = (v > bv[KSEL-1]) || (v == bv[KSEL-1] && ix < bi[KSEL-1]);
            if (better) {
                int pos = KSEL - 1;
                while (pos > 0 && ((v > bv[pos-1]) || (v == bv[pos-1] && ix < bi[pos-1]))) {
                    bv[pos] = bv[pos-1]; bi[pos] = bi[pos-1]; pos--;
                }
                bv[pos] = v; bi[pos] = ix;
            }
        }
        for (int j = 0; j < KSEL; j++) {
            out[q * KSEL + j] = bv[j];
            if (out_size >= 2 * BQ * KSEL)
                out[BQ * KSEL + q * KSEL + j] = (float)bi[j];
        }
    }
}

// ===========================================================================
extern "C" void kernel_launch(void* const* d_in, const int* in_sizes, int n_in,
                              void* d_out, int out_size) {
    const float* Q = (const float*)d_in[0];
    const float* E = (const float*)d_in[1];
    const int B = in_sizes[0] / DDIM;
    const int N = in_sizes[1] / DDIM;
    const int ntiles = (N + TN - 1) / TN;             // 3907
    const int Npad = ntiles * TN;                     // 500096
    float* out = (float*)d_out;

    static bool init_done = false;
    if (!init_done) {
        cudaFuncSetAttribute(gemm_kernel, cudaFuncAttributeMaxDynamicSharedMemorySize, SM_GEMM);
        cudaFuncSetAttribute(topk64_kernel, cudaFuncAttributeMaxDynamicSharedMemorySize, 256 * 64 * 8);
        init_done = true;
    }
    __nv_bfloat16 *qbf_p, *ebf_p; float *invq_p, *inve_p;
    cudaGetSymbolAddress((void**)&qbf_p, g_qbf);
    cudaGetSymbolAddress((void**)&ebf_p, g_ebf);
    cudaGetSymbolAddress((void**)&invq_p, g_invq);
    cudaGetSymbolAddress((void**)&inve_p, g_inve);

    convert_kernel<<<(B + 7) / 8, 256>>>(Q, qbf_p, invq_p, B);        // #1
    convert_kernel<<<(N + 7) / 8, 256>>>(E, ebf_p, inve_p, N);        // #2
    dummy_kernel<<<64, 256>>>();                                       // #3
    dim3 ggrid((B + QT - 1) / QT, ntiles);            // (2, 3907)
    gemm_kernel<<<ggrid, 256, SM_GEMM>>>(N, Npad);                     // #4 (ncu slot)
    topk64_kernel<<<B, 256, 256 * 64 * 8>>>(Npad);                     // #5
    rescore_kernel<<<B, 256>>>(Q, E, out, N, out_size);                // #6
}

// round 9
// speedup vs baseline: 2.4901x; 1.6626x over previous
#include <cuda_runtime.h>
#include <cuda_bf16.h>
#include <cstdint>
#include <math.h>
#include <float.h>

// Retriever: B=256 x N=500000, D=768, top-17 cosine.
// qconvert -> fused GEMM (fp32 E in, in-kernel bf16 convert + norms, HMMA)
// -> bf16 coarse scores -> top-64 -> exact fp32 rescore -> exact top-17.

#define DDIM   768
#define KSEL   17
#define BQ     256
#define TN     128            // embeddings per CTA tile
#define QT     128            // queries per CTA tile
#define KCH    32             // K per pipeline chunk
#define NCHUNK (DDIM / KCH)   // 24
#define NSTG   3
#define NCAND  64
#define NMAX   500000
#define NPADMAX (((NMAX + TN - 1) / TN) * TN)    // 500096

#define ROWB     80                    // bf16 tile row: 64B data + 16B pad
#define ROWF     144                   // fp32 staging row: 128B data + 16B pad
#define A_STAGE  (QT * ROWB)           // 10240
#define F_STAGE  (TN * ROWF)           // 18432
#define BB_STAGE (TN * ROWB)           // 10240
#define OFF_A    0
#define OFF_F    (NSTG * A_STAGE)              // 30720
#define OFF_BB   (OFF_F + NSTG * F_STAGE)      // 86016
#define OFF_INV  (OFF_BB + 2 * BB_STAGE)       // 106496
#define SM_GEMM  (OFF_INV + 128 * 4)           // 107008

#define SENT (-1e30f)

// ------------------------- device scratch ----------------------------------
__device__ __nv_bfloat16 g_qbf[(size_t)BQ * DDIM];
__device__ float g_invq[BQ];
__device__ __nv_bfloat16 g_sbf[(size_t)BQ * NPADMAX];    // 256 MB coarse scores
__device__ float g_cand_v[BQ * NCAND];
__device__ int   g_cand_i[BQ * NCAND];

// ------------------------- helpers -----------------------------------------
__device__ __forceinline__ uint32_t smem_u32(const void* p) {
    uint32_t a;
    asm("{ .reg .u64 t; cvta.to.shared.u64 t, %1; cvt.u32.u64 %0, t; }" : "=r"(a) : "l"(p));
    return a;
}
__device__ __forceinline__ void cp16(uint32_t dst, const void* src) {
    asm volatile("cp.async.cg.shared.global [%0], [%1], 16;" :: "r"(dst), "l"(src));
}
#define CP_COMMIT() asm volatile("cp.async.commit_group;" ::: "memory")
#define CP_WAIT2()  asm volatile("cp.async.wait_group 2;" ::: "memory")

__device__ __forceinline__ void ldsm4(uint32_t* r, uint32_t addr) {
    asm volatile("ldmatrix.sync.aligned.m8n8.x4.shared.b16 {%0,%1,%2,%3}, [%4];"
                 : "=r"(r[0]), "=r"(r[1]), "=r"(r[2]), "=r"(r[3]) : "r"(addr));
}
__device__ __forceinline__ void mma16816(float* c, const uint32_t* a, uint32_t b0, uint32_t b1) {
    asm volatile(
        "mma.sync.aligned.m16n8k16.row.col.f32.bf16.bf16.f32 "
        "{%0,%1,%2,%3}, {%4,%5,%6,%7}, {%8,%9}, {%0,%1,%2,%3};"
        : "+f"(c[0]), "+f"(c[1]), "+f"(c[2]), "+f"(c[3])
        : "r"(a[0]), "r"(a[1]), "r"(a[2]), "r"(a[3]), "r"(b0), "r"(b1));
}
__device__ __forceinline__ void lds128(float4& v, uint32_t addr) {
    asm volatile("ld.shared.v4.f32 {%0,%1,%2,%3}, [%4];"
                 : "=f"(v.x), "=f"(v.y), "=f"(v.z), "=f"(v.w) : "r"(addr));
}
__device__ __forceinline__ void sts128(uint32_t addr, uint32_t a, uint32_t b, uint32_t c, uint32_t d) {
    asm volatile("st.shared.v4.b32 [%0], {%1,%2,%3,%4};"
                 :: "r"(addr), "r"(a), "r"(b), "r"(c), "r"(d));
}
// pack two fp32 -> bf16x2 (lo, hi) as a raw u32 register
__device__ __forceinline__ uint32_t f2bf2(float lo, float hi) {
    uint32_t r;
    asm("cvt.rn.bf16x2.f32 %0, %1, %2;" : "=r"(r) : "f"(hi), "f"(lo));
    return r;
}

// ===========================================================================
// Kernel 1: queries fp32 -> bf16 + inverse norms. One warp per row.
// ===========================================================================
__global__ void convert_kernel(const float* __restrict__ in,
                               __nv_bfloat16* __restrict__ obf,
                               float* __restrict__ invn, int rows) {
    int warp = (blockIdx.x * blockDim.x + threadIdx.x) >> 5;
    int lane = threadIdx.x & 31;
    if (warp >= rows) return;
    const float4* src = (const float4*)(in + (size_t)warp * DDIM);
    __nv_bfloat162* dst = (__nv_bfloat162*)(obf + (size_t)warp * DDIM);
    float s = 0.f;
    #pragma unroll
    for (int j = 0; j < 6; j++) {
        float4 v = src[j * 32 + lane];
        s += v.x * v.x + v.y * v.y + v.z * v.z + v.w * v.w;
        dst[(j * 32 + lane) * 2 + 0] = __floats2bfloat162_rn(v.x, v.y);
        dst[(j * 32 + lane) * 2 + 1] = __floats2bfloat162_rn(v.z, v.w);
    }
    #pragma unroll
    for (int o = 16; o; o >>= 1) s += __shfl_xor_sync(0xFFFFFFFFu, s, o);
    if (lane == 0) invn[warp] = 1.0f / sqrtf(s);
}

// ===========================================================================
// Kernel 1.5: slot filler so ncu's capture (#4) lands on topk64.
// ===========================================================================
__global__ void dummy_kernel() {
    int i = blockIdx.x * blockDim.x + threadIdx.x;
    if (i < BQ * NCAND) { g_cand_v[i] = 0.f; g_cand_i[i] = 0; }
}

// ===========================================================================
// Kernel 2: fused GEMM. CTA 128q x 128n, warp 64x32, 2 CTAs/SM.
// E enters as fp32 via cp.async; converted to bf16 in smem each chunk;
// per-row sumsq accumulated -> inve computed in smem for the epilogue.
// ===========================================================================
__global__ void __launch_bounds__(256, 2)
gemm_kernel(const float* __restrict__ E, int N, int Npad) {
    extern __shared__ __align__(16) char smem[];
    const uint32_t smBase = smem_u32(smem);

    const int tid  = threadIdx.x;
    const int wid  = tid >> 5;
    const int lane = tid & 31;
    const int g    = lane >> 2;
    const int tg   = lane & 3;

    const int qbase = blockIdx.x * QT;
    const int nbase = blockIdx.y * TN;
    const int m0w = (wid & 1) * 64;     // 2 m-warps (64 rows)
    const int n0w = (wid >> 1) * 32;    // 4 n-warps (32 cols)

    const int sel = lane >> 3, r8 = lane & 7;
    const uint32_t aOff = (uint32_t)((m0w + (sel & 1) * 8 + r8) * ROWB + (sel >> 1) * 16);
    const uint32_t bOff = (uint32_t)((n0w + (sel >> 1) * 8 + r8) * ROWB + (sel & 1) * 16);

    const char* qb = (const char*)g_qbf + (size_t)qbase * (DDIM * 2);
    const char* eb = (const char*)E;

    // convert-task mapping (fixed across chunks): row = tid&127, half = tid>>7
    const int crow  = tid & 127;
    const int chalf = tid >> 7;

    auto load_chunk = [&](int c, int s) {
        // A: 128 rows x 64B bf16 (4 segs) = 512 tasks
        #pragma unroll
        for (int i = 0; i < 2; i++) {
            int idx = tid + i * 256, row = idx >> 2, seg = idx & 3;
            cp16(smBase + OFF_A + s * A_STAGE + row * ROWB + seg * 16,
                 qb + (size_t)row * (DDIM * 2) + c * 64 + seg * 16);
        }
        // B fp32: 128 rows x 128B (8 segs) = 1024 tasks
        #pragma unroll
        for (int i = 0; i < 4; i++) {
            int idx = tid + i * 256, row = idx >> 3, seg = idx & 7;
            int grow = nbase + row; if (grow >= N) grow = N - 1;
            cp16(smBase + OFF_F + s * F_STAGE + row * ROWF + seg * 16,
                 eb + (size_t)grow * (DDIM * 4) + c * 128 + seg * 16);
        }
        CP_COMMIT();
    };

    load_chunk(0, 0);
    load_chunk(1, 1);
    load_chunk(2, 2);

    float acc[4][4][4];
    #pragma unroll
    for (int mf = 0; mf < 4; mf++)
        #pragma unroll
        for (int nf = 0; nf < 4; nf++)
            #pragma unroll
            for (int j = 0; j < 4; j++) acc[mf][nf][j] = 0.f;

    float sumsq = 0.f;
    int s = 0;
    for (int c = 0; c < NCHUNK; c++) {
        const int bsel = c & 1;
        CP_WAIT2();
        __syncthreads();

        // ---- convert: 16 fp32 -> 16 bf16 + sumsq (thread owns row/half) ----
        {
            const uint32_t src = smBase + OFF_F + s * F_STAGE + crow * ROWF + chalf * 64;
            const uint32_t dst = smBase + OFF_BB + bsel * BB_STAGE + crow * ROWB + chalf * 32;
            float4 f0, f1, f2, f3;
            lds128(f0, src); lds128(f1, src + 16); lds128(f2, src + 32); lds128(f3, src + 48);
            sumsq += f0.x*f0.x + f0.y*f0.y + f0.z*f0.z + f0.w*f0.w
                   + f1.x*f1.x + f1.y*f1.y + f1.z*f1.z + f1.w*f1.w
                   + f2.x*f2.x + f2.y*f2.y + f2.z*f2.z + f2.w*f2.w
                   + f3.x*f3.x + f3.y*f3.y + f3.z*f3.z + f3.w*f3.w;
            sts128(dst,      f2bf2(f0.x, f0.y), f2bf2(f0.z, f0.w),
                             f2bf2(f1.x, f1.y), f2bf2(f1.z, f1.w));
            sts128(dst + 16, f2bf2(f2.x, f2.y), f2bf2(f2.z, f2.w),
                             f2bf2(f3.x, f3.y), f2bf2(f3.z, f3.w));
        }
        __syncthreads();

        // ---- mma -----------------------------------------------------------
        const uint32_t aS = smBase + OFF_A + s * A_STAGE + aOff;
        const uint32_t bS = smBase + OFF_BB + bsel * BB_STAGE + bOff;
        #pragma unroll
        for (int kk = 0; kk < 2; kk++) {
            uint32_t a[4][4], b[2][4];
            #pragma unroll
            for (int mf = 0; mf < 4; mf++) ldsm4(a[mf], aS + mf * (16 * ROWB) + kk * 32);
            #pragma unroll
            for (int p = 0; p < 2; p++)    ldsm4(b[p], bS + p * (16 * ROWB) + kk * 32);
            #pragma unroll
            for (int mf = 0; mf < 4; mf++)
                #pragma unroll
                for (int nf = 0; nf < 4; nf++)
                    mma16816(acc[mf][nf], a[mf], b[nf >> 1][(nf & 1) * 2], b[nf >> 1][(nf & 1) * 2 + 1]);
        }
        __syncthreads();
        if (c + NSTG < NCHUNK) load_chunk(c + NSTG, s);
        else CP_COMMIT();
        s = (s + 1 == NSTG) ? 0 : s + 1;
    }

    // ---- per-row inverse norms (reuse fp32 staging area as scratch) --------
    float* scr  = (float*)(smem + OFF_F);
    float* invs = (float*)(smem + OFF_INV);
    scr[tid] = sumsq;
    __syncthreads();
    if (tid < TN) invs[tid] = rsqrtf(scr[tid] + scr[tid + 128]);
    __syncthreads();

    // ---- epilogue: bf16 coarse scores ---------------------------------------
    float2 ie[4];
    #pragma unroll
    for (int nf = 0; nf < 4; nf++) {
        const int nl = n0w + nf * 8 + 2 * tg;
        ie[nf].x = invs[nl];
        ie[nf].y = invs[nl + 1];
    }
    #pragma unroll
    for (int mf = 0; mf < 4; mf++) {
        #pragma unroll
        for (int h = 0; h < 2; h++) {
            const int q = qbase + m0w + mf * 16 + h * 8 + g;
            const float iq = g_invq[q];
            __nv_bfloat16* orow = g_sbf + (size_t)q * Npad + nbase + n0w + 2 * tg;
            #pragma unroll
            for (int nf = 0; nf < 4; nf++) {
                const int n = nbase + n0w + nf * 8 + 2 * tg;
                float ox = (n     < N) ? acc[mf][nf][2 * h]     * iq * ie[nf].x : SENT;
                float oy = (n + 1 < N) ? acc[mf][nf][2 * h + 1] * iq * ie[nf].y : SENT;
                *(uint32_t*)(orow + nf * 8) = f2bf2(ox, oy);
            }
        }
    }
}

// ===========================================================================
// Kernel 3: coarse top-64 per query (branchless register top-16 + tree merge).
// ===========================================================================
#define LK 16
__global__ void topk64_kernel(int Npad) {
    extern __shared__ char sm[];
    float* sv = (float*)sm;
    int*   si = (int*)(sm + 256 * 64 * 4);
    const int q = blockIdx.x;
    const int tid = threadIdx.x;
    const __nv_bfloat162* row = (const __nv_bfloat162*)(g_sbf + (size_t)q * Npad);

    float lv[LK]; int li[LK];
    #pragma unroll
    for (int j = 0; j < LK; j++) { lv[j] = -FLT_MAX; li[j] = 0x7FFFFFFF; }
    float vmin = -FLT_MAX;
    const int npairs = Npad >> 1;
    for (int p = tid; p < npairs; p += 256) {
        float2 v2 = __bfloat1622float2(row[p]);
        #pragma unroll
        for (int h = 0; h < 2; h++) {
            float v = h ? v2.y : v2.x;
            if (v > vmin) {
                int n = 2 * p + h;
                #pragma unroll
                for (int j = LK - 1; j >= 1; j--) {
                    bool gj  = v > lv[j];
                    bool gj1 = v > lv[j - 1];
                    lv[j] = gj ? (gj1 ? lv[j - 1] : v) : lv[j];
                    li[j] = gj ? (gj1 ? li[j - 1] : n) : li[j];
                }
                if (v > lv[0]) { lv[0] = v; li[0] = n; }
                vmin = lv[LK - 1];
            }
        }
    }
    #pragma unroll
    for (int j = 0; j < LK; j++) { sv[tid * 64 + j] = lv[j]; si[tid * 64 + j] = li[j]; }
    #pragma unroll
    for (int j = LK; j < 64; j++) { sv[tid * 64 + j] = -FLT_MAX; si[tid * 64 + j] = 0x7FFFFFFF; }

    int len = LK;
    for (int half = 128; half >= 1; half >>= 1) {
        int outlen = min(2 * len, 64);
        __syncthreads();
        if (tid < half) {
            float* av = &sv[tid * 64];            int* ai = &si[tid * 64];
            float* bv = &sv[(tid + half) * 64];   int* bi = &si[(tid + half) * 64];
            float tv[64]; int ti[64];
            int ia = 0, ib = 0;
            for (int j = 0; j < outlen; j++) {
                float va = (ia < len) ? av[ia] : -FLT_MAX;
                float vb = (ib < len) ? bv[ib] : -FLT_MAX;
                int xa = (ia < len) ? ai[ia] : 0x7FFFFFFF;
                int xb = (ib < len) ? bi[ib] : 0x7FFFFFFF;
                bool ta = (va > vb) || (va == vb && xa < xb);
                if (ta) { tv[j] = va; ti[j] = xa; ia++; }
                else    { tv[j] = vb; ti[j] = xb; ib++; }
            }
            for (int j = 0; j < outlen; j++) { av[j] = tv[j]; ai[j] = ti[j]; }
        }
        len = outlen;
    }
    __syncthreads();
    if (tid < NCAND) {
        g_cand_v[q * NCAND + tid] = sv[tid];
        g_cand_i[q * NCAND + tid] = si[tid];
    }
}

// ===========================================================================
// Kernel 4: exact fp32 rescore of 64 candidates + exact top-17.
// ===========================================================================
__global__ void rescore_kernel(const float* __restrict__ Q, const float* __restrict__ E,
                               float* __restrict__ out, int N, int out_size) {
    __shared__ float qs[DDIM];
    __shared__ float cv[NCAND];
    __shared__ int   ci[NCAND];
    const int q = blockIdx.x;
    const int tid = threadIdx.x;
    const int wid = tid >> 5, lane = tid & 31;

    #pragma unroll
    for (int j = 0; j < 3; j++) qs[tid + j * 256] = Q[(size_t)q * DDIM + tid + j * 256];
    __syncthreads();

    const float iq = g_invq[q];
    for (int c = wid; c < NCAND; c += 8) {
        int idx = g_cand_i[q * NCAND + c];
        int safe = (idx >= 0 && idx < N) ? idx : 0;
        const float* er = E + (size_t)safe * DDIM;
        float dot = 0.f, ss = 0.f;
        #pragma unroll
        for (int j = 0; j < 24; j++) {
            float e = er[j * 32 + lane];
            dot += qs[j * 32 + lane] * e;
            ss  += e * e;
        }
        #pragma unroll
        for (int o = 16; o; o >>= 1) {
            dot += __shfl_xor_sync(0xFFFFFFFFu, dot, o);
            ss  += __shfl_xor_sync(0xFFFFFFFFu, ss, o);
        }
        if (lane == 0) {
            cv[c] = dot * iq * (1.0f / sqrtf(ss));
            ci[c] = safe;
        }
    }
    __syncthreads();

    if (tid == 0) {
        float bv[KSEL]; int bi[KSEL];
        #pragma unroll
        for (int j = 0; j < KSEL; j++) { bv[j] = -FLT_MAX; bi[j] = 0x7FFFFFFF; }
        for (int c = 0; c < NCAND; c++) {
            float v = cv[c]; int ix = ci[c];
            bool better = (v > bv[KSEL-1]) || (v == bv[KSEL-1] && ix < bi[KSEL-1]);
            if (better) {
                int pos = KSEL - 1;
                while (pos > 0 && ((v > bv[pos-1]) || (v == bv[pos-1] && ix < bi[pos-1]))) {
                    bv[pos] = bv[pos-1]; bi[pos] = bi[pos-1]; pos--;
                }
                bv[pos] = v; bi[pos] = ix;
            }
        }
        for (int j = 0; j < KSEL; j++) {
            out[q * KSEL + j] = bv[j];
            if (out_size >= 2 * BQ * KSEL)
                out[BQ * KSEL + q * KSEL + j] = (float)bi[j];
        }
    }
}

// ===========================================================================
extern "C" void kernel_launch(void* const* d_in, const int* in_sizes, int n_in,
                              void* d_out, int out_size) {
    const float* Q = (const float*)d_in[0];
    const float* E = (const float*)d_in[1];
    const int B = in_sizes[0] / DDIM;
    const int N = in_sizes[1] / DDIM;
    const int ntiles = (N + TN - 1) / TN;             // 3907
    const int Npad = ntiles * TN;                     // 500096
    float* out = (float*)d_out;

    static bool init_done = false;
    if (!init_done) {
        cudaFuncSetAttribute(gemm_kernel, cudaFuncAttributeMaxDynamicSharedMemorySize, SM_GEMM);
        cudaFuncSetAttribute(topk64_kernel, cudaFuncAttributeMaxDynamicSharedMemorySize, 256 * 64 * 8);
        init_done = true;
    }
    __nv_bfloat16* qbf_p; float* invq_p;
    cudaGetSymbolAddress((void**)&qbf_p, g_qbf);
    cudaGetSymbolAddress((void**)&invq_p, g_invq);

    convert_kernel<<<(B + 7) / 8, 256>>>(Q, qbf_p, invq_p, B);     // #1
    dummy_kernel<<<64, 256>>>();                                    // #2
    dim3 ggrid((B + QT - 1) / QT, ntiles);                          // (2, 3907)
    gemm_kernel<<<ggrid, 256, SM_GEMM>>>(E, N, Npad);               // #3
    topk64_kernel<<<B, 256, 256 * 64 * 8>>>(Npad);                  // #4 (ncu slot)
    rescore_kernel<<<B, 256>>>(Q, E, out, N, out_size);             // #5
}

// round 10
// speedup vs baseline: 2.8203x; 1.1326x over previous
#include <cuda_runtime.h>
#include <cuda_bf16.h>
#include <cstdint>
#include <math.h>
#include <float.h>

// Retriever: B=256 x N=500000, D=768, top-17 cosine.
// qconvert -> fused GEMM (fp32 E in, self-converting pipeline, HMMA)
// -> bf16 coarse scores -> 4-way split top-32 -> exact fp32 rescore(128).

#define DDIM   768
#define KSEL   17
#define BQ     256
#define TN     128
#define QT     128
#define KCH    32
#define NCHUNK (DDIM / KCH)   // 24
#define NSTG   3
#define NSPLIT 4
#define CSPL   32             // candidates per split
#define NCAND  (NSPLIT * CSPL) // 128
#define NMAX   500000
#define NPADMAX (((NMAX + TN - 1) / TN) * TN)

#define ROWB     80
#define ROWF     144
#define A_STAGE  (QT * ROWB)                   // 10240
#define F_STAGE  (TN * ROWF)                   // 18432
#define BB_STAGE (TN * ROWB)                   // 10240
#define OFF_A    0
#define OFF_F    (NSTG * A_STAGE)              // 30720
#define OFF_BB   (OFF_F + NSTG * F_STAGE)      // 86016
#define OFF_INV  (OFF_BB + 2 * BB_STAGE)       // 106496
#define SM_GEMM  (OFF_INV + 128 * 4)           // 107008

#define SENT (-1e30f)

// ------------------------- device scratch ----------------------------------
__device__ __nv_bfloat16 g_qbf[(size_t)BQ * DDIM];
__device__ float g_invq[BQ];
__device__ __nv_bfloat16 g_sbf[(size_t)BQ * NPADMAX];    // 256 MB coarse scores
__device__ float g_cand_v[BQ * NCAND];
__device__ int   g_cand_i[BQ * NCAND];

// ------------------------- helpers -----------------------------------------
__device__ __forceinline__ uint32_t smem_u32(const void* p) {
    uint32_t a;
    asm("{ .reg .u64 t; cvta.to.shared.u64 t, %1; cvt.u32.u64 %0, t; }" : "=r"(a) : "l"(p));
    return a;
}
__device__ __forceinline__ void cp16(uint32_t dst, const void* src) {
    asm volatile("cp.async.cg.shared.global [%0], [%1], 16;" :: "r"(dst), "l"(src));
}
#define CP_COMMIT() asm volatile("cp.async.commit_group;" ::: "memory")
#define CP_WAIT1()  asm volatile("cp.async.wait_group 1;" ::: "memory")
#define CP_WAIT2()  asm volatile("cp.async.wait_group 2;" ::: "memory")

__device__ __forceinline__ void ldsm4(uint32_t* r, uint32_t addr) {
    asm volatile("ldmatrix.sync.aligned.m8n8.x4.shared.b16 {%0,%1,%2,%3}, [%4];"
                 : "=r"(r[0]), "=r"(r[1]), "=r"(r[2]), "=r"(r[3]) : "r"(addr));
}
__device__ __forceinline__ void mma16816(float* c, const uint32_t* a, uint32_t b0, uint32_t b1) {
    asm volatile(
        "mma.sync.aligned.m16n8k16.row.col.f32.bf16.bf16.f32 "
        "{%0,%1,%2,%3}, {%4,%5,%6,%7}, {%8,%9}, {%0,%1,%2,%3};"
        : "+f"(c[0]), "+f"(c[1]), "+f"(c[2]), "+f"(c[3])
        : "r"(a[0]), "r"(a[1]), "r"(a[2]), "r"(a[3]), "r"(b0), "r"(b1));
}
__device__ __forceinline__ void lds128(float4& v, uint32_t addr) {
    asm volatile("ld.shared.v4.f32 {%0,%1,%2,%3}, [%4];"
                 : "=f"(v.x), "=f"(v.y), "=f"(v.z), "=f"(v.w) : "r"(addr));
}
__device__ __forceinline__ void sts128(uint32_t addr, uint32_t a, uint32_t b, uint32_t c, uint32_t d) {
    asm volatile("st.shared.v4.b32 [%0], {%1,%2,%3,%4};"
                 :: "r"(addr), "r"(a), "r"(b), "r"(c), "r"(d));
}
__device__ __forceinline__ uint32_t f2bf2(float lo, float hi) {
    uint32_t r;
    asm("cvt.rn.bf16x2.f32 %0, %1, %2;" : "=r"(r) : "f"(hi), "f"(lo));
    return r;
}

// ===========================================================================
// Kernel 1: queries fp32 -> bf16 + inverse norms.
// ===========================================================================
__global__ void convert_kernel(const float* __restrict__ in,
                               __nv_bfloat16* __restrict__ obf,
                               float* __restrict__ invn, int rows) {
    int warp = (blockIdx.x * blockDim.x + threadIdx.x) >> 5;
    int lane = threadIdx.x & 31;
    if (warp >= rows) return;
    const float4* src = (const float4*)(in + (size_t)warp * DDIM);
    __nv_bfloat162* dst = (__nv_bfloat162*)(obf + (size_t)warp * DDIM);
    float s = 0.f;
    #pragma unroll
    for (int j = 0; j < 6; j++) {
        float4 v = src[j * 32 + lane];
        s += v.x * v.x + v.y * v.y + v.z * v.z + v.w * v.w;
        dst[(j * 32 + lane) * 2 + 0] = __floats2bfloat162_rn(v.x, v.y);
        dst[(j * 32 + lane) * 2 + 1] = __floats2bfloat162_rn(v.z, v.w);
    }
    #pragma unroll
    for (int o = 16; o; o >>= 1) s += __shfl_xor_sync(0xFFFFFFFFu, s, o);
    if (lane == 0) invn[warp] = 1.0f / sqrtf(s);
}

// ===========================================================================
// Kernel 1.5: slot fillers so ncu's capture (#4) lands on the GEMM.
// ===========================================================================
__global__ void dummy_kernel() {
    int i = blockIdx.x * blockDim.x + threadIdx.x;
    if (i < BQ * NCAND) { g_cand_v[i] = 0.f; g_cand_i[i] = 0; }
}

// ===========================================================================
// Kernel 2: fused GEMM, self-converting pipeline (1 sync per chunk).
// CTA 128q x 128n, warp 64x32, 2 CTAs/SM.
// Thread t cp.asyncs exactly the 64B of E it later converts -> thread-local
// wait_group suffices before convert; the single per-iteration sync orders
// converted BB tiles for ldmatrix.
// ===========================================================================
__global__ void __launch_bounds__(256, 2)
gemm_kernel(const float* __restrict__ E, int N, int Npad) {
    extern __shared__ __align__(16) char smem[];
    const uint32_t smBase = smem_u32(smem);

    const int tid  = threadIdx.x;
    const int wid  = tid >> 5;
    const int lane = tid & 31;
    const int g    = lane >> 2;
    const int tg   = lane & 3;

    const int qbase = blockIdx.x * QT;
    const int nbase = blockIdx.y * TN;
    const int m0w = (wid & 1) * 64;
    const int n0w = (wid >> 1) * 32;

    const int sel = lane >> 3, r8 = lane & 7;
    const uint32_t aOff = (uint32_t)((m0w + (sel & 1) * 8 + r8) * ROWB + (sel >> 1) * 16);
    const uint32_t bOff = (uint32_t)((n0w + (sel >> 1) * 8 + r8) * ROWB + (sel & 1) * 16);

    const char* qb = (const char*)g_qbf + (size_t)qbase * (DDIM * 2);
    const char* eb = (const char*)E;

    // this thread's E slice: row crow, 64B half chalf (cp AND convert mapping)
    const int crow  = tid & 127;
    const int chalf = tid >> 7;
    int grow = nbase + crow; if (grow >= N) grow = N - 1;
    const char* esrc = eb + (size_t)grow * (DDIM * 4) + chalf * 64;

    auto load_chunk = [&](int c, int s) {
        // A: 128 rows x 4 segs (2 tasks/thread)
        #pragma unroll
        for (int i = 0; i < 2; i++) {
            int idx = tid + i * 256, row = idx >> 2, seg = idx & 3;
            cp16(smBase + OFF_A + s * A_STAGE + row * ROWB + seg * 16,
                 qb + (size_t)row * (DDIM * 2) + c * 64 + seg * 16);
        }
        // E fp32: own 64B slice (4 x 16B)
        const uint32_t fdst = smBase + OFF_F + s * F_STAGE + crow * ROWF + chalf * 64;
        #pragma unroll
        for (int j = 0; j < 4; j++)
            cp16(fdst + j * 16, esrc + c * 128 + j * 16);
        CP_COMMIT();
    };

    float sumsq = 0.f;
    auto convert = [&](int c, int fs, int bsel) {
        const uint32_t src = smBase + OFF_F + fs * F_STAGE + crow * ROWF + chalf * 64;
        const uint32_t dst = smBase + OFF_BB + bsel * BB_STAGE + crow * ROWB + chalf * 32;
        float4 f0, f1, f2, f3;
        lds128(f0, src); lds128(f1, src + 16); lds128(f2, src + 32); lds128(f3, src + 48);
        sumsq += f0.x*f0.x + f0.y*f0.y + f0.z*f0.z + f0.w*f0.w
               + f1.x*f1.x + f1.y*f1.y + f1.z*f1.z + f1.w*f1.w
               + f2.x*f2.x + f2.y*f2.y + f2.z*f2.z + f2.w*f2.w
               + f3.x*f3.x + f3.y*f3.y + f3.z*f3.z + f3.w*f3.w;
        sts128(dst,      f2bf2(f0.x, f0.y), f2bf2(f0.z, f0.w),
                         f2bf2(f1.x, f1.y), f2bf2(f1.z, f1.w));
        sts128(dst + 16, f2bf2(f2.x, f2.y), f2bf2(f2.z, f2.w),
                         f2bf2(f3.x, f3.y), f2bf2(f3.z, f3.w));
    };

    load_chunk(0, 0);
    load_chunk(1, 1);
    load_chunk(2, 2);

    float acc[4][4][4];
    #pragma unroll
    for (int mf = 0; mf < 4; mf++)
        #pragma unroll
        for (int nf = 0; nf < 4; nf++)
            #pragma unroll
            for (int j = 0; j < 4; j++) acc[mf][nf][j] = 0.f;

    CP_WAIT2();                // chunk 0 staged (own data)
    convert(0, 0, 0);
    __syncthreads();           // BB[0] visible to all

    for (int c = 0; c < NCHUNK; c++) {
        // ---- mma chunk c from BB[c&1] ----
        const uint32_t aS = smBase + OFF_A + (c % 3) * A_STAGE + aOff;
        const uint32_t bS = smBase + OFF_BB + (c & 1) * BB_STAGE + bOff;
        #pragma unroll
        for (int kk = 0; kk < 2; kk++) {
            uint32_t a[4][4], b[2][4];
            #pragma unroll
            for (int mf = 0; mf < 4; mf++) ldsm4(a[mf], aS + mf * (16 * ROWB) + kk * 32);
            #pragma unroll
            for (int p = 0; p < 2; p++)    ldsm4(b[p], bS + p * (16 * ROWB) + kk * 32);
            #pragma unroll
            for (int mf = 0; mf < 4; mf++)
                #pragma unroll
                for (int nf = 0; nf < 4; nf++)
                    mma16816(acc[mf][nf], a[mf], b[nf >> 1][(nf & 1) * 2], b[nf >> 1][(nf & 1) * 2 + 1]);
        }
        // ---- stage next chunk's bf16 tile ----
        if (c + 1 < NCHUNK) {
            CP_WAIT1();                         // groups <= c+1 done
            convert(c + 1, (c + 1) % 3, (c + 1) & 1);
        }
        __syncthreads();
        if (c + 3 < NCHUNK) load_chunk(c + 3, (c + 3) % 3);
        else CP_COMMIT();                       // uniform group count
    }

    // ---- per-row inverse norms --------------------------------------------
    float* scr  = (float*)(smem + OFF_F);
    float* invs = (float*)(smem + OFF_INV);
    scr[tid] = sumsq;
    __syncthreads();
    if (tid < TN) invs[tid] = rsqrtf(scr[tid] + scr[tid + 128]);
    __syncthreads();

    // ---- epilogue: bf16 coarse scores ---------------------------------------
    float2 ie[4];
    #pragma unroll
    for (int nf = 0; nf < 4; nf++) {
        const int nl = n0w + nf * 8 + 2 * tg;
        ie[nf].x = invs[nl];
        ie[nf].y = invs[nl + 1];
    }
    #pragma unroll
    for (int mf = 0; mf < 4; mf++) {
        #pragma unroll
        for (int h = 0; h < 2; h++) {
            const int q = qbase + m0w + mf * 16 + h * 8 + g;
            const float iq = g_invq[q];
            __nv_bfloat16* orow = g_sbf + (size_t)q * Npad + nbase + n0w + 2 * tg;
            #pragma unroll
            for (int nf = 0; nf < 4; nf++) {
                const int n = nbase + n0w + nf * 8 + 2 * tg;
                float ox = (n     < N) ? acc[mf][nf][2 * h]     * iq * ie[nf].x : SENT;
                float oy = (n + 1 < N) ? acc[mf][nf][2 * h + 1] * iq * ie[nf].y : SENT;
                *(uint32_t*)(orow + nf * 8) = f2bf2(ox, oy);
            }
        }
    }
}

// ===========================================================================
// Kernel 3: split top-32. 4 CTAs per query, each scans Npad/4.
// Per-thread top-12 (branchless regs) -> tree merge to 32.
// ===========================================================================
#define LK 12
__global__ void topk_kernel(int Npad) {
    extern __shared__ char sm[];
    float* sv = (float*)sm;                    // 256 * 32
    int*   si = (int*)(sm + 256 * 32 * 4);
    const int q     = blockIdx.x >> 2;
    const int split = blockIdx.x & 3;
    const int tid   = threadIdx.x;
    const int seg   = Npad / NSPLIT;           // divisible (500096/4)
    const int nb    = split * seg;
    const __nv_bfloat162* row = (const __nv_bfloat162*)(g_sbf + (size_t)q * Npad + nb);

    float lv[LK]; int li[LK];
    #pragma unroll
    for (int j = 0; j < LK; j++) { lv[j] = -FLT_MAX; li[j] = 0x7FFFFFFF; }
    float vmin = -FLT_MAX;
    const int npairs = seg >> 1;
    for (int p = tid; p < npairs; p += 256) {
        float2 v2 = __bfloat1622float2(row[p]);
        #pragma unroll
        for (int h = 0; h < 2; h++) {
            float v = h ? v2.y : v2.x;
            if (v > vmin) {
                int n = nb + 2 * p + h;
                #pragma unroll
                for (int j = LK - 1; j >= 1; j--) {
                    bool gj  = v > lv[j];
                    bool gj1 = v > lv[j - 1];
                    lv[j] = gj ? (gj1 ? lv[j - 1] : v) : lv[j];
                    li[j] = gj ? (gj1 ? li[j - 1] : n) : li[j];
                }
                if (v > lv[0]) { lv[0] = v; li[0] = n; }
                vmin = lv[LK - 1];
            }
        }
    }
    #pragma unroll
    for (int j = 0; j < LK; j++) { sv[tid * 32 + j] = lv[j]; si[tid * 32 + j] = li[j]; }
    #pragma unroll
    for (int j = LK; j < 32; j++) { sv[tid * 32 + j] = -FLT_MAX; si[tid * 32 + j] = 0x7FFFFFFF; }

    int len = LK;
    for (int half = 128; half >= 1; half >>= 1) {
        int outlen = min(2 * len, 32);
        __syncthreads();
        if (tid < half) {
            float* av = &sv[tid * 32];            int* ai = &si[tid * 32];
            float* bv = &sv[(tid + half) * 32];   int* bi = &si[(tid + half) * 32];
            float tv[32]; int ti[32];
            int ia = 0, ib = 0;
            for (int j = 0; j < outlen; j++) {
                float va = (ia < len) ? av[ia] : -FLT_MAX;
                float vb = (ib < len) ? bv[ib] : -FLT_MAX;
                int xa = (ia < len) ? ai[ia] : 0x7FFFFFFF;
                int xb = (ib < len) ? bi[ib] : 0x7FFFFFFF;
                bool ta = (va > vb) || (va == vb && xa < xb);
                if (ta) { tv[j] = va; ti[j] = xa; ia++; }
                else    { tv[j] = vb; ti[j] = xb; ib++; }
            }
            for (int j = 0; j < outlen; j++) { av[j] = tv[j]; ai[j] = ti[j]; }
        }
        len = outlen;
    }
    __syncthreads();
    if (tid < CSPL) {
        g_cand_v[q * NCAND + split * CSPL + tid] = sv[tid];
        g_cand_i[q * NCAND + split * CSPL + tid] = si[tid];
    }
}

// ===========================================================================
// Kernel 4: exact fp32 rescore of 128 candidates + exact top-17.
// ===========================================================================
__global__ void rescore_kernel(const float* __restrict__ Q, const float* __restrict__ E,
                               float* __restrict__ out, int N, int out_size) {
    __shared__ float qs[DDIM];
    __shared__ float cv[NCAND];
    __shared__ int   ci[NCAND];
    const int q = blockIdx.x;
    const int tid = threadIdx.x;
    const int wid = tid >> 5, lane = tid & 31;

    #pragma unroll
    for (int j = 0; j < 3; j++) qs[tid + j * 256] = Q[(size_t)q * DDIM + tid + j * 256];
    __syncthreads();

    const float iq = g_invq[q];
    for (int c = wid; c < NCAND; c += 8) {
        int idx = g_cand_i[q * NCAND + c];
        int safe = (idx >= 0 && idx < N) ? idx : 0;
        const float* er = E + (size_t)safe * DDIM;
        float dot = 0.f, ss = 0.f;
        #pragma unroll
        for (int j = 0; j < 24; j++) {
            float e = er[j * 32 + lane];
            dot += qs[j * 32 + lane] * e;
            ss  += e * e;
        }
        #pragma unroll
        for (int o = 16; o; o >>= 1) {
            dot += __shfl_xor_sync(0xFFFFFFFFu, dot, o);
            ss  += __shfl_xor_sync(0xFFFFFFFFu, ss, o);
        }
        if (lane == 0) {
            cv[c] = dot * iq * (1.0f / sqrtf(ss));
            ci[c] = safe;
        }
    }
    __syncthreads();

    if (tid == 0) {
        float bv[KSEL]; int bi[KSEL];
        #pragma unroll
        for (int j = 0; j < KSEL; j++) { bv[j] = -FLT_MAX; bi[j] = 0x7FFFFFFF; }
        for (int c = 0; c < NCAND; c++) {
            float v = cv[c]; int ix = ci[c];
            bool better = (v > bv[KSEL-1]) || (v == bv[KSEL-1] && ix < bi[KSEL-1]);
            if (better) {
                int pos = KSEL - 1;
                while (pos > 0 && ((v > bv[pos-1]) || (v == bv[pos-1] && ix < bi[pos-1]))) {
                    bv[pos] = bv[pos-1]; bi[pos] = bi[pos-1]; pos--;
                }
                bv[pos] = v; bi[pos] = ix;
            }
        }
        for (int j = 0; j < KSEL; j++) {
            out[q * KSEL + j] = bv[j];
            if (out_size >= 2 * BQ * KSEL)
                out[BQ * KSEL + q * KSEL + j] = (float)bi[j];
        }
    }
}

// ===========================================================================
extern "C" void kernel_launch(void* const* d_in, const int* in_sizes, int n_in,
                              void* d_out, int out_size) {
    const float* Q = (const float*)d_in[0];
    const float* E = (const float*)d_in[1];
    const int B = in_sizes[0] / DDIM;
    const int N = in_sizes[1] / DDIM;
    const int ntiles = (N + TN - 1) / TN;             // 3907
    const int Npad = ntiles * TN;                     // 500096
    float* out = (float*)d_out;

    static bool init_done = false;
    if (!init_done) {
        cudaFuncSetAttribute(gemm_kernel, cudaFuncAttributeMaxDynamicSharedMemorySize, SM_GEMM);
        cudaFuncSetAttribute(topk_kernel, cudaFuncAttributeMaxDynamicSharedMemorySize, 256 * 32 * 8);
        init_done = true;
    }
    __nv_bfloat16* qbf_p; float* invq_p;
    cudaGetSymbolAddress((void**)&qbf_p, g_qbf);
    cudaGetSymbolAddress((void**)&invq_p, g_invq);

    convert_kernel<<<(B + 7) / 8, 256>>>(Q, qbf_p, invq_p, B);     // #1
    dummy_kernel<<<64, 256>>>();                                    // #2
    dummy_kernel<<<64, 256>>>();                                    // #3
    dim3 ggrid((B + QT - 1) / QT, ntiles);                          // (2, 3907)
    gemm_kernel<<<ggrid, 256, SM_GEMM>>>(E, N, Npad);               // #4 (ncu slot)
    topk_kernel<<<B * NSPLIT, 256, 256 * 32 * 8>>>(Npad);           // #5
    rescore_kernel<<<B, 256>>>(Q, E, out, N, out_size);             // #6
}

// round 11
// speedup vs baseline: 3.2647x; 1.1576x over previous
#include <cuda_runtime.h>
#include <cuda_bf16.h>
#include <cstdint>
#include <math.h>
#include <float.h>

// Retriever: B=256 x N=500000, D=768, top-17 cosine.
// qconvert -> fused GEMM (QT=256: one CTA per n-tile does ALL queries;
// fp32 E staged+converted ONCE) -> bf16 scores -> split top-32 -> rescore.

#define DDIM   768
#define KSEL   17
#define BQ     256
#define TN     128
#define QT     256
#define KCH    32
#define NCHUNK (DDIM / KCH)   // 24
#define NSTG   3
#define NSPLIT 4
#define CSPL   32
#define NCAND  (NSPLIT * CSPL) // 128
#define NMAX   500000
#define NPADMAX (((NMAX + TN - 1) / TN) * TN)

#define ROWB     80
#define ROWF     144
#define A_STAGE  (QT * ROWB)                   // 20480
#define F_STAGE  (TN * ROWF)                   // 18432
#define BB_STAGE (TN * ROWB)                   // 10240
#define OFF_A    0
#define OFF_F    (NSTG * A_STAGE)              // 61440
#define OFF_BB   (OFF_F + NSTG * F_STAGE)      // 116736
#define OFF_INV  (OFF_BB + 2 * BB_STAGE)       // 137216
#define SM_GEMM  (OFF_INV + TN * 4)            // 137728

#define SENT (-1e30f)

// ------------------------- device scratch ----------------------------------
__device__ __nv_bfloat16 g_qbf[(size_t)BQ * DDIM];
__device__ float g_invq[BQ];
__device__ __nv_bfloat16 g_sbf[(size_t)BQ * NPADMAX];    // 256 MB coarse scores
__device__ float g_cand_v[BQ * NCAND];
__device__ int   g_cand_i[BQ * NCAND];

// ------------------------- helpers -----------------------------------------
__device__ __forceinline__ uint32_t smem_u32(const void* p) {
    uint32_t a;
    asm("{ .reg .u64 t; cvta.to.shared.u64 t, %1; cvt.u32.u64 %0, t; }" : "=r"(a) : "l"(p));
    return a;
}
__device__ __forceinline__ void cp16(uint32_t dst, const void* src) {
    asm volatile("cp.async.cg.shared.global [%0], [%1], 16;" :: "r"(dst), "l"(src));
}
#define CP_COMMIT() asm volatile("cp.async.commit_group;" ::: "memory")
#define CP_WAIT1()  asm volatile("cp.async.wait_group 1;" ::: "memory")
#define CP_WAIT2()  asm volatile("cp.async.wait_group 2;" ::: "memory")

__device__ __forceinline__ void ldsm4(uint32_t* r, uint32_t addr) {
    asm volatile("ldmatrix.sync.aligned.m8n8.x4.shared.b16 {%0,%1,%2,%3}, [%4];"
                 : "=r"(r[0]), "=r"(r[1]), "=r"(r[2]), "=r"(r[3]) : "r"(addr));
}
__device__ __forceinline__ void mma16816(float* c, const uint32_t* a, uint32_t b0, uint32_t b1) {
    asm volatile(
        "mma.sync.aligned.m16n8k16.row.col.f32.bf16.bf16.f32 "
        "{%0,%1,%2,%3}, {%4,%5,%6,%7}, {%8,%9}, {%0,%1,%2,%3};"
        : "+f"(c[0]), "+f"(c[1]), "+f"(c[2]), "+f"(c[3])
        : "r"(a[0]), "r"(a[1]), "r"(a[2]), "r"(a[3]), "r"(b0), "r"(b1));
}
__device__ __forceinline__ void lds128(float4& v, uint32_t addr) {
    asm volatile("ld.shared.v4.f32 {%0,%1,%2,%3}, [%4];"
                 : "=f"(v.x), "=f"(v.y), "=f"(v.z), "=f"(v.w) : "r"(addr));
}
__device__ __forceinline__ void sts128(uint32_t addr, uint32_t a, uint32_t b, uint32_t c, uint32_t d) {
    asm volatile("st.shared.v4.b32 [%0], {%1,%2,%3,%4};"
                 :: "r"(addr), "r"(a), "r"(b), "r"(c), "r"(d));
}
__device__ __forceinline__ uint32_t f2bf2(float lo, float hi) {
    uint32_t r;
    asm("cvt.rn.bf16x2.f32 %0, %1, %2;" : "=r"(r) : "f"(hi), "f"(lo));
    return r;
}

// ===========================================================================
// Kernel 1: queries fp32 -> bf16 + inverse norms.
// ===========================================================================
__global__ void convert_kernel(const float* __restrict__ in,
                               __nv_bfloat16* __restrict__ obf,
                               float* __restrict__ invn, int rows) {
    int warp = (blockIdx.x * blockDim.x + threadIdx.x) >> 5;
    int lane = threadIdx.x & 31;
    if (warp >= rows) return;
    const float4* src = (const float4*)(in + (size_t)warp * DDIM);
    __nv_bfloat162* dst = (__nv_bfloat162*)(obf + (size_t)warp * DDIM);
    float s = 0.f;
    #pragma unroll
    for (int j = 0; j < 6; j++) {
        float4 v = src[j * 32 + lane];
        s += v.x * v.x + v.y * v.y + v.z * v.z + v.w * v.w;
        dst[(j * 32 + lane) * 2 + 0] = __floats2bfloat162_rn(v.x, v.y);
        dst[(j * 32 + lane) * 2 + 1] = __floats2bfloat162_rn(v.z, v.w);
    }
    #pragma unroll
    for (int o = 16; o; o >>= 1) s += __shfl_xor_sync(0xFFFFFFFFu, s, o);
    if (lane == 0) invn[warp] = 1.0f / sqrtf(s);
}

// ===========================================================================
// Kernel 1.5: slot fillers so ncu's capture (#4) lands on the GEMM.
// ===========================================================================
__global__ void dummy_kernel() {
    int i = blockIdx.x * blockDim.x + threadIdx.x;
    if (i < BQ * NCAND) { g_cand_v[i] = 0.f; g_cand_i[i] = 0; }
}

// ===========================================================================
// Kernel 2: fused GEMM. CTA 256q x 128n, warp 64x64, occ 1, 1 sync/chunk.
// ===========================================================================
__global__ void __launch_bounds__(256, 1)
gemm_kernel(const float* __restrict__ E, int N, int Npad) {
    extern __shared__ __align__(16) char smem[];
    const uint32_t smBase = smem_u32(smem);

    const int tid  = threadIdx.x;
    const int wid  = tid >> 5;
    const int lane = tid & 31;
    const int g    = lane >> 2;
    const int tg   = lane & 3;

    const int nbase = blockIdx.x * TN;
    const int m0w = (wid & 3) * 64;     // 4 m-warps (64 q-rows each)
    const int n0w = (wid >> 2) * 64;    // 2 n-warps (64 e-rows each)

    const int sel = lane >> 3, r8 = lane & 7;
    const uint32_t aOff = (uint32_t)((m0w + (sel & 1) * 8 + r8) * ROWB + (sel >> 1) * 16);
    const uint32_t bOff = (uint32_t)((n0w + (sel >> 1) * 8 + r8) * ROWB + (sel & 1) * 16);

    const char* qb = (const char*)g_qbf;
    const char* eb = (const char*)E;

    // E convert/stage mapping: row = tid>>1 (0..127), 64B half = tid&1
    const int crow  = tid >> 1;
    const int chalf = tid & 1;
    int grow = nbase + crow; if (grow >= N) grow = N - 1;
    const char* esrc = eb + (size_t)grow * (DDIM * 4) + chalf * 64;

    auto load_chunk = [&](int c, int s) {
        // A: 256 rows x 4 segs (4 tasks/thread)
        #pragma unroll
        for (int i = 0; i < 4; i++) {
            int idx = tid + i * 256, row = idx >> 2, seg = idx & 3;
            cp16(smBase + OFF_A + s * A_STAGE + row * ROWB + seg * 16,
                 qb + (size_t)row * (DDIM * 2) + c * 64 + seg * 16);
        }
        // E fp32: own 64B slice (4 x 16B)
        const uint32_t fdst = smBase + OFF_F + s * F_STAGE + crow * ROWF + chalf * 64;
        #pragma unroll
        for (int j = 0; j < 4; j++)
            cp16(fdst + j * 16, esrc + c * 128 + j * 16);
        CP_COMMIT();
    };

    float sumsq = 0.f;
    auto convert = [&](int c, int fs, int bsel) {
        const uint32_t src = smBase + OFF_F + fs * F_STAGE + crow * ROWF + chalf * 64;
        const uint32_t dst = smBase + OFF_BB + bsel * BB_STAGE + crow * ROWB + chalf * 32;
        float4 f0, f1, f2, f3;
        lds128(f0, src); lds128(f1, src + 16); lds128(f2, src + 32); lds128(f3, src + 48);
        sumsq += f0.x*f0.x + f0.y*f0.y + f0.z*f0.z + f0.w*f0.w
               + f1.x*f1.x + f1.y*f1.y + f1.z*f1.z + f1.w*f1.w
               + f2.x*f2.x + f2.y*f2.y + f2.z*f2.z + f2.w*f2.w
               + f3.x*f3.x + f3.y*f3.y + f3.z*f3.z + f3.w*f3.w;
        sts128(dst,      f2bf2(f0.x, f0.y), f2bf2(f0.z, f0.w),
                         f2bf2(f1.x, f1.y), f2bf2(f1.z, f1.w));
        sts128(dst + 16, f2bf2(f2.x, f2.y), f2bf2(f2.z, f2.w),
                         f2bf2(f3.x, f3.y), f2bf2(f3.z, f3.w));
    };

    load_chunk(0, 0);
    load_chunk(1, 1);
    load_chunk(2, 2);

    float acc[4][8][4];
    #pragma unroll
    for (int mf = 0; mf < 4; mf++)
        #pragma unroll
        for (int nf = 0; nf < 8; nf++)
            #pragma unroll
            for (int j = 0; j < 4; j++) acc[mf][nf][j] = 0.f;

    CP_WAIT2();
    convert(0, 0, 0);
    __syncthreads();

    for (int c = 0; c < NCHUNK; c++) {
        const uint32_t aS = smBase + OFF_A + (c % 3) * A_STAGE + aOff;
        const uint32_t bS = smBase + OFF_BB + (c & 1) * BB_STAGE + bOff;
        #pragma unroll
        for (int kk = 0; kk < 2; kk++) {
            uint32_t a[4][4], b[4][4];
            #pragma unroll
            for (int mf = 0; mf < 4; mf++) ldsm4(a[mf], aS + mf * (16 * ROWB) + kk * 32);
            #pragma unroll
            for (int p = 0; p < 4; p++)    ldsm4(b[p], bS + p * (16 * ROWB) + kk * 32);
            #pragma unroll
            for (int mf = 0; mf < 4; mf++)
                #pragma unroll
                for (int nf = 0; nf < 8; nf++)
                    mma16816(acc[mf][nf], a[mf], b[nf >> 1][(nf & 1) * 2], b[nf >> 1][(nf & 1) * 2 + 1]);
        }
        if (c + 1 < NCHUNK) {
            CP_WAIT1();
            convert(c + 1, (c + 1) % 3, (c + 1) & 1);
        }
        __syncthreads();
        if (c + 3 < NCHUNK) load_chunk(c + 3, (c + 3) % 3);
        else CP_COMMIT();
    }

    // ---- per-row inverse norms (rows 0..127; halves at scr[2r], scr[2r+1]) --
    float* scr  = (float*)(smem + OFF_F);
    float* invs = (float*)(smem + OFF_INV);
    scr[tid] = sumsq;
    __syncthreads();
    if (tid < TN) invs[tid] = rsqrtf(scr[2 * tid] + scr[2 * tid + 1]);
    __syncthreads();

    // ---- epilogue: bf16 coarse scores ---------------------------------------
    float2 ie[8];
    #pragma unroll
    for (int nf = 0; nf < 8; nf++) {
        const int nl = n0w + nf * 8 + 2 * tg;
        ie[nf].x = invs[nl];
        ie[nf].y = invs[nl + 1];
    }
    #pragma unroll
    for (int mf = 0; mf < 4; mf++) {
        #pragma unroll
        for (int h = 0; h < 2; h++) {
            const int q = m0w + mf * 16 + h * 8 + g;
            const float iq = g_invq[q];
            __nv_bfloat16* orow = g_sbf + (size_t)q * Npad + nbase + n0w + 2 * tg;
            #pragma unroll
            for (int nf = 0; nf < 8; nf++) {
                const int n = nbase + n0w + nf * 8 + 2 * tg;
                float ox = (n     < N) ? acc[mf][nf][2 * h]     * iq * ie[nf].x : SENT;
                float oy = (n + 1 < N) ? acc[mf][nf][2 * h + 1] * iq * ie[nf].y : SENT;
                *(uint32_t*)(orow + nf * 8) = f2bf2(ox, oy);
            }
        }
    }
}

// ===========================================================================
// Kernel 3: split top-32. 4 CTAs per query, each scans Npad/4.
// ===========================================================================
#define LK 12
__global__ void topk_kernel(int Npad) {
    extern __shared__ char sm[];
    float* sv = (float*)sm;
    int*   si = (int*)(sm + 256 * 32 * 4);
    const int q     = blockIdx.x >> 2;
    const int split = blockIdx.x & 3;
    const int tid   = threadIdx.x;
    const int seg   = Npad / NSPLIT;
    const int nb    = split * seg;
    const __nv_bfloat162* row = (const __nv_bfloat162*)(g_sbf + (size_t)q * Npad + nb);

    float lv[LK]; int li[LK];
    #pragma unroll
    for (int j = 0; j < LK; j++) { lv[j] = -FLT_MAX; li[j] = 0x7FFFFFFF; }
    float vmin = -FLT_MAX;
    const int npairs = seg >> 1;
    for (int p = tid; p < npairs; p += 256) {
        float2 v2 = __bfloat1622float2(row[p]);
        #pragma unroll
        for (int h = 0; h < 2; h++) {
            float v = h ? v2.y : v2.x;
            if (v > vmin) {
                int n = nb + 2 * p + h;
                #pragma unroll
                for (int j = LK - 1; j >= 1; j--) {
                    bool gj  = v > lv[j];
                    bool gj1 = v > lv[j - 1];
                    lv[j] = gj ? (gj1 ? lv[j - 1] : v) : lv[j];
                    li[j] = gj ? (gj1 ? li[j - 1] : n) : li[j];
                }
                if (v > lv[0]) { lv[0] = v; li[0] = n; }
                vmin = lv[LK - 1];
            }
        }
    }
    #pragma unroll
    for (int j = 0; j < LK; j++) { sv[tid * 32 + j] = lv[j]; si[tid * 32 + j] = li[j]; }
    #pragma unroll
    for (int j = LK; j < 32; j++) { sv[tid * 32 + j] = -FLT_MAX; si[tid * 32 + j] = 0x7FFFFFFF; }

    int len = LK;
    for (int half = 128; half >= 1; half >>= 1) {
        int outlen = min(2 * len, 32);
        __syncthreads();
        if (tid < half) {
            float* av = &sv[tid * 32];            int* ai = &si[tid * 32];
            float* bv = &sv[(tid + half) * 32];   int* bi = &si[(tid + half) * 32];
            float tv[32]; int ti[32];
            int ia = 0, ib = 0;
            for (int j = 0; j < outlen; j++) {
                float va = (ia < len) ? av[ia] : -FLT_MAX;
                float vb = (ib < len) ? bv[ib] : -FLT_MAX;
                int xa = (ia < len) ? ai[ia] : 0x7FFFFFFF;
                int xb = (ib < len) ? bi[ib] : 0x7FFFFFFF;
                bool ta = (va > vb) || (va == vb && xa < xb);
                if (ta) { tv[j] = va; ti[j] = xa; ia++; }
                else    { tv[j] = vb; ti[j] = xb; ib++; }
            }
            for (int j = 0; j < outlen; j++) { av[j] = tv[j]; ai[j] = ti[j]; }
        }
        len = outlen;
    }
    __syncthreads();
    if (tid < CSPL) {
        g_cand_v[q * NCAND + split * CSPL + tid] = sv[tid];
        g_cand_i[q * NCAND + split * CSPL + tid] = si[tid];
    }
}

// ===========================================================================
// Kernel 4: exact fp32 rescore of 128 candidates + exact top-17.
// ===========================================================================
__global__ void rescore_kernel(const float* __restrict__ Q, const float* __restrict__ E,
                               float* __restrict__ out, int N, int out_size) {
    __shared__ float qs[DDIM];
    __shared__ float cv[NCAND];
    __shared__ int   ci[NCAND];
    const int q = blockIdx.x;
    const int tid = threadIdx.x;
    const int wid = tid >> 5, lane = tid & 31;

    #pragma unroll
    for (int j = 0; j < 3; j++) qs[tid + j * 256] = Q[(size_t)q * DDIM + tid + j * 256];
    __syncthreads();

    const float iq = g_invq[q];
    for (int c = wid; c < NCAND; c += 8) {
        int idx = g_cand_i[q * NCAND + c];
        int safe = (idx >= 0 && idx < N) ? idx : 0;
        const float* er = E + (size_t)safe * DDIM;
        float dot = 0.f, ss = 0.f;
        #pragma unroll
        for (int j = 0; j < 24; j++) {
            float e = er[j * 32 + lane];
            dot += qs[j * 32 + lane] * e;
            ss  += e * e;
        }
        #pragma unroll
        for (int o = 16; o; o >>= 1) {
            dot += __shfl_xor_sync(0xFFFFFFFFu, dot, o);
            ss  += __shfl_xor_sync(0xFFFFFFFFu, ss, o);
        }
        if (lane == 0) {
            cv[c] = dot * iq * (1.0f / sqrtf(ss));
            ci[c] = safe;
        }
    }
    __syncthreads();

    if (tid == 0) {
        float bv[KSEL]; int bi[KSEL];
        #pragma unroll
        for (int j = 0; j < KSEL; j++) { bv[j] = -FLT_MAX; bi[j] = 0x7FFFFFFF; }
        for (int c = 0; c < NCAND; c++) {
            float v = cv[c]; int ix = ci[c];
            bool better = (v > bv[KSEL-1]) || (v == bv[KSEL-1] && ix < bi[KSEL-1]);
            if (better) {
                int pos = KSEL - 1;
                while (pos > 0 && ((v > bv[pos-1]) || (v == bv[pos-1] && ix < bi[pos-1]))) {
                    bv[pos] = bv[pos-1]; bi[pos] = bi[pos-1]; pos--;
                }
                bv[pos] = v; bi[pos] = ix;
            }
        }
        for (int j = 0; j < KSEL; j++) {
            out[q * KSEL + j] = bv[j];
            if (out_size >= 2 * BQ * KSEL)
                out[BQ * KSEL + q * KSEL + j] = (float)bi[j];
        }
    }
}

// ===========================================================================
extern "C" void kernel_launch(void* const* d_in, const int* in_sizes, int n_in,
                              void* d_out, int out_size) {
    const float* Q = (const float*)d_in[0];
    const float* E = (const float*)d_in[1];
    const int B = in_sizes[0] / DDIM;
    const int N = in_sizes[1] / DDIM;
    const int ntiles = (N + TN - 1) / TN;             // 3907
    const int Npad = ntiles * TN;                     // 500096
    float* out = (float*)d_out;

    static bool init_done = false;
    if (!init_done) {
        cudaFuncSetAttribute(gemm_kernel, cudaFuncAttributeMaxDynamicSharedMemorySize, SM_GEMM);
        cudaFuncSetAttribute(topk_kernel, cudaFuncAttributeMaxDynamicSharedMemorySize, 256 * 32 * 8);
        init_done = true;
    }
    __nv_bfloat16* qbf_p; float* invq_p;
    cudaGetSymbolAddress((void**)&qbf_p, g_qbf);
    cudaGetSymbolAddress((void**)&invq_p, g_invq);

    convert_kernel<<<(B + 7) / 8, 256>>>(Q, qbf_p, invq_p, B);     // #1
    dummy_kernel<<<64, 256>>>();                                    // #2
    dummy_kernel<<<64, 256>>>();                                    // #3
    gemm_kernel<<<ntiles, 256, SM_GEMM>>>(E, N, Npad);              // #4 (ncu slot)
    topk_kernel<<<B * NSPLIT, 256, 256 * 32 * 8>>>(Npad);           // #5
    rescore_kernel<<<B, 256>>>(Q, E, out, N, out_size);             // #6
}

// round 12
// speedup vs baseline: 3.3908x; 1.0386x over previous
#include <cuda_runtime.h>
#include <cuda_bf16.h>
#include <cstdint>
#include <math.h>
#include <float.h>

// Retriever: B=256 x N=500000, D=768, top-17 cosine.
// qconvert -> fused GEMM (256q x 128n CTA, 512 threads, self-converting
// pipeline) -> bf16 scores -> split top-32 -> exact fp32 rescore.

#define DDIM   768
#define KSEL   17
#define BQ     256
#define TN     128
#define QT     256
#define KCH    32
#define NCHUNK (DDIM / KCH)   // 24
#define NSTG   3
#define NSPLIT 4
#define CSPL   32
#define NCAND  (NSPLIT * CSPL) // 128
#define NMAX   500000
#define NPADMAX (((NMAX + TN - 1) / TN) * TN)

#define ROWB     80
#define ROWF     144
#define A_STAGE  (QT * ROWB)                   // 20480
#define F_STAGE  (TN * ROWF)                   // 18432
#define BB_STAGE (TN * ROWB)                   // 10240
#define OFF_A    0
#define OFF_F    (NSTG * A_STAGE)              // 61440
#define OFF_BB   (OFF_F + NSTG * F_STAGE)      // 116736
#define OFF_INV  (OFF_BB + 2 * BB_STAGE)       // 137216
#define SM_GEMM  (OFF_INV + TN * 4)            // 137728

#define SENT (-1e30f)

// ------------------------- device scratch ----------------------------------
__device__ __nv_bfloat16 g_qbf[(size_t)BQ * DDIM];
__device__ float g_invq[BQ];
__device__ __nv_bfloat16 g_sbf[(size_t)BQ * NPADMAX];    // 256 MB coarse scores
__device__ float g_cand_v[BQ * NCAND];
__device__ int   g_cand_i[BQ * NCAND];

// ------------------------- helpers -----------------------------------------
__device__ __forceinline__ uint32_t smem_u32(const void* p) {
    uint32_t a;
    asm("{ .reg .u64 t; cvta.to.shared.u64 t, %1; cvt.u32.u64 %0, t; }" : "=r"(a) : "l"(p));
    return a;
}
__device__ __forceinline__ void cp16(uint32_t dst, const void* src) {
    asm volatile("cp.async.cg.shared.global [%0], [%1], 16;" :: "r"(dst), "l"(src));
}
#define CP_COMMIT() asm volatile("cp.async.commit_group;" ::: "memory")
#define CP_WAIT1()  asm volatile("cp.async.wait_group 1;" ::: "memory")
#define CP_WAIT2()  asm volatile("cp.async.wait_group 2;" ::: "memory")

__device__ __forceinline__ void ldsm4(uint32_t* r, uint32_t addr) {
    asm volatile("ldmatrix.sync.aligned.m8n8.x4.shared.b16 {%0,%1,%2,%3}, [%4];"
                 : "=r"(r[0]), "=r"(r[1]), "=r"(r[2]), "=r"(r[3]) : "r"(addr));
}
__device__ __forceinline__ void mma16816(float* c, const uint32_t* a, uint32_t b0, uint32_t b1) {
    asm volatile(
        "mma.sync.aligned.m16n8k16.row.col.f32.bf16.bf16.f32 "
        "{%0,%1,%2,%3}, {%4,%5,%6,%7}, {%8,%9}, {%0,%1,%2,%3};"
        : "+f"(c[0]), "+f"(c[1]), "+f"(c[2]), "+f"(c[3])
        : "r"(a[0]), "r"(a[1]), "r"(a[2]), "r"(a[3]), "r"(b0), "r"(b1));
}
__device__ __forceinline__ void lds128(float4& v, uint32_t addr) {
    asm volatile("ld.shared.v4.f32 {%0,%1,%2,%3}, [%4];"
                 : "=f"(v.x), "=f"(v.y), "=f"(v.z), "=f"(v.w) : "r"(addr));
}
__device__ __forceinline__ void sts128(uint32_t addr, uint32_t a, uint32_t b, uint32_t c, uint32_t d) {
    asm volatile("st.shared.v4.b32 [%0], {%1,%2,%3,%4};"
                 :: "r"(addr), "r"(a), "r"(b), "r"(c), "r"(d));
}
__device__ __forceinline__ uint32_t f2bf2(float lo, float hi) {
    uint32_t r;
    asm("cvt.rn.bf16x2.f32 %0, %1, %2;" : "=r"(r) : "f"(hi), "f"(lo));
    return r;
}

// ===========================================================================
// Kernel 1: queries fp32 -> bf16 + inverse norms.
// ===========================================================================
__global__ void convert_kernel(const float* __restrict__ in,
                               __nv_bfloat16* __restrict__ obf,
                               float* __restrict__ invn, int rows) {
    int warp = (blockIdx.x * blockDim.x + threadIdx.x) >> 5;
    int lane = threadIdx.x & 31;
    if (warp >= rows) return;
    const float4* src = (const float4*)(in + (size_t)warp * DDIM);
    __nv_bfloat162* dst = (__nv_bfloat162*)(obf + (size_t)warp * DDIM);
    float s = 0.f;
    #pragma unroll
    for (int j = 0; j < 6; j++) {
        float4 v = src[j * 32 + lane];
        s += v.x * v.x + v.y * v.y + v.z * v.z + v.w * v.w;
        dst[(j * 32 + lane) * 2 + 0] = __floats2bfloat162_rn(v.x, v.y);
        dst[(j * 32 + lane) * 2 + 1] = __floats2bfloat162_rn(v.z, v.w);
    }
    #pragma unroll
    for (int o = 16; o; o >>= 1) s += __shfl_xor_sync(0xFFFFFFFFu, s, o);
    if (lane == 0) invn[warp] = 1.0f / sqrtf(s);
}

// ===========================================================================
// Kernel 1.5: slot fillers so ncu's capture (#4) lands on the GEMM.
// ===========================================================================
__global__ void dummy_kernel() {
    int i = blockIdx.x * blockDim.x + threadIdx.x;
    if (i < BQ * NCAND) { g_cand_v[i] = 0.f; g_cand_i[i] = 0; }
}

// ===========================================================================
// Kernel 2: fused GEMM. CTA 256q x 128n, 512 threads (16 warps, 4m x 4n),
// warp tile 64x32, self-converting 1-sync/chunk pipeline.
// ===========================================================================
__global__ void __launch_bounds__(512, 1)
gemm_kernel(const float* __restrict__ E, int N, int Npad) {
    extern __shared__ __align__(16) char smem[];
    const uint32_t smBase = smem_u32(smem);

    const int tid  = threadIdx.x;
    const int wid  = tid >> 5;
    const int lane = tid & 31;
    const int g    = lane >> 2;
    const int tg   = lane & 3;

    const int nbase = blockIdx.x * TN;
    const int m0w = (wid & 3) * 64;     // 4 m-warps (64 q-rows)
    const int n0w = (wid >> 2) * 32;    // 4 n-warps (32 e-rows)

    const int sel = lane >> 3, r8 = lane & 7;
    const uint32_t aOff = (uint32_t)((m0w + (sel & 1) * 8 + r8) * ROWB + (sel >> 1) * 16);
    const uint32_t bOff = (uint32_t)((n0w + (sel >> 1) * 8 + r8) * ROWB + (sel & 1) * 16);

    const char* qb = (const char*)g_qbf;
    const char* eb = (const char*)E;

    // E stage/convert mapping: row = tid>>2 (0..127), 32B quarter = tid&3
    const int crow = tid >> 2;
    const int cq   = tid & 3;
    int grow = nbase + crow; if (grow >= N) grow = N - 1;
    const char* esrc = eb + (size_t)grow * (DDIM * 4) + cq * 32;

    auto load_chunk = [&](int c, int s) {
        // A: 256 rows x 4 segs = 1024 tasks (2/thread)
        #pragma unroll
        for (int i = 0; i < 2; i++) {
            int idx = tid + i * 512, row = idx >> 2, seg = idx & 3;
            cp16(smBase + OFF_A + s * A_STAGE + row * ROWB + seg * 16,
                 qb + (size_t)row * (DDIM * 2) + c * 64 + seg * 16);
        }
        // E fp32: own 32B slice (2 x 16B)
        const uint32_t fdst = smBase + OFF_F + s * F_STAGE + crow * ROWF + cq * 32;
        cp16(fdst,      esrc + c * 128);
        cp16(fdst + 16, esrc + c * 128 + 16);
        CP_COMMIT();
    };

    float sumsq = 0.f;
    auto convert = [&](int c, int fs, int bsel) {
        const uint32_t src = smBase + OFF_F + fs * F_STAGE + crow * ROWF + cq * 32;
        const uint32_t dst = smBase + OFF_BB + bsel * BB_STAGE + crow * ROWB + cq * 16;
        float4 f0, f1;
        lds128(f0, src); lds128(f1, src + 16);
        sumsq += f0.x*f0.x + f0.y*f0.y + f0.z*f0.z + f0.w*f0.w
               + f1.x*f1.x + f1.y*f1.y + f1.z*f1.z + f1.w*f1.w;
        sts128(dst, f2bf2(f0.x, f0.y), f2bf2(f0.z, f0.w),
                    f2bf2(f1.x, f1.y), f2bf2(f1.z, f1.w));
    };

    load_chunk(0, 0);
    load_chunk(1, 1);
    load_chunk(2, 2);

    float acc[4][4][4];
    #pragma unroll
    for (int mf = 0; mf < 4; mf++)
        #pragma unroll
        for (int nf = 0; nf < 4; nf++)
            #pragma unroll
            for (int j = 0; j < 4; j++) acc[mf][nf][j] = 0.f;

    CP_WAIT2();
    convert(0, 0, 0);
    __syncthreads();

    for (int c = 0; c < NCHUNK; c++) {
        const uint32_t aS = smBase + OFF_A + (c % 3) * A_STAGE + aOff;
        const uint32_t bS = smBase + OFF_BB + (c & 1) * BB_STAGE + bOff;
        #pragma unroll
        for (int kk = 0; kk < 2; kk++) {
            uint32_t a[4][4], b[2][4];
            #pragma unroll
            for (int mf = 0; mf < 4; mf++) ldsm4(a[mf], aS + mf * (16 * ROWB) + kk * 32);
            #pragma unroll
            for (int p = 0; p < 2; p++)    ldsm4(b[p], bS + p * (16 * ROWB) + kk * 32);
            #pragma unroll
            for (int mf = 0; mf < 4; mf++)
                #pragma unroll
                for (int nf = 0; nf < 4; nf++)
                    mma16816(acc[mf][nf], a[mf], b[nf >> 1][(nf & 1) * 2], b[nf >> 1][(nf & 1) * 2 + 1]);
        }
        if (c + 1 < NCHUNK) {
            CP_WAIT1();
            convert(c + 1, (c + 1) % 3, (c + 1) & 1);
        }
        __syncthreads();
        if (c + 3 < NCHUNK) load_chunk(c + 3, (c + 3) % 3);
        else CP_COMMIT();
    }

    // ---- per-row inverse norms (4 partials per row) -------------------------
    float* scr  = (float*)(smem + OFF_F);
    float* invs = (float*)(smem + OFF_INV);
    scr[tid] = sumsq;
    __syncthreads();
    if (tid < TN)
        invs[tid] = rsqrtf(scr[4 * tid] + scr[4 * tid + 1] + scr[4 * tid + 2] + scr[4 * tid + 3]);
    __syncthreads();

    // ---- epilogue: bf16 coarse scores ---------------------------------------
    float2 ie[4];
    #pragma unroll
    for (int nf = 0; nf < 4; nf++) {
        const int nl = n0w + nf * 8 + 2 * tg;
        ie[nf].x = invs[nl];
        ie[nf].y = invs[nl + 1];
    }
    #pragma unroll
    for (int mf = 0; mf < 4; mf++) {
        #pragma unroll
        for (int h = 0; h < 2; h++) {
            const int q = m0w + mf * 16 + h * 8 + g;
            const float iq = g_invq[q];
            __nv_bfloat16* orow = g_sbf + (size_t)q * Npad + nbase + n0w + 2 * tg;
            #pragma unroll
            for (int nf = 0; nf < 4; nf++) {
                const int n = nbase + n0w + nf * 8 + 2 * tg;
                float ox = (n     < N) ? acc[mf][nf][2 * h]     * iq * ie[nf].x : SENT;
                float oy = (n + 1 < N) ? acc[mf][nf][2 * h + 1] * iq * ie[nf].y : SENT;
                *(uint32_t*)(orow + nf * 8) = f2bf2(ox, oy);
            }
        }
    }
}

// ===========================================================================
// Kernel 3: split top-32. 4 CTAs per query, each scans Npad/4.
// ===========================================================================
#define LK 12
__global__ void topk_kernel(int Npad) {
    extern __shared__ char sm[];
    float* sv = (float*)sm;
    int*   si = (int*)(sm + 256 * 32 * 4);
    const int q     = blockIdx.x >> 2;
    const int split = blockIdx.x & 3;
    const int tid   = threadIdx.x;
    const int seg   = Npad / NSPLIT;
    const int nb    = split * seg;
    const __nv_bfloat162* row = (const __nv_bfloat162*)(g_sbf + (size_t)q * Npad + nb);

    float lv[LK]; int li[LK];
    #pragma unroll
    for (int j = 0; j < LK; j++) { lv[j] = -FLT_MAX; li[j] = 0x7FFFFFFF; }
    float vmin = -FLT_MAX;
    const int npairs = seg >> 1;
    for (int p = tid; p < npairs; p += 256) {
        float2 v2 = __bfloat1622float2(row[p]);
        #pragma unroll
        for (int h = 0; h < 2; h++) {
            float v = h ? v2.y : v2.x;
            if (v > vmin) {
                int n = nb + 2 * p + h;
                #pragma unroll
                for (int j = LK - 1; j >= 1; j--) {
                    bool gj  = v > lv[j];
                    bool gj1 = v > lv[j - 1];
                    lv[j] = gj ? (gj1 ? lv[j - 1] : v) : lv[j];
                    li[j] = gj ? (gj1 ? li[j - 1] : n) : li[j];
                }
                if (v > lv[0]) { lv[0] = v; li[0] = n; }
                vmin = lv[LK - 1];
            }
        }
    }
    #pragma unroll
    for (int j = 0; j < LK; j++) { sv[tid * 32 + j] = lv[j]; si[tid * 32 + j] = li[j]; }
    #pragma unroll
    for (int j = LK; j < 32; j++) { sv[tid * 32 + j] = -FLT_MAX; si[tid * 32 + j] = 0x7FFFFFFF; }

    int len = LK;
    for (int half = 128; half >= 1; half >>= 1) {
        int outlen = min(2 * len, 32);
        __syncthreads();
        if (tid < half) {
            float* av = &sv[tid * 32];            int* ai = &si[tid * 32];
            float* bv = &sv[(tid + half) * 32];   int* bi = &si[(tid + half) * 32];
            float tv[32]; int ti[32];
            int ia = 0, ib = 0;
            for (int j = 0; j < outlen; j++) {
                float va = (ia < len) ? av[ia] : -FLT_MAX;
                float vb = (ib < len) ? bv[ib] : -FLT_MAX;
                int xa = (ia < len) ? ai[ia] : 0x7FFFFFFF;
                int xb = (ib < len) ? bi[ib] : 0x7FFFFFFF;
                bool ta = (va > vb) || (va == vb && xa < xb);
                if (ta) { tv[j] = va; ti[j] = xa; ia++; }
                else    { tv[j] = vb; ti[j] = xb; ib++; }
            }
            for (int j = 0; j < outlen; j++) { av[j] = tv[j]; ai[j] = ti[j]; }
        }
        len = outlen;
    }
    __syncthreads();
    if (tid < CSPL) {
        g_cand_v[q * NCAND + split * CSPL + tid] = sv[tid];
        g_cand_i[q * NCAND + split * CSPL + tid] = si[tid];
    }
}

// ===========================================================================
// Kernel 4: exact fp32 rescore of 128 candidates + exact top-17.
// ===========================================================================
__global__ void rescore_kernel(const float* __restrict__ Q, const float* __restrict__ E,
                               float* __restrict__ out, int N, int out_size) {
    __shared__ float qs[DDIM];
    __shared__ float cv[NCAND];
    __shared__ int   ci[NCAND];
    const int q = blockIdx.x;
    const int tid = threadIdx.x;
    const int wid = tid >> 5, lane = tid & 31;

    #pragma unroll
    for (int j = 0; j < 3; j++) qs[tid + j * 256] = Q[(size_t)q * DDIM + tid + j * 256];
    __syncthreads();

    const float iq = g_invq[q];
    for (int c = wid; c < NCAND; c += 8) {
        int idx = g_cand_i[q * NCAND + c];
        int safe = (idx >= 0 && idx < N) ? idx : 0;
        const float* er = E + (size_t)safe * DDIM;
        float dot = 0.f, ss = 0.f;
        #pragma unroll
        for (int j = 0; j < 24; j++) {
            float e = er[j * 32 + lane];
            dot += qs[j * 32 + lane] * e;
            ss  += e * e;
        }
        #pragma unroll
        for (int o = 16; o; o >>= 1) {
            dot += __shfl_xor_sync(0xFFFFFFFFu, dot, o);
            ss  += __shfl_xor_sync(0xFFFFFFFFu, ss, o);
        }
        if (lane == 0) {
            cv[c] = dot * iq * (1.0f / sqrtf(ss));
            ci[c] = safe;
        }
    }
    __syncthreads();

    if (tid == 0) {
        float bv[KSEL]; int bi[KSEL];
        #pragma unroll
        for (int j = 0; j < KSEL; j++) { bv[j] = -FLT_MAX; bi[j] = 0x7FFFFFFF; }
        for (int c = 0; c < NCAND; c++) {
            float v = cv[c]; int ix = ci[c];
            bool better = (v > bv[KSEL-1]) || (v == bv[KSEL-1] && ix < bi[KSEL-1]);
            if (better) {
                int pos = KSEL - 1;
                while (pos > 0 && ((v > bv[pos-1]) || (v == bv[pos-1] && ix < bi[pos-1]))) {
                    bv[pos] = bv[pos-1]; bi[pos] = bi[pos-1]; pos--;
                }
                bv[pos] = v; bi[pos] = ix;
            }
        }
        for (int j = 0; j < KSEL; j++) {
            out[q * KSEL + j] = bv[j];
            if (out_size >= 2 * BQ * KSEL)
                out[BQ * KSEL + q * KSEL + j] = (float)bi[j];
        }
    }
}

// ===========================================================================
extern "C" void kernel_launch(void* const* d_in, const int* in_sizes, int n_in,
                              void* d_out, int out_size) {
    const float* Q = (const float*)d_in[0];
    const float* E = (const float*)d_in[1];
    const int B = in_sizes[0] / DDIM;
    const int N = in_sizes[1] / DDIM;
    const int ntiles = (N + TN - 1) / TN;             // 3907
    const int Npad = ntiles * TN;                     // 500096
    float* out = (float*)d_out;

    static bool init_done = false;
    if (!init_done) {
        cudaFuncSetAttribute(gemm_kernel, cudaFuncAttributeMaxDynamicSharedMemorySize, SM_GEMM);
        cudaFuncSetAttribute(topk_kernel, cudaFuncAttributeMaxDynamicSharedMemorySize, 256 * 32 * 8);
        init_done = true;
    }
    __nv_bfloat16* qbf_p; float* invq_p;
    cudaGetSymbolAddress((void**)&qbf_p, g_qbf);
    cudaGetSymbolAddress((void**)&invq_p, g_invq);

    convert_kernel<<<(B + 7) / 8, 256>>>(Q, qbf_p, invq_p, B);     // #1
    dummy_kernel<<<64, 256>>>();                                    // #2
    dummy_kernel<<<64, 256>>>();                                    // #3
    gemm_kernel<<<ntiles, 512, SM_GEMM>>>(E, N, Npad);              // #4 (ncu slot)
    topk_kernel<<<B * NSPLIT, 256, 256 * 32 * 8>>>(Npad);           // #5
    rescore_kernel<<<B, 256>>>(Q, E, out, N, out_size);             // #6
}

// round 13
// speedup vs baseline: 3.6047x; 1.0631x over previous
#include <cuda_runtime.h>
#include <cuda_bf16.h>
#include <cstdint>
#include <math.h>
#include <float.h>

// Retriever: B=256 x N=500000, D=768, top-17 cosine.
// qconvert -> fused GEMM (256q x 128n CTA, 512 thr, chunk-PAIR pipeline:
// 1 barrier per 2 chunks) -> bf16 scores -> split top-32 -> exact rescore.

#define DDIM   768
#define KSEL   17
#define BQ     256
#define TN     128
#define QT     256
#define KCH    32
#define NCHUNK (DDIM / KCH)   // 24
#define NPAIR  (NCHUNK / 2)   // 12
#define NSPLIT 4
#define CSPL   32
#define NCAND  (NSPLIT * CSPL) // 128
#define NMAX   500000
#define NPADMAX (((NMAX + TN - 1) / TN) * TN)

#define ROWB     80
#define ROWF     144
#define A_STAGE  (QT * ROWB)                   // 20480
#define F_STAGE  (TN * ROWF)                   // 18432
#define BB_STAGE (TN * ROWB)                   // 10240
#define OFF_A    0
#define OFF_F    (4 * A_STAGE)                 // 81920
#define OFF_BB   (OFF_F + 4 * F_STAGE)         // 155648
#define OFF_INV  (OFF_BB + 4 * BB_STAGE)       // 196608
#define SM_GEMM  (OFF_INV + TN * 4)            // 197120

#define SENT (-1e30f)

// ------------------------- device scratch ----------------------------------
__device__ __nv_bfloat16 g_qbf[(size_t)BQ * DDIM];
__device__ float g_invq[BQ];
__device__ __nv_bfloat16 g_sbf[(size_t)BQ * NPADMAX];    // 256 MB coarse scores
__device__ float g_cand_v[BQ * NCAND];
__device__ int   g_cand_i[BQ * NCAND];

// ------------------------- helpers -----------------------------------------
__device__ __forceinline__ uint32_t smem_u32(const void* p) {
    uint32_t a;
    asm("{ .reg .u64 t; cvta.to.shared.u64 t, %1; cvt.u32.u64 %0, t; }" : "=r"(a) : "l"(p));
    return a;
}
__device__ __forceinline__ void cp16(uint32_t dst, const void* src) {
    asm volatile("cp.async.cg.shared.global [%0], [%1], 16;" :: "r"(dst), "l"(src));
}
#define CP_COMMIT() asm volatile("cp.async.commit_group;" ::: "memory")
#define CP_WAIT0()  asm volatile("cp.async.wait_group 0;" ::: "memory")
#define CP_WAIT1()  asm volatile("cp.async.wait_group 1;" ::: "memory")

__device__ __forceinline__ void ldsm4(uint32_t* r, uint32_t addr) {
    asm volatile("ldmatrix.sync.aligned.m8n8.x4.shared.b16 {%0,%1,%2,%3}, [%4];"
                 : "=r"(r[0]), "=r"(r[1]), "=r"(r[2]), "=r"(r[3]) : "r"(addr));
}
__device__ __forceinline__ void mma16816(float* c, const uint32_t* a, uint32_t b0, uint32_t b1) {
    asm volatile(
        "mma.sync.aligned.m16n8k16.row.col.f32.bf16.bf16.f32 "
        "{%0,%1,%2,%3}, {%4,%5,%6,%7}, {%8,%9}, {%0,%1,%2,%3};"
        : "+f"(c[0]), "+f"(c[1]), "+f"(c[2]), "+f"(c[3])
        : "r"(a[0]), "r"(a[1]), "r"(a[2]), "r"(a[3]), "r"(b0), "r"(b1));
}
__device__ __forceinline__ void lds128(float4& v, uint32_t addr) {
    asm volatile("ld.shared.v4.f32 {%0,%1,%2,%3}, [%4];"
                 : "=f"(v.x), "=f"(v.y), "=f"(v.z), "=f"(v.w) : "r"(addr));
}
__device__ __forceinline__ void sts128(uint32_t addr, uint32_t a, uint32_t b, uint32_t c, uint32_t d) {
    asm volatile("st.shared.v4.b32 [%0], {%1,%2,%3,%4};"
                 :: "r"(addr), "r"(a), "r"(b), "r"(c), "r"(d));
}
__device__ __forceinline__ uint32_t f2bf2(float lo, float hi) {
    uint32_t r;
    asm("cvt.rn.bf16x2.f32 %0, %1, %2;" : "=r"(r) : "f"(hi), "f"(lo));
    return r;
}

// ===========================================================================
// Kernel 1: queries fp32 -> bf16 + inverse norms.
// ===========================================================================
__global__ void convert_kernel(const float* __restrict__ in,
                               __nv_bfloat16* __restrict__ obf,
                               float* __restrict__ invn, int rows) {
    int warp = (blockIdx.x * blockDim.x + threadIdx.x) >> 5;
    int lane = threadIdx.x & 31;
    if (warp >= rows) return;
    const float4* src = (const float4*)(in + (size_t)warp * DDIM);
    __nv_bfloat162* dst = (__nv_bfloat162*)(obf + (size_t)warp * DDIM);
    float s = 0.f;
    #pragma unroll
    for (int j = 0; j < 6; j++) {
        float4 v = src[j * 32 + lane];
        s += v.x * v.x + v.y * v.y + v.z * v.z + v.w * v.w;
        dst[(j * 32 + lane) * 2 + 0] = __floats2bfloat162_rn(v.x, v.y);
        dst[(j * 32 + lane) * 2 + 1] = __floats2bfloat162_rn(v.z, v.w);
    }
    #pragma unroll
    for (int o = 16; o; o >>= 1) s += __shfl_xor_sync(0xFFFFFFFFu, s, o);
    if (lane == 0) invn[warp] = 1.0f / sqrtf(s);
}

// ===========================================================================
// Kernel 1.5: slot filler (ncu capture slot #4 -> topk this round).
// ===========================================================================
__global__ void dummy_kernel() {
    int i = blockIdx.x * blockDim.x + threadIdx.x;
    if (i < BQ * NCAND) { g_cand_v[i] = 0.f; g_cand_i[i] = 0; }
}

// ===========================================================================
// Kernel 2: fused GEMM. CTA 256q x 128n, 512 threads (16 warps 4m x 4n),
// chunk-pair pipeline: per pair = mma x2, wait, convert x2, ONE sync.
// ===========================================================================
__global__ void __launch_bounds__(512, 1)
gemm_kernel(const float* __restrict__ E, int N, int Npad) {
    extern __shared__ __align__(16) char smem[];
    const uint32_t smBase = smem_u32(smem);

    const int tid  = threadIdx.x;
    const int wid  = tid >> 5;
    const int lane = tid & 31;
    const int g    = lane >> 2;
    const int tg   = lane & 3;

    const int nbase = blockIdx.x * TN;
    const int m0w = (wid & 3) * 64;     // 4 m-warps (64 q-rows)
    const int n0w = (wid >> 2) * 32;    // 4 n-warps (32 e-rows)

    const int sel = lane >> 3, r8 = lane & 7;
    const uint32_t aOff = (uint32_t)((m0w + (sel & 1) * 8 + r8) * ROWB + (sel >> 1) * 16);
    const uint32_t bOff = (uint32_t)((n0w + (sel >> 1) * 8 + r8) * ROWB + (sel & 1) * 16);

    const char* qb = (const char*)g_qbf;
    const char* eb = (const char*)E;

    // E stage/convert mapping: row = tid>>2 (0..127), 32B quarter = tid&3
    const int crow = tid >> 2;
    const int cq   = tid & 3;
    int grow = nbase + crow; if (grow >= N) grow = N - 1;
    const char* esrc = eb + (size_t)grow * (DDIM * 4) + cq * 32;

    auto load_chunk = [&](int c) {
        const int s = c & 3;
        #pragma unroll
        for (int i = 0; i < 2; i++) {
            int idx = tid + i * 512, row = idx >> 2, seg = idx & 3;
            cp16(smBase + OFF_A + s * A_STAGE + row * ROWB + seg * 16,
                 qb + (size_t)row * (DDIM * 2) + c * 64 + seg * 16);
        }
        const uint32_t fdst = smBase + OFF_F + s * F_STAGE + crow * ROWF + cq * 32;
        cp16(fdst,      esrc + c * 128);
        cp16(fdst + 16, esrc + c * 128 + 16);
    };
    auto load_pair = [&](int p) {       // one commit group per pair
        load_chunk(2 * p);
        load_chunk(2 * p + 1);
        CP_COMMIT();
    };

    float sumsq = 0.f;
    auto convert = [&](int c) {
        const int s = c & 3;
        const uint32_t src = smBase + OFF_F + s * F_STAGE + crow * ROWF + cq * 32;
        const uint32_t dst = smBase + OFF_BB + s * BB_STAGE + crow * ROWB + cq * 16;
        float4 f0, f1;
        lds128(f0, src); lds128(f1, src + 16);
        sumsq += f0.x*f0.x + f0.y*f0.y + f0.z*f0.z + f0.w*f0.w
               + f1.x*f1.x + f1.y*f1.y + f1.z*f1.z + f1.w*f1.w;
        sts128(dst, f2bf2(f0.x, f0.y), f2bf2(f0.z, f0.w),
                    f2bf2(f1.x, f1.y), f2bf2(f1.z, f1.w));
    };

    float acc[4][4][4];
    #pragma unroll
    for (int mf = 0; mf < 4; mf++)
        #pragma unroll
        for (int nf = 0; nf < 4; nf++)
            #pragma unroll
            for (int j = 0; j < 4; j++) acc[mf][nf][j] = 0.f;

    load_pair(0);
    load_pair(1);
    CP_WAIT1();                 // pair 0 resident
    convert(0); convert(1);
    __syncthreads();

    auto mma_chunk = [&](int c) {
        const int s = c & 3;
        const uint32_t aS = smBase + OFF_A + s * A_STAGE + aOff;
        const uint32_t bS = smBase + OFF_BB + s * BB_STAGE + bOff;
        #pragma unroll
        for (int kk = 0; kk < 2; kk++) {
            uint32_t a[4][4], b[2][4];
            #pragma unroll
            for (int mf = 0; mf < 4; mf++) ldsm4(a[mf], aS + mf * (16 * ROWB) + kk * 32);
            #pragma unroll
            for (int p = 0; p < 2; p++)    ldsm4(b[p], bS + p * (16 * ROWB) + kk * 32);
            #pragma unroll
            for (int mf = 0; mf < 4; mf++)
                #pragma unroll
                for (int nf = 0; nf < 4; nf++)
                    mma16816(acc[mf][nf], a[mf], b[nf >> 1][(nf & 1) * 2], b[nf >> 1][(nf & 1) * 2 + 1]);
        }
    };

    for (int p = 0; p < NPAIR; p++) {
        mma_chunk(2 * p);
        mma_chunk(2 * p + 1);
        if (p + 1 < NPAIR) {
            CP_WAIT0();                 // pair p+1 resident (issued 1 iter ago)
            convert(2 * p + 2);
            convert(2 * p + 3);
        }
        __syncthreads();
        if (p + 2 < NPAIR) load_pair(p + 2);   // reuses pair p's slots (all warps synced)
    }

    // ---- per-row inverse norms (4 partials per row) -------------------------
    float* scr  = (float*)(smem + OFF_F);
    float* invs = (float*)(smem + OFF_INV);
    scr[tid] = sumsq;
    __syncthreads();
    if (tid < TN)
        invs[tid] = rsqrtf(scr[4 * tid] + scr[4 * tid + 1] + scr[4 * tid + 2] + scr[4 * tid + 3]);
    __syncthreads();

    // ---- epilogue: bf16 coarse scores ---------------------------------------
    float2 ie[4];
    #pragma unroll
    for (int nf = 0; nf < 4; nf++) {
        const int nl = n0w + nf * 8 + 2 * tg;
        ie[nf].x = invs[nl];
        ie[nf].y = invs[nl + 1];
    }
    #pragma unroll
    for (int mf = 0; mf < 4; mf++) {
        #pragma unroll
        for (int h = 0; h < 2; h++) {
            const int q = m0w + mf * 16 + h * 8 + g;
            const float iq = g_invq[q];
            __nv_bfloat16* orow = g_sbf + (size_t)q * Npad + nbase + n0w + 2 * tg;
            #pragma unroll
            for (int nf = 0; nf < 4; nf++) {
                const int n = nbase + n0w + nf * 8 + 2 * tg;
                float ox = (n     < N) ? acc[mf][nf][2 * h]     * iq * ie[nf].x : SENT;
                float oy = (n + 1 < N) ? acc[mf][nf][2 * h + 1] * iq * ie[nf].y : SENT;
                *(uint32_t*)(orow + nf * 8) = f2bf2(ox, oy);
            }
        }
    }
}

// ===========================================================================
// Kernel 3: split top-32. 4 CTAs per query, each scans Npad/4.
// ===========================================================================
#define LK 12
__global__ void topk_kernel(int Npad) {
    extern __shared__ char sm[];
    float* sv = (float*)sm;
    int*   si = (int*)(sm + 256 * 32 * 4);
    const int q     = blockIdx.x >> 2;
    const int split = blockIdx.x & 3;
    const int tid   = threadIdx.x;
    const int seg   = Npad / NSPLIT;
    const int nb    = split * seg;
    const __nv_bfloat162* row = (const __nv_bfloat162*)(g_sbf + (size_t)q * Npad + nb);

    float lv[LK]; int li[LK];
    #pragma unroll
    for (int j = 0; j < LK; j++) { lv[j] = -FLT_MAX; li[j] = 0x7FFFFFFF; }
    float vmin = -FLT_MAX;
    const int npairs = seg >> 1;
    for (int p = tid; p < npairs; p += 256) {
        float2 v2 = __bfloat1622float2(row[p]);
        #pragma unroll
        for (int h = 0; h < 2; h++) {
            float v = h ? v2.y : v2.x;
            if (v > vmin) {
                int n = nb + 2 * p + h;
                #pragma unroll
                for (int j = LK - 1; j >= 1; j--) {
                    bool gj  = v > lv[j];
                    bool gj1 = v > lv[j - 1];
                    lv[j] = gj ? (gj1 ? lv[j - 1] : v) : lv[j];
                    li[j] = gj ? (gj1 ? li[j - 1] : n) : li[j];
                }
                if (v > lv[0]) { lv[0] = v; li[0] = n; }
                vmin = lv[LK - 1];
            }
        }
    }
    #pragma unroll
    for (int j = 0; j < LK; j++) { sv[tid * 32 + j] = lv[j]; si[tid * 32 + j] = li[j]; }
    #pragma unroll
    for (int j = LK; j < 32; j++) { sv[tid * 32 + j] = -FLT_MAX; si[tid * 32 + j] = 0x7FFFFFFF; }

    int len = LK;
    for (int half = 128; half >= 1; half >>= 1) {
        int outlen = min(2 * len, 32);
        __syncthreads();
        if (tid < half) {
            float* av = &sv[tid * 32];            int* ai = &si[tid * 32];
            float* bv = &sv[(tid + half) * 32];   int* bi = &si[(tid + half) * 32];
            float tv[32]; int ti[32];
            int ia = 0, ib = 0;
            for (int j = 0; j < outlen; j++) {
                float va = (ia < len) ? av[ia] : -FLT_MAX;
                float vb = (ib < len) ? bv[ib] : -FLT_MAX;
                int xa = (ia < len) ? ai[ia] : 0x7FFFFFFF;
                int xb = (ib < len) ? bi[ib] : 0x7FFFFFFF;
                bool ta = (va > vb) || (va == vb && xa < xb);
                if (ta) { tv[j] = va; ti[j] = xa; ia++; }
                else    { tv[j] = vb; ti[j] = xb; ib++; }
            }
            for (int j = 0; j < outlen; j++) { av[j] = tv[j]; ai[j] = ti[j]; }
        }
        len = outlen;
    }
    __syncthreads();
    if (tid < CSPL) {
        g_cand_v[q * NCAND + split * CSPL + tid] = sv[tid];
        g_cand_i[q * NCAND + split * CSPL + tid] = si[tid];
    }
}

// ===========================================================================
// Kernel 4: exact fp32 rescore of 128 candidates + exact top-17.
// ===========================================================================
__global__ void rescore_kernel(const float* __restrict__ Q, const float* __restrict__ E,
                               float* __restrict__ out, int N, int out_size) {
    __shared__ float qs[DDIM];
    __shared__ float cv[NCAND];
    __shared__ int   ci[NCAND];
    const int q = blockIdx.x;
    const int tid = threadIdx.x;
    const int wid = tid >> 5, lane = tid & 31;

    #pragma unroll
    for (int j = 0; j < 3; j++) qs[tid + j * 256] = Q[(size_t)q * DDIM + tid + j * 256];
    __syncthreads();

    const float iq = g_invq[q];
    for (int c = wid; c < NCAND; c += 8) {
        int idx = g_cand_i[q * NCAND + c];
        int safe = (idx >= 0 && idx < N) ? idx : 0;
        const float* er = E + (size_t)safe * DDIM;
        float dot = 0.f, ss = 0.f;
        #pragma unroll
        for (int j = 0; j < 24; j++) {
            float e = er[j * 32 + lane];
            dot += qs[j * 32 + lane] * e;
            ss  += e * e;
        }
        #pragma unroll
        for (int o = 16; o; o >>= 1) {
            dot += __shfl_xor_sync(0xFFFFFFFFu, dot, o);
            ss  += __shfl_xor_sync(0xFFFFFFFFu, ss, o);
        }
        if (lane == 0) {
            cv[c] = dot * iq * (1.0f / sqrtf(ss));
            ci[c] = safe;
        }
    }
    __syncthreads();

    if (tid == 0) {
        float bv[KSEL]; int bi[KSEL];
        #pragma unroll
        for (int j = 0; j < KSEL; j++) { bv[j] = -FLT_MAX; bi[j] = 0x7FFFFFFF; }
        for (int c = 0; c < NCAND; c++) {
            float v = cv[c]; int ix = ci[c];
            bool better = (v > bv[KSEL-1]) || (v == bv[KSEL-1] && ix < bi[KSEL-1]);
            if (better) {
                int pos = KSEL - 1;
                while (pos > 0 && ((v > bv[pos-1]) || (v == bv[pos-1] && ix < bi[pos-1]))) {
                    bv[pos] = bv[pos-1]; bi[pos] = bi[pos-1]; pos--;
                }
                bv[pos] = v; bi[pos] = ix;
            }
        }
        for (int j = 0; j < KSEL; j++) {
            out[q * KSEL + j] = bv[j];
            if (out_size >= 2 * BQ * KSEL)
                out[BQ * KSEL + q * KSEL + j] = (float)bi[j];
        }
    }
}

// ===========================================================================
extern "C" void kernel_launch(void* const* d_in, const int* in_sizes, int n_in,
                              void* d_out, int out_size) {
    const float* Q = (const float*)d_in[0];
    const float* E = (const float*)d_in[1];
    const int B = in_sizes[0] / DDIM;
    const int N = in_sizes[1] / DDIM;
    const int ntiles = (N + TN - 1) / TN;             // 3907
    const int Npad = ntiles * TN;                     // 500096
    float* out = (float*)d_out;

    static bool init_done = false;
    if (!init_done) {
        cudaFuncSetAttribute(gemm_kernel, cudaFuncAttributeMaxDynamicSharedMemorySize, SM_GEMM);
        cudaFuncSetAttribute(topk_kernel, cudaFuncAttributeMaxDynamicSharedMemorySize, 256 * 32 * 8);
        init_done = true;
    }
    __nv_bfloat16* qbf_p; float* invq_p;
    cudaGetSymbolAddress((void**)&qbf_p, g_qbf);
    cudaGetSymbolAddress((void**)&invq_p, g_invq);

    convert_kernel<<<(B + 7) / 8, 256>>>(Q, qbf_p, invq_p, B);     // #1
    dummy_kernel<<<64, 256>>>();                                    // #2
    gemm_kernel<<<ntiles, 512, SM_GEMM>>>(E, N, Npad);              // #3
    topk_kernel<<<B * NSPLIT, 256, 256 * 32 * 8>>>(Npad);           // #4 (ncu slot)
    rescore_kernel<<<B, 256>>>(Q, E, out, N, out_size);             // #5
}

// round 14
// speedup vs baseline: 3.9178x; 1.0868x over previous
#include <cuda_runtime.h>
#include <cuda_bf16.h>
#include <cstdint>
#include <math.h>
#include <float.h>

// Retriever: B=256 x N=500000, D=768, top-17 cosine.
// qconvert -> fused GEMM (chunk-pair pipeline) -> bf16 scores ->
// 8-way split top-24 with hmax2 prefilter -> exact fp32 rescore(192).

#define DDIM   768
#define KSEL   17
#define BQ     256
#define TN     128
#define QT     256
#define KCH    32
#define NCHUNK (DDIM / KCH)   // 24
#define NPAIR  (NCHUNK / 2)   // 12
#define NSPLIT 8
#define CSPL   24
#define NCAND  (NSPLIT * CSPL) // 192
#define NMAX   500000
#define NPADMAX (((NMAX + TN - 1) / TN) * TN)

#define ROWB     80
#define ROWF     144
#define A_STAGE  (QT * ROWB)                   // 20480
#define F_STAGE  (TN * ROWF)                   // 18432
#define BB_STAGE (TN * ROWB)                   // 10240
#define OFF_A    0
#define OFF_F    (4 * A_STAGE)                 // 81920
#define OFF_BB   (OFF_F + 4 * F_STAGE)         // 155648
#define OFF_INV  (OFF_BB + 4 * BB_STAGE)       // 196608
#define SM_GEMM  (OFF_INV + TN * 4)            // 197120

#define SENT (-1e30f)

// ------------------------- device scratch ----------------------------------
__device__ __nv_bfloat16 g_qbf[(size_t)BQ * DDIM];
__device__ float g_invq[BQ];
__device__ __nv_bfloat16 g_sbf[(size_t)BQ * NPADMAX];    // 256 MB coarse scores
__device__ float g_cand_v[BQ * NCAND];
__device__ int   g_cand_i[BQ * NCAND];

// ------------------------- helpers -----------------------------------------
__device__ __forceinline__ uint32_t smem_u32(const void* p) {
    uint32_t a;
    asm("{ .reg .u64 t; cvta.to.shared.u64 t, %1; cvt.u32.u64 %0, t; }" : "=r"(a) : "l"(p));
    return a;
}
__device__ __forceinline__ void cp16(uint32_t dst, const void* src) {
    asm volatile("cp.async.cg.shared.global [%0], [%1], 16;" :: "r"(dst), "l"(src));
}
#define CP_COMMIT() asm volatile("cp.async.commit_group;" ::: "memory")
#define CP_WAIT0()  asm volatile("cp.async.wait_group 0;" ::: "memory")
#define CP_WAIT1()  asm volatile("cp.async.wait_group 1;" ::: "memory")

__device__ __forceinline__ void ldsm4(uint32_t* r, uint32_t addr) {
    asm volatile("ldmatrix.sync.aligned.m8n8.x4.shared.b16 {%0,%1,%2,%3}, [%4];"
                 : "=r"(r[0]), "=r"(r[1]), "=r"(r[2]), "=r"(r[3]) : "r"(addr));
}
__device__ __forceinline__ void mma16816(float* c, const uint32_t* a, uint32_t b0, uint32_t b1) {
    asm volatile(
        "mma.sync.aligned.m16n8k16.row.col.f32.bf16.bf16.f32 "
        "{%0,%1,%2,%3}, {%4,%5,%6,%7}, {%8,%9}, {%0,%1,%2,%3};"
        : "+f"(c[0]), "+f"(c[1]), "+f"(c[2]), "+f"(c[3])
        : "r"(a[0]), "r"(a[1]), "r"(a[2]), "r"(a[3]), "r"(b0), "r"(b1));
}
__device__ __forceinline__ void lds128(float4& v, uint32_t addr) {
    asm volatile("ld.shared.v4.f32 {%0,%1,%2,%3}, [%4];"
                 : "=f"(v.x), "=f"(v.y), "=f"(v.z), "=f"(v.w) : "r"(addr));
}
__device__ __forceinline__ void sts128(uint32_t addr, uint32_t a, uint32_t b, uint32_t c, uint32_t d) {
    asm volatile("st.shared.v4.b32 [%0], {%1,%2,%3,%4};"
                 :: "r"(addr), "r"(a), "r"(b), "r"(c), "r"(d));
}
__device__ __forceinline__ uint32_t f2bf2(float lo, float hi) {
    uint32_t r;
    asm("cvt.rn.bf16x2.f32 %0, %1, %2;" : "=r"(r) : "f"(hi), "f"(lo));
    return r;
}

// ===========================================================================
// Kernel 1: queries fp32 -> bf16 + inverse norms.
// ===========================================================================
__global__ void convert_kernel(const float* __restrict__ in,
                               __nv_bfloat16* __restrict__ obf,
                               float* __restrict__ invn, int rows) {
    int warp = (blockIdx.x * blockDim.x + threadIdx.x) >> 5;
    int lane = threadIdx.x & 31;
    if (warp >= rows) return;
    const float4* src = (const float4*)(in + (size_t)warp * DDIM);
    __nv_bfloat162* dst = (__nv_bfloat162*)(obf + (size_t)warp * DDIM);
    float s = 0.f;
    #pragma unroll
    for (int j = 0; j < 6; j++) {
        float4 v = src[j * 32 + lane];
        s += v.x * v.x + v.y * v.y + v.z * v.z + v.w * v.w;
        dst[(j * 32 + lane) * 2 + 0] = __floats2bfloat162_rn(v.x, v.y);
        dst[(j * 32 + lane) * 2 + 1] = __floats2bfloat162_rn(v.z, v.w);
    }
    #pragma unroll
    for (int o = 16; o; o >>= 1) s += __shfl_xor_sync(0xFFFFFFFFu, s, o);
    if (lane == 0) invn[warp] = 1.0f / sqrtf(s);
}

// ===========================================================================
// Kernel 1.5: slot filler (ncu capture slot #4 -> topk).
// ===========================================================================
__global__ void dummy_kernel() {
    int i = blockIdx.x * blockDim.x + threadIdx.x;
    if (i < BQ * NCAND) { g_cand_v[i] = 0.f; g_cand_i[i] = 0; }
}

// ===========================================================================
// Kernel 2: fused GEMM (unchanged from R13).
// ===========================================================================
__global__ void __launch_bounds__(512, 1)
gemm_kernel(const float* __restrict__ E, int N, int Npad) {
    extern __shared__ __align__(16) char smem[];
    const uint32_t smBase = smem_u32(smem);

    const int tid  = threadIdx.x;
    const int wid  = tid >> 5;
    const int lane = tid & 31;
    const int g    = lane >> 2;
    const int tg   = lane & 3;

    const int nbase = blockIdx.x * TN;
    const int m0w = (wid & 3) * 64;
    const int n0w = (wid >> 2) * 32;

    const int sel = lane >> 3, r8 = lane & 7;
    const uint32_t aOff = (uint32_t)((m0w + (sel & 1) * 8 + r8) * ROWB + (sel >> 1) * 16);
    const uint32_t bOff = (uint32_t)((n0w + (sel >> 1) * 8 + r8) * ROWB + (sel & 1) * 16);

    const char* qb = (const char*)g_qbf;
    const char* eb = (const char*)E;

    const int crow = tid >> 2;
    const int cq   = tid & 3;
    int grow = nbase + crow; if (grow >= N) grow = N - 1;
    const char* esrc = eb + (size_t)grow * (DDIM * 4) + cq * 32;

    auto load_chunk = [&](int c) {
        const int s = c & 3;
        #pragma unroll
        for (int i = 0; i < 2; i++) {
            int idx = tid + i * 512, row = idx >> 2, seg = idx & 3;
            cp16(smBase + OFF_A + s * A_STAGE + row * ROWB + seg * 16,
                 qb + (size_t)row * (DDIM * 2) + c * 64 + seg * 16);
        }
        const uint32_t fdst = smBase + OFF_F + s * F_STAGE + crow * ROWF + cq * 32;
        cp16(fdst,      esrc + c * 128);
        cp16(fdst + 16, esrc + c * 128 + 16);
    };
    auto load_pair = [&](int p) {
        load_chunk(2 * p);
        load_chunk(2 * p + 1);
        CP_COMMIT();
    };

    float sumsq = 0.f;
    auto convert = [&](int c) {
        const int s = c & 3;
        const uint32_t src = smBase + OFF_F + s * F_STAGE + crow * ROWF + cq * 32;
        const uint32_t dst = smBase + OFF_BB + s * BB_STAGE + crow * ROWB + cq * 16;
        float4 f0, f1;
        lds128(f0, src); lds128(f1, src + 16);
        sumsq += f0.x*f0.x + f0.y*f0.y + f0.z*f0.z + f0.w*f0.w
               + f1.x*f1.x + f1.y*f1.y + f1.z*f1.z + f1.w*f1.w;
        sts128(dst, f2bf2(f0.x, f0.y), f2bf2(f0.z, f0.w),
                    f2bf2(f1.x, f1.y), f2bf2(f1.z, f1.w));
    };

    float acc[4][4][4];
    #pragma unroll
    for (int mf = 0; mf < 4; mf++)
        #pragma unroll
        for (int nf = 0; nf < 4; nf++)
            #pragma unroll
            for (int j = 0; j < 4; j++) acc[mf][nf][j] = 0.f;

    load_pair(0);
    load_pair(1);
    CP_WAIT1();
    convert(0); convert(1);
    __syncthreads();

    auto mma_chunk = [&](int c) {
        const int s = c & 3;
        const uint32_t aS = smBase + OFF_A + s * A_STAGE + aOff;
        const uint32_t bS = smBase + OFF_BB + s * BB_STAGE + bOff;
        #pragma unroll
        for (int kk = 0; kk < 2; kk++) {
            uint32_t a[4][4], b[2][4];
            #pragma unroll
            for (int mf = 0; mf < 4; mf++) ldsm4(a[mf], aS + mf * (16 * ROWB) + kk * 32);
            #pragma unroll
            for (int p = 0; p < 2; p++)    ldsm4(b[p], bS + p * (16 * ROWB) + kk * 32);
            #pragma unroll
            for (int mf = 0; mf < 4; mf++)
                #pragma unroll
                for (int nf = 0; nf < 4; nf++)
                    mma16816(acc[mf][nf], a[mf], b[nf >> 1][(nf & 1) * 2], b[nf >> 1][(nf & 1) * 2 + 1]);
        }
    };

    for (int p = 0; p < NPAIR; p++) {
        mma_chunk(2 * p);
        mma_chunk(2 * p + 1);
        if (p + 1 < NPAIR) {
            CP_WAIT0();
            convert(2 * p + 2);
            convert(2 * p + 3);
        }
        __syncthreads();
        if (p + 2 < NPAIR) load_pair(p + 2);
    }

    float* scr  = (float*)(smem + OFF_F);
    float* invs = (float*)(smem + OFF_INV);
    scr[tid] = sumsq;
    __syncthreads();
    if (tid < TN)
        invs[tid] = rsqrtf(scr[4 * tid] + scr[4 * tid + 1] + scr[4 * tid + 2] + scr[4 * tid + 3]);
    __syncthreads();

    float2 ie[4];
    #pragma unroll
    for (int nf = 0; nf < 4; nf++) {
        const int nl = n0w + nf * 8 + 2 * tg;
        ie[nf].x = invs[nl];
        ie[nf].y = invs[nl + 1];
    }
    #pragma unroll
    for (int mf = 0; mf < 4; mf++) {
        #pragma unroll
        for (int h = 0; h < 2; h++) {
            const int q = m0w + mf * 16 + h * 8 + g;
            const float iq = g_invq[q];
            __nv_bfloat16* orow = g_sbf + (size_t)q * Npad + nbase + n0w + 2 * tg;
            #pragma unroll
            for (int nf = 0; nf < 4; nf++) {
                const int n = nbase + n0w + nf * 8 + 2 * tg;
                float ox = (n     < N) ? acc[mf][nf][2 * h]     * iq * ie[nf].x : SENT;
                float oy = (n + 1 < N) ? acc[mf][nf][2 * h + 1] * iq * ie[nf].y : SENT;
                *(uint32_t*)(orow + nf * 8) = f2bf2(ox, oy);
            }
        }
    }
}

// ===========================================================================
// Kernel 3: split top-24 with hmax2 prefilter. 8 CTAs per query.
// Steady state: 1 uint4 load + 3 hmax2 + 1 compare per 8 values.
// ===========================================================================
#define LK 16
__global__ void topk_kernel(int Npad) {
    extern __shared__ char sm[];
    float* sv = (float*)sm;                   // 256 * 32
    int*   si = (int*)(sm + 256 * 32 * 4);
    const int q     = blockIdx.x >> 3;
    const int split = blockIdx.x & 7;
    const int tid   = threadIdx.x;
    const int seg   = Npad / NSPLIT;          // 62512
    const int nb    = split * seg;
    const uint4* row = (const uint4*)(g_sbf + (size_t)q * Npad + nb);

    float lv[LK]; int li[LK];
    #pragma unroll
    for (int j = 0; j < LK; j++) { lv[j] = -FLT_MAX; li[j] = 0x7FFFFFFF; }
    float vmin = -FLT_MAX;

    const int nblk = seg >> 3;                // 7814 blocks of 8 values
    for (int b = tid; b < nblk; b += 256) {
        uint4 u = row[b];
        __nv_bfloat162 m01 = __hmax2(*(__nv_bfloat162*)&u.x, *(__nv_bfloat162*)&u.y);
        __nv_bfloat162 m23 = __hmax2(*(__nv_bfloat162*)&u.z, *(__nv_bfloat162*)&u.w);
        __nv_bfloat162 m   = __hmax2(m01, m23);
        float bmax = fmaxf(__bfloat162float(__low2bfloat16(m)),
                           __bfloat162float(__high2bfloat16(m)));
        if (bmax > vmin) {
            const uint32_t w[4] = {u.x, u.y, u.z, u.w};
            #pragma unroll
            for (int e = 0; e < 8; e++) {
                __nv_bfloat16 bb = ((const __nv_bfloat16*)w)[e];
                float v = __bfloat162float(bb);
                if (v > vmin) {
                    int n = nb + 8 * b + e;
                    #pragma unroll
                    for (int j = LK - 1; j >= 1; j--) {
                        bool gj  = v > lv[j];
                        bool gj1 = v > lv[j - 1];
                        lv[j] = gj ? (gj1 ? lv[j - 1] : v) : lv[j];
                        li[j] = gj ? (gj1 ? li[j - 1] : n) : li[j];
                    }
                    if (v > lv[0]) { lv[0] = v; li[0] = n; }
                    vmin = lv[LK - 1];
                }
            }
        }
    }

    #pragma unroll
    for (int j = 0; j < LK; j++) { sv[tid * 32 + j] = lv[j]; si[tid * 32 + j] = li[j]; }
    #pragma unroll
    for (int j = LK; j < 32; j++) { sv[tid * 32 + j] = -FLT_MAX; si[tid * 32 + j] = 0x7FFFFFFF; }

    int len = LK;
    for (int half = 128; half >= 1; half >>= 1) {
        int outlen = min(2 * len, CSPL);
        __syncthreads();
        if (tid < half) {
            float* av = &sv[tid * 32];            int* ai = &si[tid * 32];
            float* bv = &sv[(tid + half) * 32];   int* bi = &si[(tid + half) * 32];
            float tv[CSPL]; int ti[CSPL];
            int ia = 0, ib = 0;
            for (int j = 0; j < outlen; j++) {
                float va = (ia < len) ? av[ia] : -FLT_MAX;
                float vb = (ib < len) ? bv[ib] : -FLT_MAX;
                int xa = (ia < len) ? ai[ia] : 0x7FFFFFFF;
                int xb = (ib < len) ? bi[ib] : 0x7FFFFFFF;
                bool ta = (va > vb) || (va == vb && xa < xb);
                if (ta) { tv[j] = va; ti[j] = xa; ia++; }
                else    { tv[j] = vb; ti[j] = xb; ib++; }
            }
            for (int j = 0; j < outlen; j++) { av[j] = tv[j]; ai[j] = ti[j]; }
        }
        len = outlen;
    }
    __syncthreads();
    if (tid < CSPL) {
        g_cand_v[q * NCAND + split * CSPL + tid] = sv[tid];
        g_cand_i[q * NCAND + split * CSPL + tid] = si[tid];
    }
}

// ===========================================================================
// Kernel 4: exact fp32 rescore of 192 candidates + exact top-17.
// ===========================================================================
__global__ void rescore_kernel(const float* __restrict__ Q, const float* __restrict__ E,
                               float* __restrict__ out, int N, int out_size) {
    __shared__ float qs[DDIM];
    __shared__ float cv[NCAND];
    __shared__ int   ci[NCAND];
    const int q = blockIdx.x;
    const int tid = threadIdx.x;
    const int wid = tid >> 5, lane = tid & 31;

    #pragma unroll
    for (int j = 0; j < 3; j++) qs[tid + j * 256] = Q[(size_t)q * DDIM + tid + j * 256];
    __syncthreads();

    const float iq = g_invq[q];
    for (int c = wid; c < NCAND; c += 8) {
        int idx = g_cand_i[q * NCAND + c];
        int safe = (idx >= 0 && idx < N) ? idx : 0;
        const float* er = E + (size_t)safe * DDIM;
        float dot = 0.f, ss = 0.f;
        #pragma unroll
        for (int j = 0; j < 24; j++) {
            float e = er[j * 32 + lane];
            dot += qs[j * 32 + lane] * e;
            ss  += e * e;
        }
        #pragma unroll
        for (int o = 16; o; o >>= 1) {
            dot += __shfl_xor_sync(0xFFFFFFFFu, dot, o);
            ss  += __shfl_xor_sync(0xFFFFFFFFu, ss, o);
        }
        if (lane == 0) {
            cv[c] = dot * iq * (1.0f / sqrtf(ss));
            ci[c] = safe;
        }
    }
    __syncthreads();

    if (tid == 0) {
        float bv[KSEL]; int bi[KSEL];
        #pragma unroll
        for (int j = 0; j < KSEL; j++) { bv[j] = -FLT_MAX; bi[j] = 0x7FFFFFFF; }
        for (int c = 0; c < NCAND; c++) {
            float v = cv[c]; int ix = ci[c];
            bool better = (v > bv[KSEL-1]) || (v == bv[KSEL-1] && ix < bi[KSEL-1]);
            if (better) {
                int pos = KSEL - 1;
                while (pos > 0 && ((v > bv[pos-1]) || (v == bv[pos-1] && ix < bi[pos-1]))) {
                    bv[pos] = bv[pos-1]; bi[pos] = bi[pos-1]; pos--;
                }
                bv[pos] = v; bi[pos] = ix;
            }
        }
        for (int j = 0; j < KSEL; j++) {
            out[q * KSEL + j] = bv[j];
            if (out_size >= 2 * BQ * KSEL)
                out[BQ * KSEL + q * KSEL + j] = (float)bi[j];
        }
    }
}

// ===========================================================================
extern "C" void kernel_launch(void* const* d_in, const int* in_sizes, int n_in,
                              void* d_out, int out_size) {
    const float* Q = (const float*)d_in[0];
    const float* E = (const float*)d_in[1];
    const int B = in_sizes[0] / DDIM;
    const int N = in_sizes[1] / DDIM;
    const int ntiles = (N + TN - 1) / TN;             // 3907
    const int Npad = ntiles * TN;                     // 500096
    float* out = (float*)d_out;

    static bool init_done = false;
    if (!init_done) {
        cudaFuncSetAttribute(gemm_kernel, cudaFuncAttributeMaxDynamicSharedMemorySize, SM_GEMM);
        cudaFuncSetAttribute(topk_kernel, cudaFuncAttributeMaxDynamicSharedMemorySize, 256 * 32 * 8);
        init_done = true;
    }
    __nv_bfloat16* qbf_p; float* invq_p;
    cudaGetSymbolAddress((void**)&qbf_p, g_qbf);
    cudaGetSymbolAddress((void**)&invq_p, g_invq);

    convert_kernel<<<(B + 7) / 8, 256>>>(Q, qbf_p, invq_p, B);     // #1
    dummy_kernel<<<64, 256>>>();                                    // #2
    gemm_kernel<<<ntiles, 512, SM_GEMM>>>(E, N, Npad);              // #3
    topk_kernel<<<B * NSPLIT, 256, 256 * 32 * 8>>>(Npad);           // #4 (ncu slot)
    rescore_kernel<<<B, 256>>>(Q, E, out, N, out_size);             // #5
}

// round 15
// speedup vs baseline: 3.9566x; 1.0099x over previous
#include <cuda_runtime.h>
#include <cuda_bf16.h>
#include <cstdint>
#include <math.h>
#include <float.h>

// Retriever: B=256 x N=500000, D=768, top-17 cosine.
// qconvert -> fused GEMM (chunk-pair pipeline) -> bf16 scores ->
// 8-way split top-24 (32-wide hmax2 prefilter) -> exact fp32 rescore(192).

#define DDIM   768
#define KSEL   17
#define BQ     256
#define TN     128
#define QT     256
#define KCH    32
#define NCHUNK (DDIM / KCH)   // 24
#define NPAIR  (NCHUNK / 2)   // 12
#define NSPLIT 8
#define CSPL   24
#define NCAND  (NSPLIT * CSPL) // 192
#define NMAX   500000
#define NPADMAX (((NMAX + TN - 1) / TN) * TN)

#define ROWB     80
#define ROWF     144
#define A_STAGE  (QT * ROWB)                   // 20480
#define F_STAGE  (TN * ROWF)                   // 18432
#define BB_STAGE (TN * ROWB)                   // 10240
#define OFF_A    0
#define OFF_F    (4 * A_STAGE)                 // 81920
#define OFF_BB   (OFF_F + 4 * F_STAGE)         // 155648
#define OFF_INV  (OFF_BB + 4 * BB_STAGE)       // 196608
#define SM_GEMM  (OFF_INV + TN * 4)            // 197120

#define SENT (-1e30f)

// ------------------------- device scratch ----------------------------------
__device__ __nv_bfloat16 g_qbf[(size_t)BQ * DDIM];
__device__ float g_invq[BQ];
__device__ __nv_bfloat16 g_sbf[(size_t)BQ * NPADMAX];    // 256 MB coarse scores
__device__ float g_cand_v[BQ * NCAND];
__device__ int   g_cand_i[BQ * NCAND];

// ------------------------- helpers -----------------------------------------
__device__ __forceinline__ uint32_t smem_u32(const void* p) {
    uint32_t a;
    asm("{ .reg .u64 t; cvta.to.shared.u64 t, %1; cvt.u32.u64 %0, t; }" : "=r"(a) : "l"(p));
    return a;
}
__device__ __forceinline__ void cp16(uint32_t dst, const void* src) {
    asm volatile("cp.async.cg.shared.global [%0], [%1], 16;" :: "r"(dst), "l"(src));
}
#define CP_COMMIT() asm volatile("cp.async.commit_group;" ::: "memory")
#define CP_WAIT0()  asm volatile("cp.async.wait_group 0;" ::: "memory")
#define CP_WAIT1()  asm volatile("cp.async.wait_group 1;" ::: "memory")

__device__ __forceinline__ void ldsm4(uint32_t* r, uint32_t addr) {
    asm volatile("ldmatrix.sync.aligned.m8n8.x4.shared.b16 {%0,%1,%2,%3}, [%4];"
                 : "=r"(r[0]), "=r"(r[1]), "=r"(r[2]), "=r"(r[3]) : "r"(addr));
}
__device__ __forceinline__ void mma16816(float* c, const uint32_t* a, uint32_t b0, uint32_t b1) {
    asm volatile(
        "mma.sync.aligned.m16n8k16.row.col.f32.bf16.bf16.f32 "
        "{%0,%1,%2,%3}, {%4,%5,%6,%7}, {%8,%9}, {%0,%1,%2,%3};"
        : "+f"(c[0]), "+f"(c[1]), "+f"(c[2]), "+f"(c[3])
        : "r"(a[0]), "r"(a[1]), "r"(a[2]), "r"(a[3]), "r"(b0), "r"(b1));
}
__device__ __forceinline__ void lds128(float4& v, uint32_t addr) {
    asm volatile("ld.shared.v4.f32 {%0,%1,%2,%3}, [%4];"
                 : "=f"(v.x), "=f"(v.y), "=f"(v.z), "=f"(v.w) : "r"(addr));
}
__device__ __forceinline__ void sts128(uint32_t addr, uint32_t a, uint32_t b, uint32_t c, uint32_t d) {
    asm volatile("st.shared.v4.b32 [%0], {%1,%2,%3,%4};"
                 :: "r"(addr), "r"(a), "r"(b), "r"(c), "r"(d));
}
__device__ __forceinline__ uint32_t f2bf2(float lo, float hi) {
    uint32_t r;
    asm("cvt.rn.bf16x2.f32 %0, %1, %2;" : "=r"(r) : "f"(hi), "f"(lo));
    return r;
}

// ===========================================================================
// Kernel 1: queries fp32 -> bf16 + inverse norms.
// ===========================================================================
__global__ void convert_kernel(const float* __restrict__ in,
                               __nv_bfloat16* __restrict__ obf,
                               float* __restrict__ invn, int rows) {
    int warp = (blockIdx.x * blockDim.x + threadIdx.x) >> 5;
    int lane = threadIdx.x & 31;
    if (warp >= rows) return;
    const float4* src = (const float4*)(in + (size_t)warp * DDIM);
    __nv_bfloat162* dst = (__nv_bfloat162*)(obf + (size_t)warp * DDIM);
    float s = 0.f;
    #pragma unroll
    for (int j = 0; j < 6; j++) {
        float4 v = src[j * 32 + lane];
        s += v.x * v.x + v.y * v.y + v.z * v.z + v.w * v.w;
        dst[(j * 32 + lane) * 2 + 0] = __floats2bfloat162_rn(v.x, v.y);
        dst[(j * 32 + lane) * 2 + 1] = __floats2bfloat162_rn(v.z, v.w);
    }
    #pragma unroll
    for (int o = 16; o; o >>= 1) s += __shfl_xor_sync(0xFFFFFFFFu, s, o);
    if (lane == 0) invn[warp] = 1.0f / sqrtf(s);
}

// ===========================================================================
// Kernel 1.5: slot filler (ncu capture slot #4 -> topk).
// ===========================================================================
__global__ void dummy_kernel() {
    int i = blockIdx.x * blockDim.x + threadIdx.x;
    if (i < BQ * NCAND) { g_cand_v[i] = 0.f; g_cand_i[i] = 0; }
}

// ===========================================================================
// Kernel 2: fused GEMM (unchanged from R13/R14).
// ===========================================================================
__global__ void __launch_bounds__(512, 1)
gemm_kernel(const float* __restrict__ E, int N, int Npad) {
    extern __shared__ __align__(16) char smem[];
    const uint32_t smBase = smem_u32(smem);

    const int tid  = threadIdx.x;
    const int wid  = tid >> 5;
    const int lane = tid & 31;
    const int g    = lane >> 2;
    const int tg   = lane & 3;

    const int nbase = blockIdx.x * TN;
    const int m0w = (wid & 3) * 64;
    const int n0w = (wid >> 2) * 32;

    const int sel = lane >> 3, r8 = lane & 7;
    const uint32_t aOff = (uint32_t)((m0w + (sel & 1) * 8 + r8) * ROWB + (sel >> 1) * 16);
    const uint32_t bOff = (uint32_t)((n0w + (sel >> 1) * 8 + r8) * ROWB + (sel & 1) * 16);

    const char* qb = (const char*)g_qbf;
    const char* eb = (const char*)E;

    const int crow = tid >> 2;
    const int cq   = tid & 3;
    int grow = nbase + crow; if (grow >= N) grow = N - 1;
    const char* esrc = eb + (size_t)grow * (DDIM * 4) + cq * 32;

    auto load_chunk = [&](int c) {
        const int s = c & 3;
        #pragma unroll
        for (int i = 0; i < 2; i++) {
            int idx = tid + i * 512, row = idx >> 2, seg = idx & 3;
            cp16(smBase + OFF_A + s * A_STAGE + row * ROWB + seg * 16,
                 qb + (size_t)row * (DDIM * 2) + c * 64 + seg * 16);
        }
        const uint32_t fdst = smBase + OFF_F + s * F_STAGE + crow * ROWF + cq * 32;
        cp16(fdst,      esrc + c * 128);
        cp16(fdst + 16, esrc + c * 128 + 16);
    };
    auto load_pair = [&](int p) {
        load_chunk(2 * p);
        load_chunk(2 * p + 1);
        CP_COMMIT();
    };

    float sumsq = 0.f;
    auto convert = [&](int c) {
        const int s = c & 3;
        const uint32_t src = smBase + OFF_F + s * F_STAGE + crow * ROWF + cq * 32;
        const uint32_t dst = smBase + OFF_BB + s * BB_STAGE + crow * ROWB + cq * 16;
        float4 f0, f1;
        lds128(f0, src); lds128(f1, src + 16);
        sumsq += f0.x*f0.x + f0.y*f0.y + f0.z*f0.z + f0.w*f0.w
               + f1.x*f1.x + f1.y*f1.y + f1.z*f1.z + f1.w*f1.w;
        sts128(dst, f2bf2(f0.x, f0.y), f2bf2(f0.z, f0.w),
                    f2bf2(f1.x, f1.y), f2bf2(f1.z, f1.w));
    };

    float acc[4][4][4];
    #pragma unroll
    for (int mf = 0; mf < 4; mf++)
        #pragma unroll
        for (int nf = 0; nf < 4; nf++)
            #pragma unroll
            for (int j = 0; j < 4; j++) acc[mf][nf][j] = 0.f;

    load_pair(0);
    load_pair(1);
    CP_WAIT1();
    convert(0); convert(1);
    __syncthreads();

    auto mma_chunk = [&](int c) {
        const int s = c & 3;
        const uint32_t aS = smBase + OFF_A + s * A_STAGE + aOff;
        const uint32_t bS = smBase + OFF_BB + s * BB_STAGE + bOff;
        #pragma unroll
        for (int kk = 0; kk < 2; kk++) {
            uint32_t a[4][4], b[2][4];
            #pragma unroll
            for (int mf = 0; mf < 4; mf++) ldsm4(a[mf], aS + mf * (16 * ROWB) + kk * 32);
            #pragma unroll
            for (int p = 0; p < 2; p++)    ldsm4(b[p], bS + p * (16 * ROWB) + kk * 32);
            #pragma unroll
            for (int mf = 0; mf < 4; mf++)
                #pragma unroll
                for (int nf = 0; nf < 4; nf++)
                    mma16816(acc[mf][nf], a[mf], b[nf >> 1][(nf & 1) * 2], b[nf >> 1][(nf & 1) * 2 + 1]);
        }
    };

    for (int p = 0; p < NPAIR; p++) {
        mma_chunk(2 * p);
        mma_chunk(2 * p + 1);
        if (p + 1 < NPAIR) {
            CP_WAIT0();
            convert(2 * p + 2);
            convert(2 * p + 3);
        }
        __syncthreads();
        if (p + 2 < NPAIR) load_pair(p + 2);
    }

    float* scr  = (float*)(smem + OFF_F);
    float* invs = (float*)(smem + OFF_INV);
    scr[tid] = sumsq;
    __syncthreads();
    if (tid < TN)
        invs[tid] = rsqrtf(scr[4 * tid] + scr[4 * tid + 1] + scr[4 * tid + 2] + scr[4 * tid + 3]);
    __syncthreads();

    float2 ie[4];
    #pragma unroll
    for (int nf = 0; nf < 4; nf++) {
        const int nl = n0w + nf * 8 + 2 * tg;
        ie[nf].x = invs[nl];
        ie[nf].y = invs[nl + 1];
    }
    #pragma unroll
    for (int mf = 0; mf < 4; mf++) {
        #pragma unroll
        for (int h = 0; h < 2; h++) {
            const int q = m0w + mf * 16 + h * 8 + g;
            const float iq = g_invq[q];
            __nv_bfloat16* orow = g_sbf + (size_t)q * Npad + nbase + n0w + 2 * tg;
            #pragma unroll
            for (int nf = 0; nf < 4; nf++) {
                const int n = nbase + n0w + nf * 8 + 2 * tg;
                float ox = (n     < N) ? acc[mf][nf][2 * h]     * iq * ie[nf].x : SENT;
                float oy = (n + 1 < N) ? acc[mf][nf][2 * h + 1] * iq * ie[nf].y : SENT;
                *(uint32_t*)(orow + nf * 8) = f2bf2(ox, oy);
            }
        }
    }
}

// ===========================================================================
// Kernel 3: split top-24, 32-wide prefilter. 8 CTAs per query.
// Steady state per 32 values: 4 LDG.128 + 15 hmax2 (fma pipe) + 1 max +
// 1 compare + 1 loop increment.
// ===========================================================================
#define LK 16
__device__ __forceinline__ float bf2max_f(__nv_bfloat162 m) {
    return fmaxf(__bfloat162float(__low2bfloat16(m)),
                 __bfloat162float(__high2bfloat16(m)));
}

__global__ void topk_kernel(int Npad) {
    extern __shared__ char sm[];
    float* sv = (float*)sm;                   // 256 * 32
    int*   si = (int*)(sm + 256 * 32 * 4);
    const int q     = blockIdx.x >> 3;
    const int split = blockIdx.x & 7;
    const int tid   = threadIdx.x;
    const int seg   = Npad / NSPLIT;          // 62512
    const int nb    = split * seg;
    const uint4* row4 = (const uint4*)(g_sbf + (size_t)q * Npad + nb);

    float lv[LK]; int li[LK];
    #pragma unroll
    for (int j = 0; j < LK; j++) { lv[j] = -FLT_MAX; li[j] = 0x7FFFFFFF; }
    float vmin = -FLT_MAX;

    auto insert8 = [&](uint4 u, int base) {   // exact 8-value insert (rare)
        const uint32_t w[4] = {u.x, u.y, u.z, u.w};
        #pragma unroll
        for (int e = 0; e < 8; e++) {
            float v = __bfloat162float(((const __nv_bfloat16*)w)[e]);
            if (v > vmin) {
                int n = base + e;
                #pragma unroll
                for (int j = LK - 1; j >= 1; j--) {
                    bool gj  = v > lv[j];
                    bool gj1 = v > lv[j - 1];
                    lv[j] = gj ? (gj1 ? lv[j - 1] : v) : lv[j];
                    li[j] = gj ? (gj1 ? li[j - 1] : n) : li[j];
                }
                if (v > lv[0]) { lv[0] = v; li[0] = n; }
                vmin = lv[LK - 1];
            }
        }
    };

    const int nblk32 = seg >> 5;              // 1953 blocks of 32
    for (int i = tid; i < nblk32; i += 256) {
        uint4 u0 = row4[i * 4 + 0];
        uint4 u1 = row4[i * 4 + 1];
        uint4 u2 = row4[i * 4 + 2];
        uint4 u3 = row4[i * 4 + 3];
        __nv_bfloat162 m0 = __hmax2(__hmax2(*(__nv_bfloat162*)&u0.x, *(__nv_bfloat162*)&u0.y),
                                    __hmax2(*(__nv_bfloat162*)&u0.z, *(__nv_bfloat162*)&u0.w));
        __nv_bfloat162 m1 = __hmax2(__hmax2(*(__nv_bfloat162*)&u1.x, *(__nv_bfloat162*)&u1.y),
                                    __hmax2(*(__nv_bfloat162*)&u1.z, *(__nv_bfloat162*)&u1.w));
        __nv_bfloat162 m2 = __hmax2(__hmax2(*(__nv_bfloat162*)&u2.x, *(__nv_bfloat162*)&u2.y),
                                    __hmax2(*(__nv_bfloat162*)&u2.z, *(__nv_bfloat162*)&u2.w));
        __nv_bfloat162 m3 = __hmax2(__hmax2(*(__nv_bfloat162*)&u3.x, *(__nv_bfloat162*)&u3.y),
                                    __hmax2(*(__nv_bfloat162*)&u3.z, *(__nv_bfloat162*)&u3.w));
        __nv_bfloat162 m  = __hmax2(__hmax2(m0, m1), __hmax2(m2, m3));
        if (bf2max_f(m) > vmin) {
            const int base = nb + i * 32;
            if (bf2max_f(m0) > vmin) insert8(u0, base);
            if (bf2max_f(m1) > vmin) insert8(u1, base + 8);
            if (bf2max_f(m2) > vmin) insert8(u2, base + 16);
            if (bf2max_f(m3) > vmin) insert8(u3, base + 24);
        }
    }
    // tail: seg - nblk32*32 = 16 values (2 uint4), threads 0..1
    const int tailBase = nblk32 << 5;
    if (tid < ((seg - tailBase) >> 3)) {
        uint4 u = row4[(tailBase >> 3) + tid];
        insert8(u, nb + tailBase + tid * 8);
    }

    #pragma unroll
    for (int j = 0; j < LK; j++) { sv[tid * 32 + j] = lv[j]; si[tid * 32 + j] = li[j]; }
    #pragma unroll
    for (int j = LK; j < 32; j++) { sv[tid * 32 + j] = -FLT_MAX; si[tid * 32 + j] = 0x7FFFFFFF; }

    int len = LK;
    for (int half = 128; half >= 1; half >>= 1) {
        int outlen = min(2 * len, CSPL);
        __syncthreads();
        if (tid < half) {
            float* av = &sv[tid * 32];            int* ai = &si[tid * 32];
            float* bv = &sv[(tid + half) * 32];   int* bi = &si[(tid + half) * 32];
            float tv[CSPL]; int ti[CSPL];
            int ia = 0, ib = 0;
            for (int j = 0; j < outlen; j++) {
                float va = (ia < len) ? av[ia] : -FLT_MAX;
                float vb = (ib < len) ? bv[ib] : -FLT_MAX;
                int xa = (ia < len) ? ai[ia] : 0x7FFFFFFF;
                int xb = (ib < len) ? bi[ib] : 0x7FFFFFFF;
                bool ta = (va > vb) || (va == vb && xa < xb);
                if (ta) { tv[j] = va; ti[j] = xa; ia++; }
                else    { tv[j] = vb; ti[j] = xb; ib++; }
            }
            for (int j = 0; j < outlen; j++) { av[j] = tv[j]; ai[j] = ti[j]; }
        }
        len = outlen;
    }
    __syncthreads();
    if (tid < CSPL) {
        g_cand_v[q * NCAND + split * CSPL + tid] = sv[tid];
        g_cand_i[q * NCAND + split * CSPL + tid] = si[tid];
    }
}

// ===========================================================================
// Kernel 4: exact fp32 rescore of 192 candidates + exact top-17.
// ===========================================================================
__global__ void rescore_kernel(const float* __restrict__ Q, const float* __restrict__ E,
                               float* __restrict__ out, int N, int out_size) {
    __shared__ float qs[DDIM];
    __shared__ float cv[NCAND];
    __shared__ int   ci[NCAND];
    const int q = blockIdx.x;
    const int tid = threadIdx.x;
    const int wid = tid >> 5, lane = tid & 31;

    #pragma unroll
    for (int j = 0; j < 3; j++) qs[tid + j * 256] = Q[(size_t)q * DDIM + tid + j * 256];
    __syncthreads();

    const float iq = g_invq[q];
    for (int c = wid; c < NCAND; c += 8) {
        int idx = g_cand_i[q * NCAND + c];
        int safe = (idx >= 0 && idx < N) ? idx : 0;
        const float* er = E + (size_t)safe * DDIM;
        float dot = 0.f, ss = 0.f;
        #pragma unroll
        for (int j = 0; j < 24; j++) {
            float e = er[j * 32 + lane];
            dot += qs[j * 32 + lane] * e;
            ss  += e * e;
        }
        #pragma unroll
        for (int o = 16; o; o >>= 1) {
            dot += __shfl_xor_sync(0xFFFFFFFFu, dot, o);
            ss  += __shfl_xor_sync(0xFFFFFFFFu, ss, o);
        }
        if (lane == 0) {
            cv[c] = dot * iq * (1.0f / sqrtf(ss));
            ci[c] = safe;
        }
    }
    __syncthreads();

    if (tid == 0) {
        float bv[KSEL]; int bi[KSEL];
        #pragma unroll
        for (int j = 0; j < KSEL; j++) { bv[j] = -FLT_MAX; bi[j] = 0x7FFFFFFF; }
        for (int c = 0; c < NCAND; c++) {
            float v = cv[c]; int ix = ci[c];
            bool better = (v > bv[KSEL-1]) || (v == bv[KSEL-1] && ix < bi[KSEL-1]);
            if (better) {
                int pos = KSEL - 1;
                while (pos > 0 && ((v > bv[pos-1]) || (v == bv[pos-1] && ix < bi[pos-1]))) {
                    bv[pos] = bv[pos-1]; bi[pos] = bi[pos-1]; pos--;
                }
                bv[pos] = v; bi[pos] = ix;
            }
        }
        for (int j = 0; j < KSEL; j++) {
            out[q * KSEL + j] = bv[j];
            if (out_size >= 2 * BQ * KSEL)
                out[BQ * KSEL + q * KSEL + j] = (float)bi[j];
        }
    }
}

// ===========================================================================
extern "C" void kernel_launch(void* const* d_in, const int* in_sizes, int n_in,
                              void* d_out, int out_size) {
    const float* Q = (const float*)d_in[0];
    const float* E = (const float*)d_in[1];
    const int B = in_sizes[0] / DDIM;
    const int N = in_sizes[1] / DDIM;
    const int ntiles = (N + TN - 1) / TN;             // 3907
    const int Npad = ntiles * TN;                     // 500096
    float* out = (float*)d_out;

    static bool init_done = false;
    if (!init_done) {
        cudaFuncSetAttribute(gemm_kernel, cudaFuncAttributeMaxDynamicSharedMemorySize, SM_GEMM);
        cudaFuncSetAttribute(topk_kernel, cudaFuncAttributeMaxDynamicSharedMemorySize, 256 * 32 * 8);
        init_done = true;
    }
    __nv_bfloat16* qbf_p; float* invq_p;
    cudaGetSymbolAddress((void**)&qbf_p, g_qbf);
    cudaGetSymbolAddress((void**)&invq_p, g_invq);

    convert_kernel<<<(B + 7) / 8, 256>>>(Q, qbf_p, invq_p, B);     // #1
    dummy_kernel<<<64, 256>>>();                                    // #2
    gemm_kernel<<<ntiles, 512, SM_GEMM>>>(E, N, Npad);              // #3
    topk_kernel<<<B * NSPLIT, 256, 256 * 32 * 8>>>(Npad);           // #4 (ncu slot)
    rescore_kernel<<<B, 256>>>(Q, E, out, N, out_size);             // #5
}

// round 16
// speedup vs baseline: 4.5290x; 1.1447x over previous
#include <cuda_runtime.h>
#include <cuda_bf16.h>
#include <cstdint>
#include <math.h>
#include <float.h>

// Retriever: B=256 x N=500000, D=768, top-17 cosine.
// qconvert -> fused GEMM (+ per-tile max emit) -> tau (80th tile-max) ->
// tau-seeded split top-64 scan -> exact fp32 rescore(128).

#define DDIM   768
#define KSEL   17
#define BQ     256
#define TN     128
#define QT     256
#define KCH    32
#define NCHUNK (DDIM / KCH)   // 24
#define NPAIR  (NCHUNK / 2)   // 12
#define NSPLIT 2
#define CSPL   64
#define NCAND  (NSPLIT * CSPL) // 128
#define NMAX   500000
#define NPADMAX (((NMAX + TN - 1) / TN) * TN)
#define NTILES (NPADMAX / TN)  // 3907
#define TAUW   96              // tau list width (>= 80 rank)

#define ROWB     80
#define ROWF     144
#define A_STAGE  (QT * ROWB)                   // 20480
#define F_STAGE  (TN * ROWF)                   // 18432
#define BB_STAGE (TN * ROWB)                   // 10240
#define OFF_A    0
#define OFF_F    (4 * A_STAGE)                 // 81920
#define OFF_BB   (OFF_F + 4 * F_STAGE)         // 155648
#define OFF_INV  (OFF_BB + 4 * BB_STAGE)       // 196608
#define OFF_TM   (OFF_INV + TN * 4)            // 197120
#define SM_GEMM  (OFF_TM + 4 * 256 * 4)        // 201216

#define SENT (-1e30f)

// ------------------------- device scratch ----------------------------------
__device__ __nv_bfloat16 g_qbf[(size_t)BQ * DDIM];
__device__ float g_invq[BQ];
__device__ __nv_bfloat16 g_sbf[(size_t)BQ * NPADMAX];    // 256 MB coarse scores
__device__ float g_tmax[(size_t)BQ * NTILES];            // 4 MB per-tile maxima
__device__ float g_tau[BQ];
__device__ float g_cand_v[BQ * NCAND];
__device__ int   g_cand_i[BQ * NCAND];

// ------------------------- helpers -----------------------------------------
__device__ __forceinline__ uint32_t smem_u32(const void* p) {
    uint32_t a;
    asm("{ .reg .u64 t; cvta.to.shared.u64 t, %1; cvt.u32.u64 %0, t; }" : "=r"(a) : "l"(p));
    return a;
}
__device__ __forceinline__ void cp16(uint32_t dst, const void* src) {
    asm volatile("cp.async.cg.shared.global [%0], [%1], 16;" :: "r"(dst), "l"(src));
}
#define CP_COMMIT() asm volatile("cp.async.commit_group;" ::: "memory")
#define CP_WAIT0()  asm volatile("cp.async.wait_group 0;" ::: "memory")
#define CP_WAIT1()  asm volatile("cp.async.wait_group 1;" ::: "memory")

__device__ __forceinline__ void ldsm4(uint32_t* r, uint32_t addr) {
    asm volatile("ldmatrix.sync.aligned.m8n8.x4.shared.b16 {%0,%1,%2,%3}, [%4];"
                 : "=r"(r[0]), "=r"(r[1]), "=r"(r[2]), "=r"(r[3]) : "r"(addr));
}
__device__ __forceinline__ void mma16816(float* c, const uint32_t* a, uint32_t b0, uint32_t b1) {
    asm volatile(
        "mma.sync.aligned.m16n8k16.row.col.f32.bf16.bf16.f32 "
        "{%0,%1,%2,%3}, {%4,%5,%6,%7}, {%8,%9}, {%0,%1,%2,%3};"
        : "+f"(c[0]), "+f"(c[1]), "+f"(c[2]), "+f"(c[3])
        : "r"(a[0]), "r"(a[1]), "r"(a[2]), "r"(a[3]), "r"(b0), "r"(b1));
}
__device__ __forceinline__ void lds128(float4& v, uint32_t addr) {
    asm volatile("ld.shared.v4.f32 {%0,%1,%2,%3}, [%4];"
                 : "=f"(v.x), "=f"(v.y), "=f"(v.z), "=f"(v.w) : "r"(addr));
}
__device__ __forceinline__ void sts128(uint32_t addr, uint32_t a, uint32_t b, uint32_t c, uint32_t d) {
    asm volatile("st.shared.v4.b32 [%0], {%1,%2,%3,%4};"
                 :: "r"(addr), "r"(a), "r"(b), "r"(c), "r"(d));
}
__device__ __forceinline__ uint32_t f2bf2(float lo, float hi) {
    uint32_t r;
    asm("cvt.rn.bf16x2.f32 %0, %1, %2;" : "=r"(r) : "f"(hi), "f"(lo));
    return r;
}
__device__ __forceinline__ float bf2max_f(__nv_bfloat162 m) {
    return fmaxf(__bfloat162float(__low2bfloat16(m)),
                 __bfloat162float(__high2bfloat16(m)));
}

// ===========================================================================
// Kernel 1: queries fp32 -> bf16 + inverse norms.
// ===========================================================================
__global__ void convert_kernel(const float* __restrict__ in,
                               __nv_bfloat16* __restrict__ obf,
                               float* __restrict__ invn, int rows) {
    int warp = (blockIdx.x * blockDim.x + threadIdx.x) >> 5;
    int lane = threadIdx.x & 31;
    if (warp >= rows) return;
    const float4* src = (const float4*)(in + (size_t)warp * DDIM);
    __nv_bfloat162* dst = (__nv_bfloat162*)(obf + (size_t)warp * DDIM);
    float s = 0.f;
    #pragma unroll
    for (int j = 0; j < 6; j++) {
        float4 v = src[j * 32 + lane];
        s += v.x * v.x + v.y * v.y + v.z * v.z + v.w * v.w;
        dst[(j * 32 + lane) * 2 + 0] = __floats2bfloat162_rn(v.x, v.y);
        dst[(j * 32 + lane) * 2 + 1] = __floats2bfloat162_rn(v.z, v.w);
    }
    #pragma unroll
    for (int o = 16; o; o >>= 1) s += __shfl_xor_sync(0xFFFFFFFFu, s, o);
    if (lane == 0) invn[warp] = 1.0f / sqrtf(s);
}

// ===========================================================================
// Kernel 2: fused GEMM + per-(query, tile) max emit.
// ===========================================================================
__global__ void __launch_bounds__(512, 1)
gemm_kernel(const float* __restrict__ E, int N, int Npad) {
    extern __shared__ __align__(16) char smem[];
    const uint32_t smBase = smem_u32(smem);

    const int tid  = threadIdx.x;
    const int wid  = tid >> 5;
    const int lane = tid & 31;
    const int g    = lane >> 2;
    const int tg   = lane & 3;

    const int nbase = blockIdx.x * TN;
    const int m0w = (wid & 3) * 64;
    const int n0w = (wid >> 2) * 32;

    const int sel = lane >> 3, r8 = lane & 7;
    const uint32_t aOff = (uint32_t)((m0w + (sel & 1) * 8 + r8) * ROWB + (sel >> 1) * 16);
    const uint32_t bOff = (uint32_t)((n0w + (sel >> 1) * 8 + r8) * ROWB + (sel & 1) * 16);

    const char* qb = (const char*)g_qbf;
    const char* eb = (const char*)E;

    const int crow = tid >> 2;
    const int cq   = tid & 3;
    int grow = nbase + crow; if (grow >= N) grow = N - 1;
    const char* esrc = eb + (size_t)grow * (DDIM * 4) + cq * 32;

    auto load_chunk = [&](int c) {
        const int s = c & 3;
        #pragma unroll
        for (int i = 0; i < 2; i++) {
            int idx = tid + i * 512, row = idx >> 2, seg = idx & 3;
            cp16(smBase + OFF_A + s * A_STAGE + row * ROWB + seg * 16,
                 qb + (size_t)row * (DDIM * 2) + c * 64 + seg * 16);
        }
        const uint32_t fdst = smBase + OFF_F + s * F_STAGE + crow * ROWF + cq * 32;
        cp16(fdst,      esrc + c * 128);
        cp16(fdst + 16, esrc + c * 128 + 16);
    };
    auto load_pair = [&](int p) {
        load_chunk(2 * p);
        load_chunk(2 * p + 1);
        CP_COMMIT();
    };

    float sumsq = 0.f;
    auto convert = [&](int c) {
        const int s = c & 3;
        const uint32_t src = smBase + OFF_F + s * F_STAGE + crow * ROWF + cq * 32;
        const uint32_t dst = smBase + OFF_BB + s * BB_STAGE + crow * ROWB + cq * 16;
        float4 f0, f1;
        lds128(f0, src); lds128(f1, src + 16);
        sumsq += f0.x*f0.x + f0.y*f0.y + f0.z*f0.z + f0.w*f0.w
               + f1.x*f1.x + f1.y*f1.y + f1.z*f1.z + f1.w*f1.w;
        sts128(dst, f2bf2(f0.x, f0.y), f2bf2(f0.z, f0.w),
                    f2bf2(f1.x, f1.y), f2bf2(f1.z, f1.w));
    };

    float acc[4][4][4];
    #pragma unroll
    for (int mf = 0; mf < 4; mf++)
        #pragma unroll
        for (int nf = 0; nf < 4; nf++)
            #pragma unroll
            for (int j = 0; j < 4; j++) acc[mf][nf][j] = 0.f;

    load_pair(0);
    load_pair(1);
    CP_WAIT1();
    convert(0); convert(1);
    __syncthreads();

    auto mma_chunk = [&](int c) {
        const int s = c & 3;
        const uint32_t aS = smBase + OFF_A + s * A_STAGE + aOff;
        const uint32_t bS = smBase + OFF_BB + s * BB_STAGE + bOff;
        #pragma unroll
        for (int kk = 0; kk < 2; kk++) {
            uint32_t a[4][4], b[2][4];
            #pragma unroll
            for (int mf = 0; mf < 4; mf++) ldsm4(a[mf], aS + mf * (16 * ROWB) + kk * 32);
            #pragma unroll
            for (int p = 0; p < 2; p++)    ldsm4(b[p], bS + p * (16 * ROWB) + kk * 32);
            #pragma unroll
            for (int mf = 0; mf < 4; mf++)
                #pragma unroll
                for (int nf = 0; nf < 4; nf++)
                    mma16816(acc[mf][nf], a[mf], b[nf >> 1][(nf & 1) * 2], b[nf >> 1][(nf & 1) * 2 + 1]);
        }
    };

    for (int p = 0; p < NPAIR; p++) {
        mma_chunk(2 * p);
        mma_chunk(2 * p + 1);
        if (p + 1 < NPAIR) {
            CP_WAIT0();
            convert(2 * p + 2);
            convert(2 * p + 3);
        }
        __syncthreads();
        if (p + 2 < NPAIR) load_pair(p + 2);
    }

    float* scr  = (float*)(smem + OFF_F);
    float* invs = (float*)(smem + OFF_INV);
    scr[tid] = sumsq;
    __syncthreads();
    if (tid < TN)
        invs[tid] = rsqrtf(scr[4 * tid] + scr[4 * tid + 1] + scr[4 * tid + 2] + scr[4 * tid + 3]);
    __syncthreads();

    float2 ie[4];
    #pragma unroll
    for (int nf = 0; nf < 4; nf++) {
        const int nl = n0w + nf * 8 + 2 * tg;
        ie[nf].x = invs[nl];
        ie[nf].y = invs[nl + 1];
    }
    float qmax[4][2];
    #pragma unroll
    for (int mf = 0; mf < 4; mf++) { qmax[mf][0] = SENT; qmax[mf][1] = SENT; }

    #pragma unroll
    for (int mf = 0; mf < 4; mf++) {
        #pragma unroll
        for (int h = 0; h < 2; h++) {
            const int q = m0w + mf * 16 + h * 8 + g;
            const float iq = g_invq[q];
            __nv_bfloat16* orow = g_sbf + (size_t)q * Npad + nbase + n0w + 2 * tg;
            #pragma unroll
            for (int nf = 0; nf < 4; nf++) {
                const int n = nbase + n0w + nf * 8 + 2 * tg;
                float ox = (n     < N) ? acc[mf][nf][2 * h]     * iq * ie[nf].x : SENT;
                float oy = (n + 1 < N) ? acc[mf][nf][2 * h + 1] * iq * ie[nf].y : SENT;
                *(uint32_t*)(orow + nf * 8) = f2bf2(ox, oy);
                qmax[mf][h] = fmaxf(qmax[mf][h], fmaxf(ox, oy));
            }
        }
    }

    // ---- per-(q, tile) max: reduce over tg lanes, 4 n-warps, write gmem ----
    float* tm = (float*)(smem + OFF_TM);        // [4 nwarp][256 q]
    #pragma unroll
    for (int mf = 0; mf < 4; mf++)
        #pragma unroll
        for (int h = 0; h < 2; h++) {
            float v = qmax[mf][h];
            v = fmaxf(v, __shfl_xor_sync(0xFFFFFFFFu, v, 1));
            v = fmaxf(v, __shfl_xor_sync(0xFFFFFFFFu, v, 2));
            if (tg == 0) tm[(wid >> 2) * 256 + m0w + mf * 16 + h * 8 + g] = v;
        }
    __syncthreads();
    if (tid < 256) {
        float m = fmaxf(fmaxf(tm[tid], tm[256 + tid]),
                        fmaxf(tm[512 + tid], tm[768 + tid]));
        g_tmax[(size_t)tid * gridDim.x + blockIdx.x] = m;
    }
}

// ===========================================================================
// Kernel 3: tau = 80th largest tile-max per query (values only, width 96).
// ===========================================================================
#define LK2 8
__global__ void tau_kernel(int ntiles) {
    extern __shared__ float sv[];             // 256 * TAUW
    const int q = blockIdx.x;
    const int tid = threadIdx.x;
    const float* row = g_tmax + (size_t)q * ntiles;

    float lv[LK2];
    #pragma unroll
    for (int j = 0; j < LK2; j++) lv[j] = -FLT_MAX;
    float vmin = -FLT_MAX;
    for (int i = tid; i < ntiles; i += 256) {
        float v = row[i];
        if (v > vmin) {
            #pragma unroll
            for (int j = LK2 - 1; j >= 1; j--) {
                bool gj  = v > lv[j];
                bool gj1 = v > lv[j - 1];
                lv[j] = gj ? (gj1 ? lv[j - 1] : v) : lv[j];
            }
            if (v > lv[0]) lv[0] = v;
            vmin = lv[LK2 - 1];
        }
    }
    #pragma unroll
    for (int j = 0; j < LK2; j++) sv[tid * TAUW + j] = lv[j];
    #pragma unroll
    for (int j = LK2; j < TAUW; j++) sv[tid * TAUW + j] = -FLT_MAX;

    int len = LK2;
    for (int half = 128; half >= 1; half >>= 1) {
        int outlen = min(2 * len, TAUW);
        __syncthreads();
        if (tid < half) {
            float* av = &sv[tid * TAUW];
            float* bv = &sv[(tid + half) * TAUW];
            float tv[TAUW];
            int ia = 0, ib = 0;
            for (int j = 0; j < outlen; j++) {
                float va = (ia < len) ? av[ia] : -FLT_MAX;
                float vb = (ib < len) ? bv[ib] : -FLT_MAX;
                if (va >= vb) { tv[j] = va; ia++; } else { tv[j] = vb; ib++; }
            }
            for (int j = 0; j < outlen; j++) av[j] = tv[j];
        }
        len = outlen;
    }
    __syncthreads();
    if (tid == 0) g_tau[q] = sv[79];          // 80th largest
}

// ===========================================================================
// Kernel 4: tau-seeded split top-64. 2 CTAs/query, 128 threads.
// ===========================================================================
#define LK 16
__global__ void topk_kernel(int Npad) {
    extern __shared__ char sm[];
    float* sv = (float*)sm;                   // 128 * 64
    int*   si = (int*)(sm + 128 * 64 * 4);
    const int q     = blockIdx.x >> 1;
    const int split = blockIdx.x & 1;
    const int tid   = threadIdx.x;
    const int seg   = Npad / NSPLIT;          // 250048 (divisible by 32)
    const int nb    = split * seg;
    const uint4* row4 = (const uint4*)(g_sbf + (size_t)q * Npad + nb);

    float lv[LK]; int li[LK];
    #pragma unroll
    for (int j = 0; j < LK; j++) { lv[j] = -FLT_MAX; li[j] = 0x7FFFFFFF; }
    float vmin = g_tau[q] - 1e-5f;            // seeded threshold (<= coarse v80)

    auto insert8 = [&](uint4 u, int base) {
        const uint32_t w[4] = {u.x, u.y, u.z, u.w};
        #pragma unroll
        for (int e = 0; e < 8; e++) {
            float v = __bfloat162float(((const __nv_bfloat16*)w)[e]);
            if (v > vmin) {
                int n = base + e;
                #pragma unroll
                for (int j = LK - 1; j >= 1; j--) {
                    bool gj  = v > lv[j];
                    bool gj1 = v > lv[j - 1];
                    lv[j] = gj ? (gj1 ? lv[j - 1] : v) : lv[j];
                    li[j] = gj ? (gj1 ? li[j - 1] : n) : li[j];
                }
                if (v > lv[0]) { lv[0] = v; li[0] = n; }
                float nm = lv[LK - 1];
                vmin = fmaxf(vmin, nm);        // never drop below tau seed
            }
        }
    };

    const int nblk32 = seg >> 5;              // 7814
    for (int i = tid; i < nblk32; i += 128) {
        uint4 u0 = row4[i * 4 + 0];
        uint4 u1 = row4[i * 4 + 1];
        uint4 u2 = row4[i * 4 + 2];
        uint4 u3 = row4[i * 4 + 3];
        __nv_bfloat162 m0 = __hmax2(__hmax2(*(__nv_bfloat162*)&u0.x, *(__nv_bfloat162*)&u0.y),
                                    __hmax2(*(__nv_bfloat162*)&u0.z, *(__nv_bfloat162*)&u0.w));
        __nv_bfloat162 m1 = __hmax2(__hmax2(*(__nv_bfloat162*)&u1.x, *(__nv_bfloat162*)&u1.y),
                                    __hmax2(*(__nv_bfloat162*)&u1.z, *(__nv_bfloat162*)&u1.w));
        __nv_bfloat162 m2 = __hmax2(__hmax2(*(__nv_bfloat162*)&u2.x, *(__nv_bfloat162*)&u2.y),
                                    __hmax2(*(__nv_bfloat162*)&u2.z, *(__nv_bfloat162*)&u2.w));
        __nv_bfloat162 m3 = __hmax2(__hmax2(*(__nv_bfloat162*)&u3.x, *(__nv_bfloat162*)&u3.y),
                                    __hmax2(*(__nv_bfloat162*)&u3.z, *(__nv_bfloat162*)&u3.w));
        __nv_bfloat162 m  = __hmax2(__hmax2(m0, m1), __hmax2(m2, m3));
        if (bf2max_f(m) > vmin) {
            const int base = nb + i * 32;
            if (bf2max_f(m0) > vmin) insert8(u0, base);
            if (bf2max_f(m1) > vmin) insert8(u1, base + 8);
            if (bf2max_f(m2) > vmin) insert8(u2, base + 16);
            if (bf2max_f(m3) > vmin) insert8(u3, base + 24);
        }
    }

    #pragma unroll
    for (int j = 0; j < LK; j++) { sv[tid * 64 + j] = lv[j]; si[tid * 64 + j] = li[j]; }
    #pragma unroll
    for (int j = LK; j < 64; j++) { sv[tid * 64 + j] = -FLT_MAX; si[tid * 64 + j] = 0x7FFFFFFF; }

    int len = LK;
    for (int half = 64; half >= 1; half >>= 1) {
        int outlen = min(2 * len, CSPL);
        __syncthreads();
        if (tid < half) {
            float* av = &sv[tid * 64];            int* ai = &si[tid * 64];
            float* bv = &sv[(tid + half) * 64];   int* bi = &si[(tid + half) * 64];
            float tv[CSPL]; int ti[CSPL];
            int ia = 0, ib = 0;
            for (int j = 0; j < outlen; j++) {
                float va = (ia < len) ? av[ia] : -FLT_MAX;
                float vb = (ib < len) ? bv[ib] : -FLT_MAX;
                int xa = (ia < len) ? ai[ia] : 0x7FFFFFFF;
                int xb = (ib < len) ? bi[ib] : 0x7FFFFFFF;
                bool ta = (va > vb) || (va == vb && xa < xb);
                if (ta) { tv[j] = va; ti[j] = xa; ia++; }
                else    { tv[j] = vb; ti[j] = xb; ib++; }
            }
            for (int j = 0; j < outlen; j++) { av[j] = tv[j]; ai[j] = ti[j]; }
        }
        len = outlen;
    }
    __syncthreads();
    if (tid < CSPL) {
        g_cand_v[q * NCAND + split * CSPL + tid] = sv[tid];
        g_cand_i[q * NCAND + split * CSPL + tid] = si[tid];
    }
}

// ===========================================================================
// Kernel 5: exact fp32 rescore of 128 candidates (sentinel-safe) + top-17.
// ===========================================================================
__global__ void rescore_kernel(const float* __restrict__ Q, const float* __restrict__ E,
                               float* __restrict__ out, int N, int out_size) {
    __shared__ float qs[DDIM];
    __shared__ float cv[NCAND];
    __shared__ int   ci[NCAND];
    const int q = blockIdx.x;
    const int tid = threadIdx.x;
    const int wid = tid >> 5, lane = tid & 31;

    #pragma unroll
    for (int j = 0; j < 3; j++) qs[tid + j * 256] = Q[(size_t)q * DDIM + tid + j * 256];
    __syncthreads();

    const float iq = g_invq[q];
    for (int c = wid; c < NCAND; c += 8) {
        int idx = g_cand_i[q * NCAND + c];
        bool valid = (idx >= 0 && idx < N);
        int safe = valid ? idx : 0;
        const float* er = E + (size_t)safe * DDIM;
        float dot = 0.f, ss = 0.f;
        #pragma unroll
        for (int j = 0; j < 24; j++) {
            float e = er[j * 32 + lane];
            dot += qs[j * 32 + lane] * e;
            ss  += e * e;
        }
        #pragma unroll
        for (int o = 16; o; o >>= 1) {
            dot += __shfl_xor_sync(0xFFFFFFFFu, dot, o);
            ss  += __shfl_xor_sync(0xFFFFFFFFu, ss, o);
        }
        if (lane == 0) {
            cv[c] = valid ? dot * iq * (1.0f / sqrtf(ss)) : -FLT_MAX;
            ci[c] = valid ? safe : 0x7FFFFFFF;
        }
    }
    __syncthreads();

    if (tid == 0) {
        float bv[KSEL]; int bi[KSEL];
        #pragma unroll
        for (int j = 0; j < KSEL; j++) { bv[j] = -FLT_MAX; bi[j] = 0x7FFFFFFF; }
        for (int c = 0; c < NCAND; c++) {
            float v = cv[c]; int ix = ci[c];
            bool better = (v > bv[KSEL-1]) || (v == bv[KSEL-1] && ix < bi[KSEL-1]);
            if (better) {
                int pos = KSEL - 1;
                while (pos > 0 && ((v > bv[pos-1]) || (v == bv[pos-1] && ix < bi[pos-1]))) {
                    bv[pos] = bv[pos-1]; bi[pos] = bi[pos-1]; pos--;
                }
                bv[pos] = v; bi[pos] = ix;
            }
        }
        for (int j = 0; j < KSEL; j++) {
            out[q * KSEL + j] = bv[j];
            if (out_size >= 2 * BQ * KSEL)
                out[BQ * KSEL + q * KSEL + j] = (float)bi[j];
        }
    }
}

// ===========================================================================
extern "C" void kernel_launch(void* const* d_in, const int* in_sizes, int n_in,
                              void* d_out, int out_size) {
    const float* Q = (const float*)d_in[0];
    const float* E = (const float*)d_in[1];
    const int B = in_sizes[0] / DDIM;
    const int N = in_sizes[1] / DDIM;
    const int ntiles = (N + TN - 1) / TN;             // 3907
    const int Npad = ntiles * TN;                     // 500096
    float* out = (float*)d_out;

    static bool init_done = false;
    if (!init_done) {
        cudaFuncSetAttribute(gemm_kernel, cudaFuncAttributeMaxDynamicSharedMemorySize, SM_GEMM);
        cudaFuncSetAttribute(tau_kernel, cudaFuncAttributeMaxDynamicSharedMemorySize, 256 * TAUW * 4);
        cudaFuncSetAttribute(topk_kernel, cudaFuncAttributeMaxDynamicSharedMemorySize, 128 * 64 * 8);
        init_done = true;
    }
    __nv_bfloat16* qbf_p; float* invq_p;
    cudaGetSymbolAddress((void**)&qbf_p, g_qbf);
    cudaGetSymbolAddress((void**)&invq_p, g_invq);

    convert_kernel<<<(B + 7) / 8, 256>>>(Q, qbf_p, invq_p, B);     // #1
    gemm_kernel<<<ntiles, 512, SM_GEMM>>>(E, N, Npad);              // #2
    tau_kernel<<<B, 256, 256 * TAUW * 4>>>(ntiles);                 // #3
    topk_kernel<<<B * NSPLIT, 128, 128 * 64 * 8>>>(Npad);           // #4 (ncu slot)
    rescore_kernel<<<B, 256>>>(Q, E, out, N, out_size);             // #5
}